// round 1
// baseline (speedup 1.0000x reference)
#include <cuda_runtime.h>
#include <cuda_bf16.h>
#include <math.h>

// Problem constants
#define BB 2
#define SS 2048
#define DD 1024
#define HH 16
#define DQ 64
#define DFFN 4096
#define MROWS (BB*SS)          // 4096
#define RES_SCALE 0.70710678118654752440f

// ---------------- device scratch (no allocs allowed) ----------------
__device__ float g_h  [MROWS * DD];
__device__ float g_q  [MROWS * DD];
__device__ float g_k  [MROWS * DD];
__device__ float g_v  [MROWS * DD];
__device__ float g_ctx[MROWS * DD];
__device__ float g_x1 [MROWS * DD];
__device__ float g_ff [MROWS * DFFN];

// ---------------- LayerNorm: one block per row of 1024 ----------------
__global__ __launch_bounds__(256) void ln_kernel(const float* __restrict__ x,
                                                 const float* __restrict__ g,
                                                 const float* __restrict__ b,
                                                 float* __restrict__ out)
{
    int row = blockIdx.x;
    int tid = threadIdx.x;
    const float4* xr = (const float4*)(x + (size_t)row * DD);
    float4 v = xr[tid];
    float s  = v.x + v.y + v.z + v.w;
    float ss = v.x*v.x + v.y*v.y + v.z*v.z + v.w*v.w;
    #pragma unroll
    for (int o = 16; o; o >>= 1) {
        s  += __shfl_xor_sync(0xffffffffu, s, o);
        ss += __shfl_xor_sync(0xffffffffu, ss, o);
    }
    __shared__ float sm1[8], sm2[8];
    int w = tid >> 5, l = tid & 31;
    if (l == 0) { sm1[w] = s; sm2[w] = ss; }
    __syncthreads();
    if (tid == 0) {
        float S = 0.f, SSu = 0.f;
        #pragma unroll
        for (int i = 0; i < 8; i++) { S += sm1[i]; SSu += sm2[i]; }
        float mu  = S  * (1.f / DD);
        float var = SSu * (1.f / DD) - mu * mu;
        sm1[0] = mu;
        sm2[0] = rsqrtf(var + 1e-5f);
    }
    __syncthreads();
    float mu  = sm1[0];
    float inv = sm2[0];
    float4 gg = ((const float4*)g)[tid];
    float4 bb = ((const float4*)b)[tid];
    float4 o4;
    o4.x = (v.x - mu) * inv * gg.x + bb.x;
    o4.y = (v.y - mu) * inv * gg.y + bb.y;
    o4.z = (v.z - mu) * inv * gg.z + bb.z;
    o4.w = (v.w - mu) * inv * gg.w + bb.w;
    ((float4*)(out + (size_t)row * DD))[tid] = o4;
}

// ---------------- SGEMM 128x128x16, 256 thr, 8x8 microtile ----------------
// MODE 0: C = A*B + bias
// MODE 1: C = gelu_tanh(A*B + bias)
// MODE 2: C = R + (A*B + bias) * scale
#define BM 128
#define BN 128
#define BK 16

__device__ __forceinline__ float gelu_tanh(float x) {
    float x3 = x * x * x;
    return 0.5f * x * (1.f + tanhf(0.7978845608028654f * (x + 0.044715f * x3)));
}

template<int MODE>
__global__ __launch_bounds__(256, 2)
void sgemm_kernel(const float* __restrict__ A, const float* __restrict__ B,
                  const float* __restrict__ bias, const float* __restrict__ R,
                  float* __restrict__ C, int M, int N, int K, float scale)
{
    __shared__ float As[2][BK][BM];
    __shared__ float Bs[2][BK][BN];

    int tid = threadIdx.x;
    int bm = blockIdx.y * BM;
    int bn = blockIdx.x * BN;
    int ty = tid >> 4, tx = tid & 15;

    float acc[8][8];
    #pragma unroll
    for (int i = 0; i < 8; i++)
        #pragma unroll
        for (int j = 0; j < 8; j++) acc[i][j] = 0.f;

    const int numTiles = K / BK;

    // load tile 0
    #pragma unroll
    for (int i = 0; i < 2; i++) {
        int idx = tid + i * 256;
        int r = idx >> 2, c4 = idx & 3;
        float4 a = *(const float4*)(A + (size_t)(bm + r) * K + c4 * 4);
        As[0][c4*4+0][r] = a.x; As[0][c4*4+1][r] = a.y;
        As[0][c4*4+2][r] = a.z; As[0][c4*4+3][r] = a.w;
        int br = idx >> 5, bc4 = idx & 31;
        *(float4*)(&Bs[0][br][bc4*4]) = *(const float4*)(B + (size_t)br * N + bn + bc4 * 4);
    }
    __syncthreads();

    int cur = 0;
    float4 aReg[2], bReg[2];

    for (int t = 0; t < numTiles; t++) {
        if (t + 1 < numTiles) {
            int k0 = (t + 1) * BK;
            #pragma unroll
            for (int i = 0; i < 2; i++) {
                int idx = tid + i * 256;
                int r = idx >> 2, c4 = idx & 3;
                aReg[i] = *(const float4*)(A + (size_t)(bm + r) * K + k0 + c4 * 4);
                int br = idx >> 5, bc4 = idx & 31;
                bReg[i] = *(const float4*)(B + (size_t)(k0 + br) * N + bn + bc4 * 4);
            }
        }
        #pragma unroll
        for (int k = 0; k < BK; k++) {
            float af[8], bf[8];
            *(float4*)&af[0] = *(float4*)&As[cur][k][ty * 4];
            *(float4*)&af[4] = *(float4*)&As[cur][k][64 + ty * 4];
            *(float4*)&bf[0] = *(float4*)&Bs[cur][k][tx * 4];
            *(float4*)&bf[4] = *(float4*)&Bs[cur][k][64 + tx * 4];
            #pragma unroll
            for (int i = 0; i < 8; i++)
                #pragma unroll
                for (int j = 0; j < 8; j++)
                    acc[i][j] += af[i] * bf[j];
        }
        if (t + 1 < numTiles) {
            int nxt = cur ^ 1;
            #pragma unroll
            for (int i = 0; i < 2; i++) {
                int idx = tid + i * 256;
                int r = idx >> 2, c4 = idx & 3;
                As[nxt][c4*4+0][r] = aReg[i].x; As[nxt][c4*4+1][r] = aReg[i].y;
                As[nxt][c4*4+2][r] = aReg[i].z; As[nxt][c4*4+3][r] = aReg[i].w;
                int br = idx >> 5, bc4 = idx & 31;
                *(float4*)(&Bs[nxt][br][bc4*4]) = bReg[i];
            }
            __syncthreads();
            cur = nxt;
        }
    }

    // epilogue
    #pragma unroll
    for (int i = 0; i < 8; i++) {
        int r = bm + ((i < 4) ? 0 : 64) + ty * 4 + (i & 3);
        #pragma unroll
        for (int jb = 0; jb < 2; jb++) {
            int c = bn + (jb ? 64 : 0) + tx * 4;
            float4 bia = *(const float4*)(bias + c);
            float tv[4];
            tv[0] = acc[i][jb*4+0] + bia.x;
            tv[1] = acc[i][jb*4+1] + bia.y;
            tv[2] = acc[i][jb*4+2] + bia.z;
            tv[3] = acc[i][jb*4+3] + bia.w;
            float4 o4;
            if (MODE == 1) {
                o4.x = gelu_tanh(tv[0]); o4.y = gelu_tanh(tv[1]);
                o4.z = gelu_tanh(tv[2]); o4.w = gelu_tanh(tv[3]);
            } else if (MODE == 2) {
                float4 rr = *(const float4*)(R + (size_t)r * N + c);
                o4.x = rr.x + tv[0] * scale; o4.y = rr.y + tv[1] * scale;
                o4.z = rr.z + tv[2] * scale; o4.w = rr.w + tv[3] * scale;
            } else {
                o4.x = tv[0]; o4.y = tv[1]; o4.z = tv[2]; o4.w = tv[3];
            }
            *(float4*)(C + (size_t)r * N + c) = o4;
        }
    }
}

// ---------------- block-local causal attention ----------------
// grid: (S/64, H, B). Each block: 64 queries x <=64 keys x 64 dims, one head.
__global__ __launch_bounds__(256)
void attn_kernel(const float* __restrict__ q, const float* __restrict__ k,
                 const float* __restrict__ v, float* __restrict__ ctx)
{
    __shared__ float qs[64][64];
    __shared__ float ks[64][64];   // reused as attn-probs after scores
    __shared__ float vs[64][64];

    int tid = threadIdx.x;
    int rowbase = blockIdx.z * SS + blockIdx.x * 64;
    int colbase = blockIdx.y * 64;

    #pragma unroll
    for (int i = 0; i < 4; i++) {
        int idx = tid + i * 256;       // 0..1023
        int r = idx >> 4, c4 = idx & 15;
        size_t off = (size_t)(rowbase + r) * DD + colbase + c4 * 4;
        *(float4*)&qs[r][c4*4] = *(const float4*)(q + off);
        *(float4*)&ks[r][c4*4] = *(const float4*)(k + off);
        *(float4*)&vs[r][c4*4] = *(const float4*)(v + off);
    }
    __syncthreads();

    int qi = tid >> 2;          // query row 0..63
    int jg = (tid & 3) * 16;    // key group start

    float sc[16];
    float m = -1e30f;
    #pragma unroll
    for (int jj = 0; jj < 16; jj++) {
        int j = jg + jj;
        float s = -1e30f;
        if (j <= qi) {
            s = 0.f;
            #pragma unroll
            for (int d = 0; d < 64; d++) s += qs[qi][d] * ks[j][d];
            s *= 0.125f;  // 1/sqrt(64)
            m = fmaxf(m, s);
        }
        sc[jj] = s;
    }
    m = fmaxf(m, __shfl_xor_sync(0xffffffffu, m, 1));
    m = fmaxf(m, __shfl_xor_sync(0xffffffffu, m, 2));

    float sum = 0.f;
    #pragma unroll
    for (int jj = 0; jj < 16; jj++) {
        float e = (jg + jj <= qi) ? expf(sc[jj] - m) : 0.f;
        sc[jj] = e;
        sum += e;
    }
    sum += __shfl_xor_sync(0xffffffffu, sum, 1);
    sum += __shfl_xor_sync(0xffffffffu, sum, 2);
    float inv = 1.f / sum;

    __syncthreads();   // all done reading ks (scores computed)
    #pragma unroll
    for (int jj = 0; jj < 16; jj++)
        ks[qi][jg + jj] = sc[jj] * inv;   // attn probs into ks
    __syncthreads();

    float out[16];
    #pragma unroll
    for (int dd = 0; dd < 16; dd++) out[dd] = 0.f;
    for (int j = 0; j <= qi; j++) {
        float p = ks[qi][j];
        #pragma unroll
        for (int dd = 0; dd < 16; dd++)
            out[dd] += p * vs[j][jg + dd];
    }

    float* dst = ctx + (size_t)(rowbase + qi) * DD + colbase + jg;
    #pragma unroll
    for (int dd = 0; dd < 16; dd += 4) {
        float4 o4 = make_float4(out[dd], out[dd+1], out[dd+2], out[dd+3]);
        *(float4*)(dst + dd) = o4;
    }
}

// ---------------- launch ----------------
extern "C" void kernel_launch(void* const* d_in, const int* in_sizes, int n_in,
                              void* d_out, int out_size)
{
    const float* x    = (const float*)d_in[0];
    // d_in[1] = mask_sa (unused: mask is analytically causal & block-diagonal)
    const float* Wq   = (const float*)d_in[2];
    const float* bq   = (const float*)d_in[3];
    const float* Wk   = (const float*)d_in[4];
    const float* bk   = (const float*)d_in[5];
    const float* Wv   = (const float*)d_in[6];
    const float* bv   = (const float*)d_in[7];
    const float* Wo   = (const float*)d_in[8];
    const float* bo   = (const float*)d_in[9];
    const float* ln1g = (const float*)d_in[10];
    const float* ln1b = (const float*)d_in[11];
    const float* ln2g = (const float*)d_in[12];
    const float* ln2b = (const float*)d_in[13];
    const float* W1   = (const float*)d_in[14];
    const float* b1   = (const float*)d_in[15];
    const float* W2   = (const float*)d_in[16];
    const float* b2   = (const float*)d_in[17];
    float* out = (float*)d_out;

    float *h, *q, *k, *v, *ctx, *x1, *ff;
    cudaGetSymbolAddress((void**)&h,   g_h);
    cudaGetSymbolAddress((void**)&q,   g_q);
    cudaGetSymbolAddress((void**)&k,   g_k);
    cudaGetSymbolAddress((void**)&v,   g_v);
    cudaGetSymbolAddress((void**)&ctx, g_ctx);
    cudaGetSymbolAddress((void**)&x1,  g_x1);
    cudaGetSymbolAddress((void**)&ff,  g_ff);

    // 1. LN1: h = LN(x)
    ln_kernel<<<MROWS, 256>>>(x, ln1g, ln1b, h);

    // 2. QKV projections
    dim3 gD(DD / BN, MROWS / BM);     // (8, 32)
    sgemm_kernel<0><<<gD, 256>>>(h, Wq, bq, nullptr, q, MROWS, DD, DD, 0.f);
    sgemm_kernel<0><<<gD, 256>>>(h, Wk, bk, nullptr, k, MROWS, DD, DD, 0.f);
    sgemm_kernel<0><<<gD, 256>>>(h, Wv, bv, nullptr, v, MROWS, DD, DD, 0.f);

    // 3. block-local causal attention
    dim3 gA(SS / 64, HH, BB);
    attn_kernel<<<gA, 256>>>(q, k, v, ctx);

    // 4. x1 = x + (ctx @ Wo + bo) * res_scale
    sgemm_kernel<2><<<gD, 256>>>(ctx, Wo, bo, x, x1, MROWS, DD, DD, RES_SCALE);

    // 5. LN2: h = LN(x1)
    ln_kernel<<<MROWS, 256>>>(x1, ln2g, ln2b, h);

    // 6. ff = gelu(h @ W1 + b1)
    dim3 gF1(DFFN / BN, MROWS / BM);  // (32, 32)
    sgemm_kernel<1><<<gF1, 256>>>(h, W1, b1, nullptr, ff, MROWS, DFFN, DD, 0.f);

    // 7. out = x1 + (ff @ W2 + b2) * res_scale
    sgemm_kernel<2><<<gD, 256>>>(ff, W2, b2, x1, out, MROWS, DD, DFFN, RES_SCALE);
}

// round 4
// speedup vs baseline: 2.5369x; 2.5369x over previous
#include <cuda_runtime.h>
#include <cuda_bf16.h>
#include <math.h>

typedef unsigned int u32;

// Problem constants
#define BB 2
#define SS 2048
#define DD 1024
#define HH 16
#define DFFN 4096
#define MROWS (BB*SS)          // 4096
#define RES_SCALE 0.70710678118654752440f

// ---------------- device scratch (no allocs allowed) ----------------
__device__ float g_h  [MROWS * DD];
__device__ float g_q  [MROWS * DD];
__device__ float g_k  [MROWS * DD];
__device__ float g_v  [MROWS * DD];
__device__ float g_ctx[MROWS * DD];
__device__ float g_x1 [MROWS * DD];
__device__ float g_ff [MROWS * DFFN];

// ---------------- LayerNorm ----------------
__global__ __launch_bounds__(256) void ln_kernel(const float* __restrict__ x,
                                                 const float* __restrict__ g,
                                                 const float* __restrict__ b,
                                                 float* __restrict__ out)
{
    int row = blockIdx.x;
    int tid = threadIdx.x;
    const float4* xr = (const float4*)(x + (size_t)row * DD);
    float4 v = xr[tid];
    float s  = v.x + v.y + v.z + v.w;
    float ss = v.x*v.x + v.y*v.y + v.z*v.z + v.w*v.w;
    #pragma unroll
    for (int o = 16; o; o >>= 1) {
        s  += __shfl_xor_sync(0xffffffffu, s, o);
        ss += __shfl_xor_sync(0xffffffffu, ss, o);
    }
    __shared__ float sm1[8], sm2[8];
    int w = tid >> 5, l = tid & 31;
    if (l == 0) { sm1[w] = s; sm2[w] = ss; }
    __syncthreads();
    if (tid == 0) {
        float S = 0.f, SSu = 0.f;
        #pragma unroll
        for (int i = 0; i < 8; i++) { S += sm1[i]; SSu += sm2[i]; }
        float mu  = S  * (1.f / DD);
        float var = SSu * (1.f / DD) - mu * mu;
        sm1[0] = mu;
        sm2[0] = rsqrtf(var + 1e-5f);
    }
    __syncthreads();
    float mu  = sm1[0];
    float inv = sm2[0];
    float4 gg = ((const float4*)g)[tid];
    float4 bb = ((const float4*)b)[tid];
    float4 o4;
    o4.x = (v.x - mu) * inv * gg.x + bb.x;
    o4.y = (v.y - mu) * inv * gg.y + bb.y;
    o4.z = (v.z - mu) * inv * gg.z + bb.z;
    o4.w = (v.w - mu) * inv * gg.w + bb.w;
    ((float4*)(out + (size_t)row * DD))[tid] = o4;
}

// ---------------- TF32 tensor-core GEMM ----------------
// 128x128 CTA tile, BK=32, 8 warps each 64x32, mma.m16n8k8 tf32.
// MODE 0: C = A*B + bias
// MODE 1: C = gelu_tanh(A*B + bias)
// MODE 2: C = R + (A*B + bias) * scale

#define ASTRIDE 36      // 32 + 4 pad (floats) -> conflict-free frag loads
#define BSTRIDE 136     // 128 + 8 pad (floats) -> conflict-free frag loads
#define A_STAGE (128 * ASTRIDE)
#define B_STAGE (32 * BSTRIDE)
#define SMEM_FLOATS (2 * A_STAGE + 2 * B_STAGE)
#define SMEM_BYTES (SMEM_FLOATS * 4)

__device__ __forceinline__ float gelu_tanh(float x) {
    float x3 = x * x * x;
    return 0.5f * x * (1.f + tanhf(0.7978845608028654f * (x + 0.044715f * x3)));
}

__device__ __forceinline__ void cp_async16(float* dst, const float* src) {
    u32 d = (u32)__cvta_generic_to_shared(dst);
    asm volatile("cp.async.cg.shared.global [%0], [%1], 16;\n" :: "r"(d), "l"(src));
}
__device__ __forceinline__ void cp_commit() {
    asm volatile("cp.async.commit_group;\n");
}
__device__ __forceinline__ void cp_wait0() {
    asm volatile("cp.async.wait_group 0;\n");
}
__device__ __forceinline__ u32 f2tf32(float f) {
    u32 r;
    asm("cvt.rna.tf32.f32 %0, %1;" : "=r"(r) : "f"(f));
    return r;
}

// All asm operands are plain scalars (compile-safe).
__device__ __forceinline__ void mma_tf32(float* acc,
                                         u32 a0, u32 a1, u32 a2, u32 a3,
                                         u32 b0, u32 b1)
{
    float d0 = acc[0], d1 = acc[1], d2 = acc[2], d3 = acc[3];
    asm volatile(
        "mma.sync.aligned.m16n8k8.row.col.f32.tf32.tf32.f32 "
        "{%0,%1,%2,%3}, {%4,%5,%6,%7}, {%8,%9}, {%0,%1,%2,%3};"
        : "+f"(d0), "+f"(d1), "+f"(d2), "+f"(d3)
        : "r"(a0), "r"(a1), "r"(a2), "r"(a3), "r"(b0), "r"(b1));
    acc[0] = d0; acc[1] = d1; acc[2] = d2; acc[3] = d3;
}

template<int MODE>
__global__ __launch_bounds__(256, 2)
void mma_gemm(const float* __restrict__ A, const float* __restrict__ B,
              const float* __restrict__ bias, const float* __restrict__ R,
              float* __restrict__ C, int M, int N, int K, float scale)
{
    extern __shared__ float smem[];
    float* AsBase = smem;                 // [2][128][ASTRIDE]
    float* BsBase = smem + 2 * A_STAGE;   // [2][32][BSTRIDE]

    const int tid  = threadIdx.x;
    const int lane = tid & 31;
    const int warp = tid >> 5;
    const int wm   = (warp >> 2) * 64;    // 0 / 64
    const int wn   = (warp & 3) * 32;     // 0,32,64,96
    const int bm   = blockIdx.y * 128;
    const int bn   = blockIdx.x * 128;
    const int gid  = lane >> 2;           // group id 0..7
    const int tig  = lane & 3;            // thread-in-group

    float acc[4][4][4];
    #pragma unroll
    for (int mi = 0; mi < 4; mi++)
        #pragma unroll
        for (int ni = 0; ni < 4; ni++)
            #pragma unroll
            for (int r = 0; r < 4; r++) acc[mi][ni][r] = 0.f;

    const int T = K / 32;

    // prologue: tile 0 -> stage 0
    {
        const float* Ag = A + (size_t)bm * K;
        const float* Bg = B + bn;
        #pragma unroll
        for (int i = 0; i < 4; i++) {
            int idx = tid + i * 256;
            int r = idx >> 3, c = (idx & 7) * 4;
            cp_async16(AsBase + r * ASTRIDE + c, Ag + (size_t)r * K + c);
            int br = idx >> 5, bc = (idx & 31) * 4;
            cp_async16(BsBase + br * BSTRIDE + bc, Bg + (size_t)br * N + bc);
        }
        cp_commit();
    }

    int cur = 0;
    for (int t = 0; t < T; t++) {
        cp_wait0();
        __syncthreads();

        if (t + 1 < T) {
            int k0 = (t + 1) * 32;
            float* as = AsBase + (cur ^ 1) * A_STAGE;
            float* bs = BsBase + (cur ^ 1) * B_STAGE;
            const float* Ag = A + (size_t)bm * K + k0;
            const float* Bg = B + (size_t)k0 * N + bn;
            #pragma unroll
            for (int i = 0; i < 4; i++) {
                int idx = tid + i * 256;
                int r = idx >> 3, c = (idx & 7) * 4;
                cp_async16(as + r * ASTRIDE + c, Ag + (size_t)r * K + c);
                int br = idx >> 5, bc = (idx & 31) * 4;
                cp_async16(bs + br * BSTRIDE + bc, Bg + (size_t)br * N + bc);
            }
            cp_commit();
        }

        const float* as = AsBase + cur * A_STAGE;
        const float* bs = BsBase + cur * B_STAGE;

        #pragma unroll
        for (int kk = 0; kk < 32; kk += 8) {
            // A fragments: direct LDS, conflict-free via ASTRIDE=36
            u32 afrag[4][4];
            #pragma unroll
            for (int mi = 0; mi < 4; mi++) {
                const float* ap = as + (wm + mi * 16 + gid) * ASTRIDE + kk + tig;
                u32 t0 = f2tf32(ap[0]);
                u32 t1 = f2tf32(ap[8 * ASTRIDE]);
                u32 t2 = f2tf32(ap[4]);
                u32 t3 = f2tf32(ap[8 * ASTRIDE + 4]);
                afrag[mi][0] = t0; afrag[mi][1] = t1;
                afrag[mi][2] = t2; afrag[mi][3] = t3;
            }
            // B fragments: conflict-free via BSTRIDE=136
            u32 bfrag[4][2];
            #pragma unroll
            for (int ni = 0; ni < 4; ni++) {
                const float* bp = bs + (kk + tig) * BSTRIDE + wn + ni * 8 + gid;
                u32 u0 = f2tf32(bp[0]);
                u32 u1 = f2tf32(bp[4 * BSTRIDE]);
                bfrag[ni][0] = u0; bfrag[ni][1] = u1;
            }
            #pragma unroll
            for (int mi = 0; mi < 4; mi++) {
                u32 a0 = afrag[mi][0], a1 = afrag[mi][1];
                u32 a2 = afrag[mi][2], a3 = afrag[mi][3];
                #pragma unroll
                for (int ni = 0; ni < 4; ni++) {
                    u32 b0 = bfrag[ni][0], b1 = bfrag[ni][1];
                    mma_tf32(&acc[mi][ni][0], a0, a1, a2, a3, b0, b1);
                }
            }
        }
        __syncthreads();
        cur ^= 1;
    }

    // epilogue: frag (mi,ni): rows bm+wm+mi*16+gid+{0,8}, cols bn+wn+ni*8+tig*2+{0,1}
    const int rbase = bm + wm + gid;
    const int cbase = bn + wn + tig * 2;
    #pragma unroll
    for (int mi = 0; mi < 4; mi++) {
        #pragma unroll
        for (int half = 0; half < 2; half++) {
            int r = rbase + mi * 16 + half * 8;
            #pragma unroll
            for (int ni = 0; ni < 4; ni++) {
                int c = cbase + ni * 8;
                float v0 = acc[mi][ni][half * 2 + 0] + bias[c];
                float v1 = acc[mi][ni][half * 2 + 1] + bias[c + 1];
                float2 o2;
                if (MODE == 1) {
                    o2.x = gelu_tanh(v0);
                    o2.y = gelu_tanh(v1);
                } else if (MODE == 2) {
                    const float2 rr = *(const float2*)(R + (size_t)r * N + c);
                    o2.x = rr.x + v0 * scale;
                    o2.y = rr.y + v1 * scale;
                } else {
                    o2.x = v0; o2.y = v1;
                }
                *(float2*)(C + (size_t)r * N + c) = o2;
            }
        }
    }
}

// ---------------- block-local causal attention ----------------
__global__ __launch_bounds__(256)
void attn_kernel(const float* __restrict__ q, const float* __restrict__ k,
                 const float* __restrict__ v, float* __restrict__ ctx)
{
    __shared__ float qs[64][64];
    __shared__ float ks[64][64];
    __shared__ float vs[64][64];

    int tid = threadIdx.x;
    int rowbase = blockIdx.z * SS + blockIdx.x * 64;
    int colbase = blockIdx.y * 64;

    #pragma unroll
    for (int i = 0; i < 4; i++) {
        int idx = tid + i * 256;
        int r = idx >> 4, c4 = idx & 15;
        size_t off = (size_t)(rowbase + r) * DD + colbase + c4 * 4;
        *(float4*)&qs[r][c4*4] = *(const float4*)(q + off);
        *(float4*)&ks[r][c4*4] = *(const float4*)(k + off);
        *(float4*)&vs[r][c4*4] = *(const float4*)(v + off);
    }
    __syncthreads();

    int qi = tid >> 2;
    int jg = (tid & 3) * 16;

    float sc[16];
    float m = -1e30f;
    #pragma unroll
    for (int jj = 0; jj < 16; jj++) {
        int j = jg + jj;
        float s = -1e30f;
        if (j <= qi) {
            s = 0.f;
            #pragma unroll
            for (int d = 0; d < 64; d++) s += qs[qi][d] * ks[j][d];
            s *= 0.125f;
            m = fmaxf(m, s);
        }
        sc[jj] = s;
    }
    m = fmaxf(m, __shfl_xor_sync(0xffffffffu, m, 1));
    m = fmaxf(m, __shfl_xor_sync(0xffffffffu, m, 2));

    float sum = 0.f;
    #pragma unroll
    for (int jj = 0; jj < 16; jj++) {
        float e = (jg + jj <= qi) ? expf(sc[jj] - m) : 0.f;
        sc[jj] = e;
        sum += e;
    }
    sum += __shfl_xor_sync(0xffffffffu, sum, 1);
    sum += __shfl_xor_sync(0xffffffffu, sum, 2);
    float inv = 1.f / sum;

    __syncthreads();
    #pragma unroll
    for (int jj = 0; jj < 16; jj++)
        ks[qi][jg + jj] = sc[jj] * inv;
    __syncthreads();

    float out[16];
    #pragma unroll
    for (int dd = 0; dd < 16; dd++) out[dd] = 0.f;
    for (int j = 0; j <= qi; j++) {
        float p = ks[qi][j];
        #pragma unroll
        for (int dd = 0; dd < 16; dd++)
            out[dd] += p * vs[j][jg + dd];
    }

    float* dst = ctx + (size_t)(rowbase + qi) * DD + colbase + jg;
    #pragma unroll
    for (int dd = 0; dd < 16; dd += 4) {
        float4 o4 = make_float4(out[dd], out[dd+1], out[dd+2], out[dd+3]);
        *(float4*)(dst + dd) = o4;
    }
}

// ---------------- launch ----------------
extern "C" void kernel_launch(void* const* d_in, const int* in_sizes, int n_in,
                              void* d_out, int out_size)
{
    const float* x    = (const float*)d_in[0];
    const float* Wq   = (const float*)d_in[2];
    const float* bq   = (const float*)d_in[3];
    const float* Wk   = (const float*)d_in[4];
    const float* bk   = (const float*)d_in[5];
    const float* Wv   = (const float*)d_in[6];
    const float* bv   = (const float*)d_in[7];
    const float* Wo   = (const float*)d_in[8];
    const float* bo   = (const float*)d_in[9];
    const float* ln1g = (const float*)d_in[10];
    const float* ln1b = (const float*)d_in[11];
    const float* ln2g = (const float*)d_in[12];
    const float* ln2b = (const float*)d_in[13];
    const float* W1   = (const float*)d_in[14];
    const float* b1   = (const float*)d_in[15];
    const float* W2   = (const float*)d_in[16];
    const float* b2   = (const float*)d_in[17];
    float* out = (float*)d_out;

    float *h, *q, *k, *v, *ctx, *x1, *ff;
    cudaGetSymbolAddress((void**)&h,   g_h);
    cudaGetSymbolAddress((void**)&q,   g_q);
    cudaGetSymbolAddress((void**)&k,   g_k);
    cudaGetSymbolAddress((void**)&v,   g_v);
    cudaGetSymbolAddress((void**)&ctx, g_ctx);
    cudaGetSymbolAddress((void**)&x1,  g_x1);
    cudaGetSymbolAddress((void**)&ff,  g_ff);

    cudaFuncSetAttribute(mma_gemm<0>, cudaFuncAttributeMaxDynamicSharedMemorySize, SMEM_BYTES);
    cudaFuncSetAttribute(mma_gemm<1>, cudaFuncAttributeMaxDynamicSharedMemorySize, SMEM_BYTES);
    cudaFuncSetAttribute(mma_gemm<2>, cudaFuncAttributeMaxDynamicSharedMemorySize, SMEM_BYTES);

    // 1. LN1
    ln_kernel<<<MROWS, 256>>>(x, ln1g, ln1b, h);

    // 2. QKV projections
    dim3 gD(DD / 128, MROWS / 128);     // (8, 32)
    mma_gemm<0><<<gD, 256, SMEM_BYTES>>>(h, Wq, bq, nullptr, q, MROWS, DD, DD, 0.f);
    mma_gemm<0><<<gD, 256, SMEM_BYTES>>>(h, Wk, bk, nullptr, k, MROWS, DD, DD, 0.f);
    mma_gemm<0><<<gD, 256, SMEM_BYTES>>>(h, Wv, bv, nullptr, v, MROWS, DD, DD, 0.f);

    // 3. attention
    dim3 gA(SS / 64, HH, BB);
    attn_kernel<<<gA, 256>>>(q, k, v, ctx);

    // 4. x1 = x + (ctx @ Wo + bo) * res_scale
    mma_gemm<2><<<gD, 256, SMEM_BYTES>>>(ctx, Wo, bo, x, x1, MROWS, DD, DD, RES_SCALE);

    // 5. LN2
    ln_kernel<<<MROWS, 256>>>(x1, ln2g, ln2b, h);

    // 6. ff = gelu(h @ W1 + b1)
    dim3 gF1(DFFN / 128, MROWS / 128);  // (32, 32)
    mma_gemm<1><<<gF1, 256, SMEM_BYTES>>>(h, W1, b1, nullptr, ff, MROWS, DFFN, DD, 0.f);

    // 7. out = x1 + (ff @ W2 + b2) * res_scale
    mma_gemm<2><<<gD, 256, SMEM_BYTES>>>(ff, W2, b2, x1, out, MROWS, DD, DFFN, RES_SCALE);
}

// round 5
// speedup vs baseline: 2.8959x; 1.1415x over previous
#include <cuda_runtime.h>
#include <cuda_bf16.h>
#include <math.h>

typedef unsigned int u32;

// Problem constants
#define BB 2
#define SS 2048
#define DD 1024
#define HH 16
#define DFFN 4096
#define MROWS (BB*SS)          // 4096
#define RES_SCALE 0.70710678118654752440f

// ---------------- device scratch (no allocs allowed) ----------------
__device__ float g_h  [MROWS * DD];
__device__ float g_q  [MROWS * DD];
__device__ float g_k  [MROWS * DD];
__device__ float g_v  [MROWS * DD];
__device__ float g_ctx[MROWS * DD];
__device__ float g_x1 [MROWS * DD];
__device__ float g_ff [MROWS * DFFN];
// tf32-pre-rounded weight copies
__device__ float g_wq [DD * DD];
__device__ float g_wk [DD * DD];
__device__ float g_wv [DD * DD];
__device__ float g_wo [DD * DD];
__device__ float g_w1 [DD * DFFN];
__device__ float g_w2 [DFFN * DD];

__device__ __forceinline__ u32 f2tf32(float f) {
    u32 r;
    asm("cvt.rna.tf32.f32 %0, %1;" : "=r"(r) : "f"(f));
    return r;
}
__device__ __forceinline__ float rnd_tf32(float f) {
    return __uint_as_float(f2tf32(f));
}

// ---------------- weight tf32 rounding pass ----------------
__global__ __launch_bounds__(256) void cvt_kernel(const float* __restrict__ in,
                                                  float* __restrict__ out, int n4)
{
    int i = blockIdx.x * 256 + threadIdx.x;
    if (i < n4) {
        float4 v = ((const float4*)in)[i];
        v.x = rnd_tf32(v.x); v.y = rnd_tf32(v.y);
        v.z = rnd_tf32(v.z); v.w = rnd_tf32(v.w);
        ((float4*)out)[i] = v;
    }
}

// ---------------- LayerNorm (output rounded to tf32) ----------------
__global__ __launch_bounds__(256) void ln_kernel(const float* __restrict__ x,
                                                 const float* __restrict__ g,
                                                 const float* __restrict__ b,
                                                 float* __restrict__ out)
{
    int row = blockIdx.x;
    int tid = threadIdx.x;
    const float4* xr = (const float4*)(x + (size_t)row * DD);
    float4 v = xr[tid];
    float s  = v.x + v.y + v.z + v.w;
    float ss = v.x*v.x + v.y*v.y + v.z*v.z + v.w*v.w;
    #pragma unroll
    for (int o = 16; o; o >>= 1) {
        s  += __shfl_xor_sync(0xffffffffu, s, o);
        ss += __shfl_xor_sync(0xffffffffu, ss, o);
    }
    __shared__ float sm1[8], sm2[8];
    int w = tid >> 5, l = tid & 31;
    if (l == 0) { sm1[w] = s; sm2[w] = ss; }
    __syncthreads();
    if (tid == 0) {
        float S = 0.f, SSu = 0.f;
        #pragma unroll
        for (int i = 0; i < 8; i++) { S += sm1[i]; SSu += sm2[i]; }
        float mu  = S  * (1.f / DD);
        float var = SSu * (1.f / DD) - mu * mu;
        sm1[0] = mu;
        sm2[0] = rsqrtf(var + 1e-5f);
    }
    __syncthreads();
    float mu  = sm1[0];
    float inv = sm2[0];
    float4 gg = ((const float4*)g)[tid];
    float4 bb = ((const float4*)b)[tid];
    float4 o4;
    o4.x = rnd_tf32((v.x - mu) * inv * gg.x + bb.x);
    o4.y = rnd_tf32((v.y - mu) * inv * gg.y + bb.y);
    o4.z = rnd_tf32((v.z - mu) * inv * gg.z + bb.z);
    o4.w = rnd_tf32((v.w - mu) * inv * gg.w + bb.w);
    ((float4*)(out + (size_t)row * DD))[tid] = o4;
}

// ---------------- TF32 tensor-core GEMM ----------------
// 128x128 CTA tile, BK=32, 4 warps each 64x64, mma.m16n8k8 tf32.
// Operands are PRE-ROUNDED to tf32 -> no cvt in the hot loop.
// MODE 0: C = A*B + bias
// MODE 1: C = tf32round(gelu_tanh(A*B + bias))   (feeds next GEMM)
// MODE 2: C = R + (A*B + bias) * scale

#define ASTRIDE 36      // 32 + 4 pad (floats) -> conflict-free frag loads
#define BSTRIDE 136     // 128 + 8 pad (floats) -> conflict-free frag loads
#define A_STAGE (128 * ASTRIDE)
#define B_STAGE (32 * BSTRIDE)
#define SMEM_FLOATS (2 * A_STAGE + 2 * B_STAGE)
#define SMEM_BYTES (SMEM_FLOATS * 4)

__device__ __forceinline__ float gelu_tanh(float x) {
    float x3 = x * x * x;
    return 0.5f * x * (1.f + tanhf(0.7978845608028654f * (x + 0.044715f * x3)));
}

__device__ __forceinline__ void cp_async16(float* dst, const float* src) {
    u32 d = (u32)__cvta_generic_to_shared(dst);
    asm volatile("cp.async.cg.shared.global [%0], [%1], 16;\n" :: "r"(d), "l"(src));
}
__device__ __forceinline__ void cp_commit() {
    asm volatile("cp.async.commit_group;\n");
}
__device__ __forceinline__ void cp_wait0() {
    asm volatile("cp.async.wait_group 0;\n");
}

// All asm operands are plain scalars (compile-safe).
__device__ __forceinline__ void mma_tf32(float* acc,
                                         u32 a0, u32 a1, u32 a2, u32 a3,
                                         u32 b0, u32 b1)
{
    float d0 = acc[0], d1 = acc[1], d2 = acc[2], d3 = acc[3];
    asm volatile(
        "mma.sync.aligned.m16n8k8.row.col.f32.tf32.tf32.f32 "
        "{%0,%1,%2,%3}, {%4,%5,%6,%7}, {%8,%9}, {%0,%1,%2,%3};"
        : "+f"(d0), "+f"(d1), "+f"(d2), "+f"(d3)
        : "r"(a0), "r"(a1), "r"(a2), "r"(a3), "r"(b0), "r"(b1));
    acc[0] = d0; acc[1] = d1; acc[2] = d2; acc[3] = d3;
}

template<int MODE>
__global__ __launch_bounds__(128, 2)
void mma_gemm(const float* __restrict__ A, const float* __restrict__ B,
              const float* __restrict__ bias, const float* __restrict__ R,
              float* __restrict__ C, int M, int N, int K, float scale)
{
    extern __shared__ float smem[];
    float* AsBase = smem;                 // [2][128][ASTRIDE]
    float* BsBase = smem + 2 * A_STAGE;   // [2][32][BSTRIDE]

    const int tid  = threadIdx.x;
    const int lane = tid & 31;
    const int warp = tid >> 5;            // 0..3
    const int wm   = (warp >> 1) * 64;    // 0 / 64
    const int wn   = (warp & 1) * 64;     // 0 / 64
    const int bm   = blockIdx.y * 128;
    const int bn   = blockIdx.x * 128;
    const int gid  = lane >> 2;           // group id 0..7
    const int tig  = lane & 3;            // thread-in-group

    float acc[4][8][4];
    #pragma unroll
    for (int mi = 0; mi < 4; mi++)
        #pragma unroll
        for (int ni = 0; ni < 8; ni++)
            #pragma unroll
            for (int r = 0; r < 4; r++) acc[mi][ni][r] = 0.f;

    const int T = K / 32;

    // prologue: tile 0 -> stage 0
    {
        const float* Ag = A + (size_t)bm * K;
        const float* Bg = B + bn;
        #pragma unroll
        for (int i = 0; i < 8; i++) {
            int idx = tid + i * 128;
            int r = idx >> 3, c = (idx & 7) * 4;
            cp_async16(AsBase + r * ASTRIDE + c, Ag + (size_t)r * K + c);
            int br = idx >> 5, bc = (idx & 31) * 4;
            cp_async16(BsBase + br * BSTRIDE + bc, Bg + (size_t)br * N + bc);
        }
        cp_commit();
    }

    int cur = 0;
    for (int t = 0; t < T; t++) {
        cp_wait0();
        __syncthreads();

        if (t + 1 < T) {
            int k0 = (t + 1) * 32;
            float* as = AsBase + (cur ^ 1) * A_STAGE;
            float* bs = BsBase + (cur ^ 1) * B_STAGE;
            const float* Ag = A + (size_t)bm * K + k0;
            const float* Bg = B + (size_t)k0 * N + bn;
            #pragma unroll
            for (int i = 0; i < 8; i++) {
                int idx = tid + i * 128;
                int r = idx >> 3, c = (idx & 7) * 4;
                cp_async16(as + r * ASTRIDE + c, Ag + (size_t)r * K + c);
                int br = idx >> 5, bc = (idx & 31) * 4;
                cp_async16(bs + br * BSTRIDE + bc, Bg + (size_t)br * N + bc);
            }
            cp_commit();
        }

        const u32* as = (const u32*)(AsBase + cur * A_STAGE);
        const u32* bs = (const u32*)(BsBase + cur * B_STAGE);

        #pragma unroll
        for (int kk = 0; kk < 32; kk += 8) {
            // A fragments: direct LDS (pre-rounded tf32 bits), conflict-free
            u32 afrag[4][4];
            #pragma unroll
            for (int mi = 0; mi < 4; mi++) {
                const u32* ap = as + (wm + mi * 16 + gid) * ASTRIDE + kk + tig;
                u32 t0 = ap[0];
                u32 t1 = ap[8 * ASTRIDE];
                u32 t2 = ap[4];
                u32 t3 = ap[8 * ASTRIDE + 4];
                afrag[mi][0] = t0; afrag[mi][1] = t1;
                afrag[mi][2] = t2; afrag[mi][3] = t3;
            }
            // B fragments: conflict-free
            u32 bfrag[8][2];
            #pragma unroll
            for (int ni = 0; ni < 8; ni++) {
                const u32* bp = bs + (kk + tig) * BSTRIDE + wn + ni * 8 + gid;
                u32 u0 = bp[0];
                u32 u1 = bp[4 * BSTRIDE];
                bfrag[ni][0] = u0; bfrag[ni][1] = u1;
            }
            #pragma unroll
            for (int mi = 0; mi < 4; mi++) {
                u32 a0 = afrag[mi][0], a1 = afrag[mi][1];
                u32 a2 = afrag[mi][2], a3 = afrag[mi][3];
                #pragma unroll
                for (int ni = 0; ni < 8; ni++) {
                    u32 b0 = bfrag[ni][0], b1 = bfrag[ni][1];
                    mma_tf32(&acc[mi][ni][0], a0, a1, a2, a3, b0, b1);
                }
            }
        }
        __syncthreads();
        cur ^= 1;
    }

    // epilogue
    const int rbase = bm + wm + gid;
    const int cbase = bn + wn + tig * 2;
    #pragma unroll
    for (int mi = 0; mi < 4; mi++) {
        #pragma unroll
        for (int half = 0; half < 2; half++) {
            int r = rbase + mi * 16 + half * 8;
            #pragma unroll
            for (int ni = 0; ni < 8; ni++) {
                int c = cbase + ni * 8;
                float v0 = acc[mi][ni][half * 2 + 0] + bias[c];
                float v1 = acc[mi][ni][half * 2 + 1] + bias[c + 1];
                float2 o2;
                if (MODE == 1) {
                    o2.x = rnd_tf32(gelu_tanh(v0));
                    o2.y = rnd_tf32(gelu_tanh(v1));
                } else if (MODE == 2) {
                    const float2 rr = *(const float2*)(R + (size_t)r * N + c);
                    o2.x = rr.x + v0 * scale;
                    o2.y = rr.y + v1 * scale;
                } else {
                    o2.x = v0; o2.y = v1;
                }
                *(float2*)(C + (size_t)r * N + c) = o2;
            }
        }
    }
}

// ---------------- block-local causal attention (output rounded to tf32) ----------------
__global__ __launch_bounds__(256)
void attn_kernel(const float* __restrict__ q, const float* __restrict__ k,
                 const float* __restrict__ v, float* __restrict__ ctx)
{
    __shared__ float qs[64][64];
    __shared__ float ks[64][64];
    __shared__ float vs[64][64];

    int tid = threadIdx.x;
    int rowbase = blockIdx.z * SS + blockIdx.x * 64;
    int colbase = blockIdx.y * 64;

    #pragma unroll
    for (int i = 0; i < 4; i++) {
        int idx = tid + i * 256;
        int r = idx >> 4, c4 = idx & 15;
        size_t off = (size_t)(rowbase + r) * DD + colbase + c4 * 4;
        *(float4*)&qs[r][c4*4] = *(const float4*)(q + off);
        *(float4*)&ks[r][c4*4] = *(const float4*)(k + off);
        *(float4*)&vs[r][c4*4] = *(const float4*)(v + off);
    }
    __syncthreads();

    int qi = tid >> 2;
    int jg = (tid & 3) * 16;

    float sc[16];
    float m = -1e30f;
    #pragma unroll
    for (int jj = 0; jj < 16; jj++) {
        int j = jg + jj;
        float s = -1e30f;
        if (j <= qi) {
            s = 0.f;
            #pragma unroll
            for (int d = 0; d < 64; d++) s += qs[qi][d] * ks[j][d];
            s *= 0.125f;
            m = fmaxf(m, s);
        }
        sc[jj] = s;
    }
    m = fmaxf(m, __shfl_xor_sync(0xffffffffu, m, 1));
    m = fmaxf(m, __shfl_xor_sync(0xffffffffu, m, 2));

    float sum = 0.f;
    #pragma unroll
    for (int jj = 0; jj < 16; jj++) {
        float e = (jg + jj <= qi) ? expf(sc[jj] - m) : 0.f;
        sc[jj] = e;
        sum += e;
    }
    sum += __shfl_xor_sync(0xffffffffu, sum, 1);
    sum += __shfl_xor_sync(0xffffffffu, sum, 2);
    float inv = 1.f / sum;

    __syncthreads();
    #pragma unroll
    for (int jj = 0; jj < 16; jj++)
        ks[qi][jg + jj] = sc[jj] * inv;
    __syncthreads();

    float out[16];
    #pragma unroll
    for (int dd = 0; dd < 16; dd++) out[dd] = 0.f;
    for (int j = 0; j <= qi; j++) {
        float p = ks[qi][j];
        #pragma unroll
        for (int dd = 0; dd < 16; dd++)
            out[dd] += p * vs[j][jg + dd];
    }

    float* dst = ctx + (size_t)(rowbase + qi) * DD + colbase + jg;
    #pragma unroll
    for (int dd = 0; dd < 16; dd += 4) {
        float4 o4 = make_float4(rnd_tf32(out[dd]),   rnd_tf32(out[dd+1]),
                                rnd_tf32(out[dd+2]), rnd_tf32(out[dd+3]));
        *(float4*)(dst + dd) = o4;
    }
}

// ---------------- launch ----------------
extern "C" void kernel_launch(void* const* d_in, const int* in_sizes, int n_in,
                              void* d_out, int out_size)
{
    const float* x    = (const float*)d_in[0];
    const float* Wq   = (const float*)d_in[2];
    const float* bq   = (const float*)d_in[3];
    const float* Wk   = (const float*)d_in[4];
    const float* bk   = (const float*)d_in[5];
    const float* Wv   = (const float*)d_in[6];
    const float* bv   = (const float*)d_in[7];
    const float* Wo   = (const float*)d_in[8];
    const float* bo   = (const float*)d_in[9];
    const float* ln1g = (const float*)d_in[10];
    const float* ln1b = (const float*)d_in[11];
    const float* ln2g = (const float*)d_in[12];
    const float* ln2b = (const float*)d_in[13];
    const float* W1   = (const float*)d_in[14];
    const float* b1   = (const float*)d_in[15];
    const float* W2   = (const float*)d_in[16];
    const float* b2   = (const float*)d_in[17];
    float* out = (float*)d_out;

    float *h, *q, *k, *v, *ctx, *x1, *ff;
    float *wq, *wk, *wv, *wo, *w1, *w2;
    cudaGetSymbolAddress((void**)&h,   g_h);
    cudaGetSymbolAddress((void**)&q,   g_q);
    cudaGetSymbolAddress((void**)&k,   g_k);
    cudaGetSymbolAddress((void**)&v,   g_v);
    cudaGetSymbolAddress((void**)&ctx, g_ctx);
    cudaGetSymbolAddress((void**)&x1,  g_x1);
    cudaGetSymbolAddress((void**)&ff,  g_ff);
    cudaGetSymbolAddress((void**)&wq,  g_wq);
    cudaGetSymbolAddress((void**)&wk,  g_wk);
    cudaGetSymbolAddress((void**)&wv,  g_wv);
    cudaGetSymbolAddress((void**)&wo,  g_wo);
    cudaGetSymbolAddress((void**)&w1,  g_w1);
    cudaGetSymbolAddress((void**)&w2,  g_w2);

    cudaFuncSetAttribute(mma_gemm<0>, cudaFuncAttributeMaxDynamicSharedMemorySize, SMEM_BYTES);
    cudaFuncSetAttribute(mma_gemm<1>, cudaFuncAttributeMaxDynamicSharedMemorySize, SMEM_BYTES);
    cudaFuncSetAttribute(mma_gemm<2>, cudaFuncAttributeMaxDynamicSharedMemorySize, SMEM_BYTES);

    // 0. pre-round weights to tf32 (memory-bound, ~20us total)
    const int n4d  = DD * DD / 4;
    const int n4f  = DD * DFFN / 4;
    cvt_kernel<<<(n4d + 255) / 256, 256>>>(Wq, wq, n4d);
    cvt_kernel<<<(n4d + 255) / 256, 256>>>(Wk, wk, n4d);
    cvt_kernel<<<(n4d + 255) / 256, 256>>>(Wv, wv, n4d);
    cvt_kernel<<<(n4d + 255) / 256, 256>>>(Wo, wo, n4d);
    cvt_kernel<<<(n4f + 255) / 256, 256>>>(W1, w1, n4f);
    cvt_kernel<<<(n4f + 255) / 256, 256>>>(W2, w2, n4f);

    // 1. LN1 (tf32-rounded output)
    ln_kernel<<<MROWS, 256>>>(x, ln1g, ln1b, h);

    // 2. QKV projections
    dim3 gD(DD / 128, MROWS / 128);     // (8, 32)
    mma_gemm<0><<<gD, 128, SMEM_BYTES>>>(h, wq, bq, nullptr, q, MROWS, DD, DD, 0.f);
    mma_gemm<0><<<gD, 128, SMEM_BYTES>>>(h, wk, bk, nullptr, k, MROWS, DD, DD, 0.f);
    mma_gemm<0><<<gD, 128, SMEM_BYTES>>>(h, wv, bv, nullptr, v, MROWS, DD, DD, 0.f);

    // 3. attention (tf32-rounded ctx)
    dim3 gA(SS / 64, HH, BB);
    attn_kernel<<<gA, 256>>>(q, k, v, ctx);

    // 4. x1 = x + (ctx @ Wo + bo) * res_scale
    mma_gemm<2><<<gD, 128, SMEM_BYTES>>>(ctx, wo, bo, x, x1, MROWS, DD, DD, RES_SCALE);

    // 5. LN2 (tf32-rounded output)
    ln_kernel<<<MROWS, 256>>>(x1, ln2g, ln2b, h);

    // 6. ff = tf32round(gelu(h @ W1 + b1))
    dim3 gF1(DFFN / 128, MROWS / 128);  // (32, 32)
    mma_gemm<1><<<gF1, 128, SMEM_BYTES>>>(h, w1, b1, nullptr, ff, MROWS, DFFN, DD, 0.f);

    // 7. out = x1 + (ff @ W2 + b2) * res_scale
    mma_gemm<2><<<gD, 128, SMEM_BYTES>>>(ff, w2, b2, x1, out, MROWS, DD, DFFN, RES_SCALE);
}

// round 7
// speedup vs baseline: 2.9632x; 1.0232x over previous
#include <cuda_runtime.h>
#include <cuda_bf16.h>
#include <math.h>

typedef unsigned int u32;
typedef unsigned long long u64;

// Problem constants
#define BB 2
#define SS 2048
#define DD 1024
#define HH 16
#define DFFN 4096
#define MROWS (BB*SS)          // 4096
#define RES_SCALE 0.70710678118654752440f

// ---------------- device scratch ----------------
__device__ float g_h  [MROWS * DD];
__device__ float g_q  [MROWS * DD];
__device__ float g_k  [MROWS * DD];
__device__ float g_v  [MROWS * DD];
__device__ float g_ctx[MROWS * DD];
__device__ float g_x1 [MROWS * DD];
__device__ float g_ff [MROWS * DFFN];
// tf32-rounded, TRANSPOSED weights: wT[n][k] = rnd(W[k][n])
__device__ float g_wq [DD * DD];
__device__ float g_wk [DD * DD];
__device__ float g_wv [DD * DD];
__device__ float g_wo [DD * DD];
__device__ float g_w1 [DFFN * DD];
__device__ float g_w2 [DD * DFFN];

__device__ __forceinline__ u32 f2tf32(float f) {
    u32 r;
    asm("cvt.rna.tf32.f32 %0, %1;" : "=r"(r) : "f"(f));
    return r;
}
__device__ __forceinline__ float rnd_tf32(float f) {
    return __uint_as_float(f2tf32(f));
}

// ---------------- weight round + transpose: out[n][k] = rnd(in[k][n]) ----------------
// in: [Kdim][Ndim] row-major. grid (Ndim/32, Kdim/32), block (32,8)
__global__ __launch_bounds__(256) void cvtT_kernel(const float* __restrict__ in,
                                                   float* __restrict__ out,
                                                   int Kdim, int Ndim)
{
    __shared__ float sm[32][33];
    int n0 = blockIdx.x * 32;
    int k0 = blockIdx.y * 32;
    int tx = threadIdx.x, ty = threadIdx.y;
    #pragma unroll
    for (int i = 0; i < 4; i++) {
        int r = ty + i * 8;                       // k-local
        sm[r][tx] = rnd_tf32(in[(size_t)(k0 + r) * Ndim + n0 + tx]);
    }
    __syncthreads();
    #pragma unroll
    for (int i = 0; i < 4; i++) {
        int r = ty + i * 8;                       // n-local
        out[(size_t)(n0 + r) * Kdim + k0 + tx] = sm[tx][r];
    }
}

// ---------------- LayerNorm (output rounded to tf32) ----------------
__global__ __launch_bounds__(256) void ln_kernel(const float* __restrict__ x,
                                                 const float* __restrict__ g,
                                                 const float* __restrict__ b,
                                                 float* __restrict__ out)
{
    int row = blockIdx.x;
    int tid = threadIdx.x;
    const float4* xr = (const float4*)(x + (size_t)row * DD);
    float4 v = xr[tid];
    float s  = v.x + v.y + v.z + v.w;
    float ss = v.x*v.x + v.y*v.y + v.z*v.z + v.w*v.w;
    #pragma unroll
    for (int o = 16; o; o >>= 1) {
        s  += __shfl_xor_sync(0xffffffffu, s, o);
        ss += __shfl_xor_sync(0xffffffffu, ss, o);
    }
    __shared__ float sm1[8], sm2[8];
    int w = tid >> 5, l = tid & 31;
    if (l == 0) { sm1[w] = s; sm2[w] = ss; }
    __syncthreads();
    if (tid == 0) {
        float S = 0.f, SSu = 0.f;
        #pragma unroll
        for (int i = 0; i < 8; i++) { S += sm1[i]; SSu += sm2[i]; }
        float mu  = S  * (1.f / DD);
        float var = SSu * (1.f / DD) - mu * mu;
        sm1[0] = mu;
        sm2[0] = rsqrtf(var + 1e-5f);
    }
    __syncthreads();
    float mu  = sm1[0];
    float inv = sm2[0];
    float4 gg = ((const float4*)g)[tid];
    float4 bb = ((const float4*)b)[tid];
    float4 o4;
    o4.x = rnd_tf32((v.x - mu) * inv * gg.x + bb.x);
    o4.y = rnd_tf32((v.y - mu) * inv * gg.y + bb.y);
    o4.z = rnd_tf32((v.z - mu) * inv * gg.z + bb.z);
    o4.w = rnd_tf32((v.w - mu) * inv * gg.w + bb.w);
    ((float4*)(out + (size_t)row * DD))[tid] = o4;
}

// ---------------- TF32 tensor-core GEMM (mma.sync + ldmatrix) ----------------
// 128x128 CTA tile, BK=32, 4 warps each 64x64.
// A smem: [128 m][32 k] stride 36.  B smem: [128 n][32 k] stride 36 (from wT[n][k]).
// Operands pre-rounded to tf32 -> no cvt in hot loop; fragments via ldmatrix.x4.
// MODE 0: C = A*B^T + bias
// MODE 1: C = tf32round(gelu_tanh(.))
// MODE 2: C = R + (.) * scale

#define TSTRIDE 36            // 32 + 4 pad floats
#define OP_STAGE (128 * TSTRIDE)              // floats per operand per stage
#define SMEM_FLOATS (4 * OP_STAGE)            // 2 ops x 2 stages
#define SMEM_BYTES (SMEM_FLOATS * 4)          // 73728 B

__device__ __forceinline__ float gelu_tanh(float x) {
    float x3 = x * x * x;
    return 0.5f * x * (1.f + tanhf(0.7978845608028654f * (x + 0.044715f * x3)));
}

__device__ __forceinline__ void cp_async16(float* dst, const float* src) {
    u32 d = (u32)__cvta_generic_to_shared(dst);
    asm volatile("cp.async.cg.shared.global [%0], [%1], 16;\n" :: "r"(d), "l"(src));
}
__device__ __forceinline__ void cp_commit() {
    asm volatile("cp.async.commit_group;\n");
}
__device__ __forceinline__ void cp_wait0() {
    asm volatile("cp.async.wait_group 0;\n" ::: "memory");
}

__device__ __forceinline__ void ldsm4(u32& r0, u32& r1, u32& r2, u32& r3, u32 addr) {
    asm volatile("ldmatrix.sync.aligned.m8n8.x4.shared.b16 {%0,%1,%2,%3}, [%4];"
                 : "=r"(r0), "=r"(r1), "=r"(r2), "=r"(r3) : "r"(addr));
}

__device__ __forceinline__ void mma_tf32(float* acc,
                                         u32 a0, u32 a1, u32 a2, u32 a3,
                                         u32 b0, u32 b1)
{
    float d0 = acc[0], d1 = acc[1], d2 = acc[2], d3 = acc[3];
    asm volatile(
        "mma.sync.aligned.m16n8k8.row.col.f32.tf32.tf32.f32 "
        "{%0,%1,%2,%3}, {%4,%5,%6,%7}, {%8,%9}, {%0,%1,%2,%3};"
        : "+f"(d0), "+f"(d1), "+f"(d2), "+f"(d3)
        : "r"(a0), "r"(a1), "r"(a2), "r"(a3), "r"(b0), "r"(b1));
    acc[0] = d0; acc[1] = d1; acc[2] = d2; acc[3] = d3;
}

template<int MODE>
__global__ __launch_bounds__(128, 2)
void mma_gemm(const float* __restrict__ A, const float* __restrict__ Bt,
              const float* __restrict__ bias, const float* __restrict__ R,
              float* __restrict__ C, int M, int N, int K, float scale)
{
    extern __shared__ float smem[];
    float* AsBase = smem;                   // [2][128][TSTRIDE]
    float* BsBase = smem + 2 * OP_STAGE;    // [2][128][TSTRIDE]

    const int tid  = threadIdx.x;
    const int lane = tid & 31;
    const int warp = tid >> 5;              // 0..3
    const int wm   = (warp >> 1) * 64;      // 0 / 64
    const int wn   = (warp & 1) * 64;       // 0 / 64
    const int bm   = blockIdx.y * 128;
    const int bn   = blockIdx.x * 128;
    const int gid  = lane >> 2;
    const int tig  = lane & 3;

    // ldmatrix per-lane byte offsets (within an operand stage), kk=0:
    //   tl = lane>>3 selects sub-tile; ri = lane&7 is row-in-tile.
    // A: row = wm + mi*16 + (tl&1)*8 + ri, col4 = (tl>>1)*4
    // B: row = wn + ni*8 + (tl>>1)*8 + ri, col4 = (tl&1)*4     (ni pair base, covers ni,ni+1)
    const int tl = lane >> 3, ri = lane & 7;
    const u32 aoff0 = (u32)(((wm + (tl & 1) * 8 + ri) * TSTRIDE + (tl >> 1) * 4) * 4);
    const u32 boff0 = (u32)(((wn + (tl >> 1) * 8 + ri) * TSTRIDE + (tl & 1) * 4) * 4);

    float acc[4][8][4];
    #pragma unroll
    for (int mi = 0; mi < 4; mi++)
        #pragma unroll
        for (int ni = 0; ni < 8; ni++)
            #pragma unroll
            for (int r = 0; r < 4; r++) acc[mi][ni][r] = 0.f;

    const int T = K / 32;

    // stage loader: A rows bm+*, B rows bn+* ; both [.][K] row-major gmem
    // 128 rows x 8 chunks of 16B each, 128 threads -> 8 iters per operand
    {
        const float* Ag = A + (size_t)bm * K;
        const float* Bg = Bt + (size_t)bn * K;
        #pragma unroll
        for (int i = 0; i < 8; i++) {
            int idx = tid + i * 128;
            int r = idx >> 3, c = (idx & 7) * 4;
            cp_async16(AsBase + r * TSTRIDE + c, Ag + (size_t)r * K + c);
            cp_async16(BsBase + r * TSTRIDE + c, Bg + (size_t)r * K + c);
        }
        cp_commit();
    }

    int cur = 0;
    for (int t = 0; t < T; t++) {
        cp_wait0();
        __syncthreads();

        if (t + 1 < T) {
            int k0 = (t + 1) * 32;
            float* as = AsBase + (cur ^ 1) * OP_STAGE;
            float* bs = BsBase + (cur ^ 1) * OP_STAGE;
            const float* Ag = A + (size_t)bm * K + k0;
            const float* Bg = Bt + (size_t)bn * K + k0;
            #pragma unroll
            for (int i = 0; i < 8; i++) {
                int idx = tid + i * 128;
                int r = idx >> 3, c = (idx & 7) * 4;
                cp_async16(as + r * TSTRIDE + c, Ag + (size_t)r * K + c);
                cp_async16(bs + r * TSTRIDE + c, Bg + (size_t)r * K + c);
            }
            cp_commit();
        }

        const u32 asAddr = (u32)__cvta_generic_to_shared(AsBase + cur * OP_STAGE);
        const u32 bsAddr = (u32)__cvta_generic_to_shared(BsBase + cur * OP_STAGE);

        #pragma unroll
        for (int kk = 0; kk < 32; kk += 8) {
            const u32 kb = (u32)(kk * 4);
            // A fragments: 4 ldmatrix.x4 (one per mi)
            u32 afrag[4][4];
            #pragma unroll
            for (int mi = 0; mi < 4; mi++) {
                u32 r0, r1, r2, r3;
                ldsm4(r0, r1, r2, r3, asAddr + aoff0 + (u32)(mi * 16 * TSTRIDE * 4) + kb);
                afrag[mi][0] = r0; afrag[mi][1] = r1;
                afrag[mi][2] = r2; afrag[mi][3] = r3;
            }
            // B fragments: 4 ldmatrix.x4 (each covers ni, ni+1)
            u32 bfrag[8][2];
            #pragma unroll
            for (int np = 0; np < 4; np++) {
                u32 r0, r1, r2, r3;
                ldsm4(r0, r1, r2, r3, bsAddr + boff0 + (u32)(np * 16 * TSTRIDE * 4) + kb);
                bfrag[np * 2 + 0][0] = r0; bfrag[np * 2 + 0][1] = r1;
                bfrag[np * 2 + 1][0] = r2; bfrag[np * 2 + 1][1] = r3;
            }
            #pragma unroll
            for (int mi = 0; mi < 4; mi++) {
                u32 a0 = afrag[mi][0], a1 = afrag[mi][1];
                u32 a2 = afrag[mi][2], a3 = afrag[mi][3];
                #pragma unroll
                for (int ni = 0; ni < 8; ni++) {
                    u32 b0 = bfrag[ni][0], b1 = bfrag[ni][1];
                    mma_tf32(&acc[mi][ni][0], a0, a1, a2, a3, b0, b1);
                }
            }
        }
        __syncthreads();
        cur ^= 1;
    }

    // epilogue: frag (mi,ni): rows bm+wm+mi*16+gid+{0,8}, cols bn+wn+ni*8+tig*2+{0,1}
    const int rbase = bm + wm + gid;
    const int cbase = bn + wn + tig * 2;
    #pragma unroll
    for (int mi = 0; mi < 4; mi++) {
        #pragma unroll
        for (int half = 0; half < 2; half++) {
            int r = rbase + mi * 16 + half * 8;
            #pragma unroll
            for (int ni = 0; ni < 8; ni++) {
                int c = cbase + ni * 8;
                float v0 = acc[mi][ni][half * 2 + 0] + bias[c];
                float v1 = acc[mi][ni][half * 2 + 1] + bias[c + 1];
                float2 o2;
                if (MODE == 1) {
                    o2.x = rnd_tf32(gelu_tanh(v0));
                    o2.y = rnd_tf32(gelu_tanh(v1));
                } else if (MODE == 2) {
                    const float2 rr = *(const float2*)(R + (size_t)r * N + c);
                    o2.x = rr.x + v0 * scale;
                    o2.y = rr.y + v1 * scale;
                } else {
                    o2.x = v0; o2.y = v1;
                }
                *(float2*)(C + (size_t)r * N + c) = o2;
            }
        }
    }
}

// ---------------- block-local causal attention (ctx rounded to tf32) ----------------
__global__ __launch_bounds__(256)
void attn_kernel(const float* __restrict__ q, const float* __restrict__ k,
                 const float* __restrict__ v, float* __restrict__ ctx)
{
    __shared__ float qs[64][64];
    __shared__ float ks[64][64];
    __shared__ float vs[64][64];

    int tid = threadIdx.x;
    int rowbase = blockIdx.z * SS + blockIdx.x * 64;
    int colbase = blockIdx.y * 64;

    #pragma unroll
    for (int i = 0; i < 4; i++) {
        int idx = tid + i * 256;
        int r = idx >> 4, c4 = idx & 15;
        size_t off = (size_t)(rowbase + r) * DD + colbase + c4 * 4;
        *(float4*)&qs[r][c4*4] = *(const float4*)(q + off);
        *(float4*)&ks[r][c4*4] = *(const float4*)(k + off);
        *(float4*)&vs[r][c4*4] = *(const float4*)(v + off);
    }
    __syncthreads();

    int qi = tid >> 2;
    int jg = (tid & 3) * 16;

    float sc[16];
    float m = -1e30f;
    #pragma unroll
    for (int jj = 0; jj < 16; jj++) {
        int j = jg + jj;
        float s = -1e30f;
        if (j <= qi) {
            s = 0.f;
            #pragma unroll
            for (int d = 0; d < 64; d++) s += qs[qi][d] * ks[j][d];
            s *= 0.125f;
            m = fmaxf(m, s);
        }
        sc[jj] = s;
    }
    m = fmaxf(m, __shfl_xor_sync(0xffffffffu, m, 1));
    m = fmaxf(m, __shfl_xor_sync(0xffffffffu, m, 2));

    float sum = 0.f;
    #pragma unroll
    for (int jj = 0; jj < 16; jj++) {
        float e = (jg + jj <= qi) ? expf(sc[jj] - m) : 0.f;
        sc[jj] = e;
        sum += e;
    }
    sum += __shfl_xor_sync(0xffffffffu, sum, 1);
    sum += __shfl_xor_sync(0xffffffffu, sum, 2);
    float inv = 1.f / sum;

    __syncthreads();
    #pragma unroll
    for (int jj = 0; jj < 16; jj++)
        ks[qi][jg + jj] = sc[jj] * inv;
    __syncthreads();

    float out[16];
    #pragma unroll
    for (int dd = 0; dd < 16; dd++) out[dd] = 0.f;
    for (int j = 0; j <= qi; j++) {
        float p = ks[qi][j];
        #pragma unroll
        for (int dd = 0; dd < 16; dd++)
            out[dd] += p * vs[j][jg + dd];
    }

    float* dst = ctx + (size_t)(rowbase + qi) * DD + colbase + jg;
    #pragma unroll
    for (int dd = 0; dd < 16; dd += 4) {
        float4 o4 = make_float4(rnd_tf32(out[dd]),   rnd_tf32(out[dd+1]),
                                rnd_tf32(out[dd+2]), rnd_tf32(out[dd+3]));
        *(float4*)(dst + dd) = o4;
    }
}

// ---------------- launch ----------------
extern "C" void kernel_launch(void* const* d_in, const int* in_sizes, int n_in,
                              void* d_out, int out_size)
{
    const float* x    = (const float*)d_in[0];
    const float* Wq   = (const float*)d_in[2];
    const float* bq   = (const float*)d_in[3];
    const float* Wk   = (const float*)d_in[4];
    const float* bk   = (const float*)d_in[5];
    const float* Wv   = (const float*)d_in[6];
    const float* bv   = (const float*)d_in[7];
    const float* Wo   = (const float*)d_in[8];
    const float* bo   = (const float*)d_in[9];
    const float* ln1g = (const float*)d_in[10];
    const float* ln1b = (const float*)d_in[11];
    const float* ln2g = (const float*)d_in[12];
    const float* ln2b = (const float*)d_in[13];
    const float* W1   = (const float*)d_in[14];
    const float* b1   = (const float*)d_in[15];
    const float* W2   = (const float*)d_in[16];
    const float* b2   = (const float*)d_in[17];
    float* out = (float*)d_out;

    float *h, *q, *k, *v, *ctx, *x1, *ff;
    float *wq, *wk, *wv, *wo, *w1, *w2;
    cudaGetSymbolAddress((void**)&h,   g_h);
    cudaGetSymbolAddress((void**)&q,   g_q);
    cudaGetSymbolAddress((void**)&k,   g_k);
    cudaGetSymbolAddress((void**)&v,   g_v);
    cudaGetSymbolAddress((void**)&ctx, g_ctx);
    cudaGetSymbolAddress((void**)&x1,  g_x1);
    cudaGetSymbolAddress((void**)&ff,  g_ff);
    cudaGetSymbolAddress((void**)&wq,  g_wq);
    cudaGetSymbolAddress((void**)&wk,  g_wk);
    cudaGetSymbolAddress((void**)&wv,  g_wv);
    cudaGetSymbolAddress((void**)&wo,  g_wo);
    cudaGetSymbolAddress((void**)&w1,  g_w1);
    cudaGetSymbolAddress((void**)&w2,  g_w2);

    cudaFuncSetAttribute(mma_gemm<0>, cudaFuncAttributeMaxDynamicSharedMemorySize, SMEM_BYTES);
    cudaFuncSetAttribute(mma_gemm<1>, cudaFuncAttributeMaxDynamicSharedMemorySize, SMEM_BYTES);
    cudaFuncSetAttribute(mma_gemm<2>, cudaFuncAttributeMaxDynamicSharedMemorySize, SMEM_BYTES);

    // 0. round + transpose weights:  wT[n][k] = tf32(W[k][n])
    dim3 tb(32, 8);
    cvtT_kernel<<<dim3(DD / 32,   DD / 32),   tb>>>(Wq, wq, DD, DD);
    cvtT_kernel<<<dim3(DD / 32,   DD / 32),   tb>>>(Wk, wk, DD, DD);
    cvtT_kernel<<<dim3(DD / 32,   DD / 32),   tb>>>(Wv, wv, DD, DD);
    cvtT_kernel<<<dim3(DD / 32,   DD / 32),   tb>>>(Wo, wo, DD, DD);
    cvtT_kernel<<<dim3(DFFN / 32, DD / 32),   tb>>>(W1, w1, DD, DFFN);
    cvtT_kernel<<<dim3(DD / 32,   DFFN / 32), tb>>>(W2, w2, DFFN, DD);

    // 1. LN1 (tf32-rounded h)
    ln_kernel<<<MROWS, 256>>>(x, ln1g, ln1b, h);

    // 2. QKV projections
    dim3 gD(DD / 128, MROWS / 128);     // (8, 32)
    mma_gemm<0><<<gD, 128, SMEM_BYTES>>>(h, wq, bq, nullptr, q, MROWS, DD, DD, 0.f);
    mma_gemm<0><<<gD, 128, SMEM_BYTES>>>(h, wk, bk, nullptr, k, MROWS, DD, DD, 0.f);
    mma_gemm<0><<<gD, 128, SMEM_BYTES>>>(h, wv, bv, nullptr, v, MROWS, DD, DD, 0.f);

    // 3. attention (tf32-rounded ctx)
    dim3 gA(SS / 64, HH, BB);
    attn_kernel<<<gA, 256>>>(q, k, v, ctx);

    // 4. x1 = x + (ctx @ Wo + bo) * res_scale
    mma_gemm<2><<<gD, 128, SMEM_BYTES>>>(ctx, wo, bo, x, x1, MROWS, DD, DD, RES_SCALE);

    // 5. LN2 (tf32-rounded h)
    ln_kernel<<<MROWS, 256>>>(x1, ln2g, ln2b, h);

    // 6. ff = tf32round(gelu(h @ W1 + b1))
    dim3 gF1(DFFN / 128, MROWS / 128);  // (32, 32)
    mma_gemm<1><<<gF1, 128, SMEM_BYTES>>>(h, w1, b1, nullptr, ff, MROWS, DFFN, DD, 0.f);

    // 7. out = x1 + (ff @ W2 + b2) * res_scale
    mma_gemm<2><<<gD, 128, SMEM_BYTES>>>(ff, w2, b2, x1, out, MROWS, DD, DFFN, RES_SCALE);
}

// round 8
// speedup vs baseline: 4.5176x; 1.5246x over previous
#include <cuda_runtime.h>
#include <cuda_fp16.h>
#include <math.h>

typedef unsigned int u32;

// Problem constants
#define BB 2
#define SS 2048
#define DD 1024
#define HH 16
#define DFFN 4096
#define MROWS (BB*SS)          // 4096
#define RES_SCALE 0.70710678118654752440f

// ---------------- device scratch ----------------
__device__ __half g_h  [MROWS * DD];
__device__ __half g_q  [MROWS * DD];
__device__ __half g_k  [MROWS * DD];
__device__ __half g_v  [MROWS * DD];
__device__ __half g_ctx[MROWS * DD];
__device__ float  g_x1 [MROWS * DD];
__device__ __half g_ff [MROWS * DFFN];
// fp16, TRANSPOSED weights: wT[n][k] = (half)W[k][n]
__device__ __half g_wq [DD * DD];
__device__ __half g_wk [DD * DD];
__device__ __half g_wv [DD * DD];
__device__ __half g_wo [DD * DD];
__device__ __half g_w1 [DFFN * DD];
__device__ __half g_w2 [DD * DFFN];

// ---------------- weight half + transpose: out[n][k] = (half)in[k][n] ----------------
__global__ __launch_bounds__(256) void cvtT_kernel(const float* __restrict__ in,
                                                   __half* __restrict__ out,
                                                   int Kdim, int Ndim)
{
    __shared__ float sm[32][33];
    int n0 = blockIdx.x * 32;
    int k0 = blockIdx.y * 32;
    int tx = threadIdx.x, ty = threadIdx.y;
    #pragma unroll
    for (int i = 0; i < 4; i++) {
        int r = ty + i * 8;
        sm[r][tx] = in[(size_t)(k0 + r) * Ndim + n0 + tx];
    }
    __syncthreads();
    #pragma unroll
    for (int i = 0; i < 4; i++) {
        int r = ty + i * 8;
        out[(size_t)(n0 + r) * Kdim + k0 + tx] = __float2half_rn(sm[tx][r]);
    }
}

// ---------------- LayerNorm (fp32 in, fp16 out) ----------------
__global__ __launch_bounds__(256) void ln_kernel(const float* __restrict__ x,
                                                 const float* __restrict__ g,
                                                 const float* __restrict__ b,
                                                 __half* __restrict__ out)
{
    int row = blockIdx.x;
    int tid = threadIdx.x;
    const float4* xr = (const float4*)(x + (size_t)row * DD);
    float4 v = xr[tid];
    float s  = v.x + v.y + v.z + v.w;
    float ss = v.x*v.x + v.y*v.y + v.z*v.z + v.w*v.w;
    #pragma unroll
    for (int o = 16; o; o >>= 1) {
        s  += __shfl_xor_sync(0xffffffffu, s, o);
        ss += __shfl_xor_sync(0xffffffffu, ss, o);
    }
    __shared__ float sm1[8], sm2[8];
    int w = tid >> 5, l = tid & 31;
    if (l == 0) { sm1[w] = s; sm2[w] = ss; }
    __syncthreads();
    if (tid == 0) {
        float S = 0.f, SSu = 0.f;
        #pragma unroll
        for (int i = 0; i < 8; i++) { S += sm1[i]; SSu += sm2[i]; }
        float mu  = S  * (1.f / DD);
        float var = SSu * (1.f / DD) - mu * mu;
        sm1[0] = mu;
        sm2[0] = rsqrtf(var + 1e-5f);
    }
    __syncthreads();
    float mu  = sm1[0];
    float inv = sm2[0];
    float4 gg = ((const float4*)g)[tid];
    float4 bb = ((const float4*)b)[tid];
    __half2* orow = (__half2*)(out + (size_t)row * DD);
    orow[tid * 2 + 0] = __floats2half2_rn((v.x - mu) * inv * gg.x + bb.x,
                                          (v.y - mu) * inv * gg.y + bb.y);
    orow[tid * 2 + 1] = __floats2half2_rn((v.z - mu) * inv * gg.z + bb.z,
                                          (v.w - mu) * inv * gg.w + bb.w);
}

// ---------------- FP16 tensor-core GEMM (mma.sync.m16n8k16 + ldmatrix) ----------------
// 128x128 CTA tile, BK=64 halves, 4 warps each 64x64.
// A smem: [128 m][64 k] halves stride 72.  B smem: [128 n][64 k] stride 72.
// MODE 0: Chalf = A*B^T + bias
// MODE 1: Chalf = (half)gelu_tanh(A*B^T + bias)
// MODE 2: Cfloat = R + (A*B^T + bias) * scale

#define BKH 64               // K-tile in halves
#define TSTRIDE 72           // 64 + 8 pad halves (16B pad)
#define OP_STAGE (128 * TSTRIDE)              // halves per operand stage
#define SMEM_BYTES (4 * OP_STAGE * 2)         // 2 ops x 2 stages x 2B = 73728

__device__ __forceinline__ float gelu_tanh(float x) {
    float x3 = x * x * x;
    return 0.5f * x * (1.f + tanhf(0.7978845608028654f * (x + 0.044715f * x3)));
}

__device__ __forceinline__ void cp_async16h(__half* dst, const __half* src) {
    u32 d = (u32)__cvta_generic_to_shared(dst);
    asm volatile("cp.async.cg.shared.global [%0], [%1], 16;\n" :: "r"(d), "l"(src));
}
__device__ __forceinline__ void cp_commit() {
    asm volatile("cp.async.commit_group;\n");
}
__device__ __forceinline__ void cp_wait0() {
    asm volatile("cp.async.wait_group 0;\n" ::: "memory");
}
__device__ __forceinline__ void ldsm4(u32& r0, u32& r1, u32& r2, u32& r3, u32 addr) {
    asm volatile("ldmatrix.sync.aligned.m8n8.x4.shared.b16 {%0,%1,%2,%3}, [%4];"
                 : "=r"(r0), "=r"(r1), "=r"(r2), "=r"(r3) : "r"(addr));
}
__device__ __forceinline__ void mma_f16(float* acc,
                                        u32 a0, u32 a1, u32 a2, u32 a3,
                                        u32 b0, u32 b1)
{
    float d0 = acc[0], d1 = acc[1], d2 = acc[2], d3 = acc[3];
    asm volatile(
        "mma.sync.aligned.m16n8k16.row.col.f32.f16.f16.f32 "
        "{%0,%1,%2,%3}, {%4,%5,%6,%7}, {%8,%9}, {%0,%1,%2,%3};"
        : "+f"(d0), "+f"(d1), "+f"(d2), "+f"(d3)
        : "r"(a0), "r"(a1), "r"(a2), "r"(a3), "r"(b0), "r"(b1));
    acc[0] = d0; acc[1] = d1; acc[2] = d2; acc[3] = d3;
}

template<int MODE>
__global__ __launch_bounds__(128, 2)
void mma_gemm(const __half* __restrict__ A, const __half* __restrict__ Bt,
              const float* __restrict__ bias, const float* __restrict__ R,
              void* __restrict__ Cv, int M, int N, int K, float scale)
{
    extern __shared__ __half smem[];
    __half* AsBase = smem;                   // [2][128][TSTRIDE]
    __half* BsBase = smem + 2 * OP_STAGE;

    const int tid  = threadIdx.x;
    const int lane = tid & 31;
    const int warp = tid >> 5;
    const int wm   = (warp >> 1) * 64;
    const int wn   = (warp & 1) * 64;
    const int bm   = blockIdx.y * 128;
    const int bn   = blockIdx.x * 128;
    const int gid  = lane >> 2;
    const int tig  = lane & 3;

    // ldmatrix per-lane byte offsets within an operand stage (kk = 0):
    //   q = lane>>3 (tile index), ri = lane&7 (row in tile)
    // A tiles: (m0,k0)(m8,k0)(m0,k8)(m8,k8): row += (q&1)*8, k(half) = (q>>1)*8
    // B tiles: (n0,k0)(n0,k8)(n8,k0)(n8,k8): row += (q>>1)*8, k(half) = (q&1)*8
    const int q = lane >> 3, ri = lane & 7;
    const u32 aoff0 = (u32)(((wm + (q & 1) * 8 + ri) * TSTRIDE + (q >> 1) * 8) * 2);
    const u32 boff0 = (u32)(((wn + (q >> 1) * 8 + ri) * TSTRIDE + (q & 1) * 8) * 2);

    float acc[4][8][4];
    #pragma unroll
    for (int mi = 0; mi < 4; mi++)
        #pragma unroll
        for (int ni = 0; ni < 8; ni++)
            #pragma unroll
            for (int r = 0; r < 4; r++) acc[mi][ni][r] = 0.f;

    const int T = K / BKH;

    // stage loader: 128 rows x 4 chunks(16B=8 halves) per operand, 128 threads
    {
        const __half* Ag = A + (size_t)bm * K;
        const __half* Bg = Bt + (size_t)bn * K;
        #pragma unroll
        for (int i = 0; i < 8; i++) {
            int idx = tid + i * 128;
            int r = idx >> 3, c = (idx & 7) * 8;
            cp_async16h(AsBase + r * TSTRIDE + c, Ag + (size_t)r * K + c);
            cp_async16h(BsBase + r * TSTRIDE + c, Bg + (size_t)r * K + c);
        }
        cp_commit();
    }

    int cur = 0;
    for (int t = 0; t < T; t++) {
        cp_wait0();
        __syncthreads();

        if (t + 1 < T) {
            int k0 = (t + 1) * BKH;
            __half* as = AsBase + (cur ^ 1) * OP_STAGE;
            __half* bs = BsBase + (cur ^ 1) * OP_STAGE;
            const __half* Ag = A + (size_t)bm * K + k0;
            const __half* Bg = Bt + (size_t)bn * K + k0;
            #pragma unroll
            for (int i = 0; i < 8; i++) {
                int idx = tid + i * 128;
                int r = idx >> 3, c = (idx & 7) * 8;
                cp_async16h(as + r * TSTRIDE + c, Ag + (size_t)r * K + c);
                cp_async16h(bs + r * TSTRIDE + c, Bg + (size_t)r * K + c);
            }
            cp_commit();
        }

        const u32 asAddr = (u32)__cvta_generic_to_shared(AsBase + cur * OP_STAGE);
        const u32 bsAddr = (u32)__cvta_generic_to_shared(BsBase + cur * OP_STAGE);

        #pragma unroll
        for (int kk = 0; kk < BKH; kk += 16) {
            const u32 kb = (u32)(kk * 2);
            u32 afrag[4][4];
            #pragma unroll
            for (int mi = 0; mi < 4; mi++) {
                u32 r0, r1, r2, r3;
                ldsm4(r0, r1, r2, r3, asAddr + aoff0 + (u32)(mi * 16 * TSTRIDE * 2) + kb);
                afrag[mi][0] = r0; afrag[mi][1] = r1;
                afrag[mi][2] = r2; afrag[mi][3] = r3;
            }
            u32 bfrag[8][2];
            #pragma unroll
            for (int np = 0; np < 4; np++) {
                u32 r0, r1, r2, r3;
                ldsm4(r0, r1, r2, r3, bsAddr + boff0 + (u32)(np * 16 * TSTRIDE * 2) + kb);
                bfrag[np * 2 + 0][0] = r0; bfrag[np * 2 + 0][1] = r1;
                bfrag[np * 2 + 1][0] = r2; bfrag[np * 2 + 1][1] = r3;
            }
            #pragma unroll
            for (int mi = 0; mi < 4; mi++) {
                u32 a0 = afrag[mi][0], a1 = afrag[mi][1];
                u32 a2 = afrag[mi][2], a3 = afrag[mi][3];
                #pragma unroll
                for (int ni = 0; ni < 8; ni++) {
                    u32 b0 = bfrag[ni][0], b1 = bfrag[ni][1];
                    mma_f16(&acc[mi][ni][0], a0, a1, a2, a3, b0, b1);
                }
            }
        }
        __syncthreads();
        cur ^= 1;
    }

    // epilogue: frag (mi,ni): rows bm+wm+mi*16+gid+{0,8}, cols bn+wn+ni*8+tig*2+{0,1}
    const int rbase = bm + wm + gid;
    const int cbase = bn + wn + tig * 2;
    #pragma unroll
    for (int mi = 0; mi < 4; mi++) {
        #pragma unroll
        for (int half_ = 0; half_ < 2; half_++) {
            int r = rbase + mi * 16 + half_ * 8;
            #pragma unroll
            for (int ni = 0; ni < 8; ni++) {
                int c = cbase + ni * 8;
                float v0 = acc[mi][ni][half_ * 2 + 0] + bias[c];
                float v1 = acc[mi][ni][half_ * 2 + 1] + bias[c + 1];
                if (MODE == 0) {
                    __half2* C = (__half2*)((__half*)Cv + (size_t)r * N + c);
                    *C = __floats2half2_rn(v0, v1);
                } else if (MODE == 1) {
                    __half2* C = (__half2*)((__half*)Cv + (size_t)r * N + c);
                    *C = __floats2half2_rn(gelu_tanh(v0), gelu_tanh(v1));
                } else {
                    float* C = (float*)Cv + (size_t)r * N + c;
                    const float2 rr = *(const float2*)(R + (size_t)r * N + c);
                    float2 o2;
                    o2.x = rr.x + v0 * scale;
                    o2.y = rr.y + v1 * scale;
                    *(float2*)C = o2;
                }
            }
        }
    }
}

// ---------------- block-local causal attention (half in, half out, fp32 math) ----------------
__global__ __launch_bounds__(256)
void attn_kernel(const __half* __restrict__ q, const __half* __restrict__ k,
                 const __half* __restrict__ v, __half* __restrict__ ctx)
{
    __shared__ float qs[64][64];
    __shared__ float ks[64][64];
    __shared__ float vs[64][64];

    int tid = threadIdx.x;
    int rowbase = blockIdx.z * SS + blockIdx.x * 64;
    int colbase = blockIdx.y * 64;

    #pragma unroll
    for (int i = 0; i < 8; i++) {
        int idx = tid + i * 256;            // 0..2047 half2 units
        int r = idx >> 5, c2 = idx & 31;
        size_t off = (size_t)(rowbase + r) * DD + colbase + c2 * 2;
        float2 fq = __half22float2(*(const __half2*)(q + off));
        float2 fk = __half22float2(*(const __half2*)(k + off));
        float2 fv = __half22float2(*(const __half2*)(v + off));
        qs[r][c2*2] = fq.x; qs[r][c2*2+1] = fq.y;
        ks[r][c2*2] = fk.x; ks[r][c2*2+1] = fk.y;
        vs[r][c2*2] = fv.x; vs[r][c2*2+1] = fv.y;
    }
    __syncthreads();

    int qi = tid >> 2;
    int jg = (tid & 3) * 16;

    float sc[16];
    float m = -1e30f;
    #pragma unroll
    for (int jj = 0; jj < 16; jj++) {
        int j = jg + jj;
        float s = -1e30f;
        if (j <= qi) {
            s = 0.f;
            #pragma unroll
            for (int d = 0; d < 64; d++) s += qs[qi][d] * ks[j][d];
            s *= 0.125f;
            m = fmaxf(m, s);
        }
        sc[jj] = s;
    }
    m = fmaxf(m, __shfl_xor_sync(0xffffffffu, m, 1));
    m = fmaxf(m, __shfl_xor_sync(0xffffffffu, m, 2));

    float sum = 0.f;
    #pragma unroll
    for (int jj = 0; jj < 16; jj++) {
        float e = (jg + jj <= qi) ? expf(sc[jj] - m) : 0.f;
        sc[jj] = e;
        sum += e;
    }
    sum += __shfl_xor_sync(0xffffffffu, sum, 1);
    sum += __shfl_xor_sync(0xffffffffu, sum, 2);
    float inv = 1.f / sum;

    __syncthreads();
    #pragma unroll
    for (int jj = 0; jj < 16; jj++)
        ks[qi][jg + jj] = sc[jj] * inv;
    __syncthreads();

    float out[16];
    #pragma unroll
    for (int dd = 0; dd < 16; dd++) out[dd] = 0.f;
    for (int j = 0; j <= qi; j++) {
        float p = ks[qi][j];
        #pragma unroll
        for (int dd = 0; dd < 16; dd++)
            out[dd] += p * vs[j][jg + dd];
    }

    __half* dst = ctx + (size_t)(rowbase + qi) * DD + colbase + jg;
    #pragma unroll
    for (int dd = 0; dd < 16; dd += 2)
        *(__half2*)(dst + dd) = __floats2half2_rn(out[dd], out[dd+1]);
}

// ---------------- launch ----------------
extern "C" void kernel_launch(void* const* d_in, const int* in_sizes, int n_in,
                              void* d_out, int out_size)
{
    const float* x    = (const float*)d_in[0];
    const float* Wq   = (const float*)d_in[2];
    const float* bq   = (const float*)d_in[3];
    const float* Wk   = (const float*)d_in[4];
    const float* bk   = (const float*)d_in[5];
    const float* Wv   = (const float*)d_in[6];
    const float* bv   = (const float*)d_in[7];
    const float* Wo   = (const float*)d_in[8];
    const float* bo   = (const float*)d_in[9];
    const float* ln1g = (const float*)d_in[10];
    const float* ln1b = (const float*)d_in[11];
    const float* ln2g = (const float*)d_in[12];
    const float* ln2b = (const float*)d_in[13];
    const float* W1   = (const float*)d_in[14];
    const float* b1   = (const float*)d_in[15];
    const float* W2   = (const float*)d_in[16];
    const float* b2   = (const float*)d_in[17];
    float* out = (float*)d_out;

    __half *h, *q, *k, *v, *ctx, *ff;
    float *x1;
    __half *wq, *wk, *wv, *wo, *w1, *w2;
    cudaGetSymbolAddress((void**)&h,   g_h);
    cudaGetSymbolAddress((void**)&q,   g_q);
    cudaGetSymbolAddress((void**)&k,   g_k);
    cudaGetSymbolAddress((void**)&v,   g_v);
    cudaGetSymbolAddress((void**)&ctx, g_ctx);
    cudaGetSymbolAddress((void**)&x1,  g_x1);
    cudaGetSymbolAddress((void**)&ff,  g_ff);
    cudaGetSymbolAddress((void**)&wq,  g_wq);
    cudaGetSymbolAddress((void**)&wk,  g_wk);
    cudaGetSymbolAddress((void**)&wv,  g_wv);
    cudaGetSymbolAddress((void**)&wo,  g_wo);
    cudaGetSymbolAddress((void**)&w1,  g_w1);
    cudaGetSymbolAddress((void**)&w2,  g_w2);

    cudaFuncSetAttribute(mma_gemm<0>, cudaFuncAttributeMaxDynamicSharedMemorySize, SMEM_BYTES);
    cudaFuncSetAttribute(mma_gemm<1>, cudaFuncAttributeMaxDynamicSharedMemorySize, SMEM_BYTES);
    cudaFuncSetAttribute(mma_gemm<2>, cudaFuncAttributeMaxDynamicSharedMemorySize, SMEM_BYTES);

    // 0. half + transpose weights
    dim3 tb(32, 8);
    cvtT_kernel<<<dim3(DD / 32,   DD / 32),   tb>>>(Wq, wq, DD, DD);
    cvtT_kernel<<<dim3(DD / 32,   DD / 32),   tb>>>(Wk, wk, DD, DD);
    cvtT_kernel<<<dim3(DD / 32,   DD / 32),   tb>>>(Wv, wv, DD, DD);
    cvtT_kernel<<<dim3(DD / 32,   DD / 32),   tb>>>(Wo, wo, DD, DD);
    cvtT_kernel<<<dim3(DFFN / 32, DD / 32),   tb>>>(W1, w1, DD, DFFN);
    cvtT_kernel<<<dim3(DD / 32,   DFFN / 32), tb>>>(W2, w2, DFFN, DD);

    // 1. LN1 -> h (half)
    ln_kernel<<<MROWS, 256>>>(x, ln1g, ln1b, h);

    // 2. QKV projections (half out)
    dim3 gD(DD / 128, MROWS / 128);     // (8, 32)
    mma_gemm<0><<<gD, 128, SMEM_BYTES>>>(h, wq, bq, nullptr, q, MROWS, DD, DD, 0.f);
    mma_gemm<0><<<gD, 128, SMEM_BYTES>>>(h, wk, bk, nullptr, k, MROWS, DD, DD, 0.f);
    mma_gemm<0><<<gD, 128, SMEM_BYTES>>>(h, wv, bv, nullptr, v, MROWS, DD, DD, 0.f);

    // 3. attention -> ctx (half)
    dim3 gA(SS / 64, HH, BB);
    attn_kernel<<<gA, 256>>>(q, k, v, ctx);

    // 4. x1 = x + (ctx @ Wo + bo) * res_scale   (fp32 out)
    mma_gemm<2><<<gD, 128, SMEM_BYTES>>>(ctx, wo, bo, x, x1, MROWS, DD, DD, RES_SCALE);

    // 5. LN2 -> h (half)
    ln_kernel<<<MROWS, 256>>>(x1, ln2g, ln2b, h);

    // 6. ff = (half)gelu(h @ W1 + b1)
    dim3 gF1(DFFN / 128, MROWS / 128);  // (32, 32)
    mma_gemm<1><<<gF1, 128, SMEM_BYTES>>>(h, w1, b1, nullptr, ff, MROWS, DFFN, DD, 0.f);

    // 7. out = x1 + (ff @ W2 + b2) * res_scale   (fp32 out)
    mma_gemm<2><<<gD, 128, SMEM_BYTES>>>(ff, w2, b2, x1, out, MROWS, DD, DFFN, RES_SCALE);
}

// round 9
// speedup vs baseline: 4.6320x; 1.0253x over previous
#include <cuda_runtime.h>
#include <cuda_fp16.h>
#include <math.h>

typedef unsigned int u32;

// Problem constants
#define BB 2
#define SS 2048
#define DD 1024
#define HH 16
#define DFFN 4096
#define MROWS (BB*SS)          // 4096
#define NQKV 3072
#define RES_SCALE 0.70710678118654752440f

// ---------------- device scratch ----------------
__device__ __half g_h   [MROWS * DD];
__device__ __half g_qkv [MROWS * NQKV];
__device__ __half g_ctx [MROWS * DD];
__device__ float  g_x1  [MROWS * DD];
__device__ __half g_ff  [MROWS * DFFN];
// fp16, TRANSPOSED weights
__device__ __half g_wqkv[NQKV * DD];     // rows: 0..1023 Wq^T, 1024.. Wk^T, 2048.. Wv^T
__device__ __half g_wo  [DD * DD];
__device__ __half g_w1  [DFFN * DD];
__device__ __half g_w2  [DD * DFFN];
__device__ float  g_bqkv[NQKV];

// ---------------- fused weight convert: all matrices + bias concat, ONE launch ----------
// block-tile ids: [0,1024) Wq | [1024,2048) Wk | [2048,3072) Wv | [3072,4096) Wo
//                 [4096,8192) W1 | [8192,12288) W2 | 12288 bias concat
__global__ __launch_bounds__(256) void cvt_all_kernel(
    const float* __restrict__ Wq, const float* __restrict__ Wk,
    const float* __restrict__ Wv, const float* __restrict__ Wo,
    const float* __restrict__ W1, const float* __restrict__ W2,
    const float* __restrict__ bq, const float* __restrict__ bk,
    const float* __restrict__ bv)
{
    int bid = blockIdx.x;
    int tx = threadIdx.x, ty = threadIdx.y;

    if (bid == 12288) {
        int t = ty * 32 + tx;
        #pragma unroll
        for (int i = 0; i < 4; i++) {
            int j = t + i * 256;
            g_bqkv[j]            = bq[j];
            g_bqkv[DD + j]       = bk[j];
            g_bqkv[2 * DD + j]   = bv[j];
        }
        return;
    }

    const float* in;
    __half* out;
    int Kdim, Ndim, n0, k0, rowOff;
    if (bid < 4096) {
        int m = bid >> 10;            // 0..3 : Wq,Wk,Wv,Wo
        int lb = bid & 1023;
        Kdim = DD; Ndim = DD;
        n0 = (lb & 31) * 32; k0 = (lb >> 5) * 32;
        if (m == 0)      { in = Wq; out = g_wqkv; rowOff = 0; }
        else if (m == 1) { in = Wk; out = g_wqkv; rowOff = DD; }
        else if (m == 2) { in = Wv; out = g_wqkv; rowOff = 2 * DD; }
        else             { in = Wo; out = g_wo;   rowOff = 0; }
    } else if (bid < 8192) {
        int lb = bid - 4096;          // W1: [1024][4096] -> [4096][1024]
        Kdim = DD; Ndim = DFFN;
        n0 = (lb & 127) * 32; k0 = (lb >> 7) * 32;
        in = W1; out = g_w1; rowOff = 0;
    } else {
        int lb = bid - 8192;          // W2: [4096][1024] -> [1024][4096]
        Kdim = DFFN; Ndim = DD;
        n0 = (lb & 31) * 32; k0 = (lb >> 5) * 32;
        in = W2; out = g_w2; rowOff = 0;
    }

    __shared__ float sm[32][33];
    #pragma unroll
    for (int i = 0; i < 4; i++) {
        int r = ty + i * 8;
        sm[r][tx] = in[(size_t)(k0 + r) * Ndim + n0 + tx];
    }
    __syncthreads();
    #pragma unroll
    for (int i = 0; i < 4; i++) {
        int r = ty + i * 8;
        out[(size_t)(rowOff + n0 + r) * Kdim + k0 + tx] = __float2half_rn(sm[tx][r]);
    }
}

// ---------------- LayerNorm (fp32 in, fp16 out) ----------------
__global__ __launch_bounds__(256) void ln_kernel(const float* __restrict__ x,
                                                 const float* __restrict__ g,
                                                 const float* __restrict__ b,
                                                 __half* __restrict__ out)
{
    int row = blockIdx.x;
    int tid = threadIdx.x;
    const float4* xr = (const float4*)(x + (size_t)row * DD);
    float4 v = xr[tid];
    float s  = v.x + v.y + v.z + v.w;
    float ss = v.x*v.x + v.y*v.y + v.z*v.z + v.w*v.w;
    #pragma unroll
    for (int o = 16; o; o >>= 1) {
        s  += __shfl_xor_sync(0xffffffffu, s, o);
        ss += __shfl_xor_sync(0xffffffffu, ss, o);
    }
    __shared__ float sm1[8], sm2[8];
    int w = tid >> 5, l = tid & 31;
    if (l == 0) { sm1[w] = s; sm2[w] = ss; }
    __syncthreads();
    if (tid == 0) {
        float S = 0.f, SSu = 0.f;
        #pragma unroll
        for (int i = 0; i < 8; i++) { S += sm1[i]; SSu += sm2[i]; }
        float mu  = S  * (1.f / DD);
        float var = SSu * (1.f / DD) - mu * mu;
        sm1[0] = mu;
        sm2[0] = rsqrtf(var + 1e-5f);
    }
    __syncthreads();
    float mu  = sm1[0];
    float inv = sm2[0];
    float4 gg = ((const float4*)g)[tid];
    float4 bb = ((const float4*)b)[tid];
    __half2* orow = (__half2*)(out + (size_t)row * DD);
    orow[tid * 2 + 0] = __floats2half2_rn((v.x - mu) * inv * gg.x + bb.x,
                                          (v.y - mu) * inv * gg.y + bb.y);
    orow[tid * 2 + 1] = __floats2half2_rn((v.z - mu) * inv * gg.z + bb.z,
                                          (v.w - mu) * inv * gg.w + bb.w);
}

// ---------------- FP16 tensor-core GEMM (mma.sync.m16n8k16 + ldmatrix) ----------------
#define BKH 64
#define TSTRIDE 72
#define OP_STAGE (128 * TSTRIDE)
#define SMEM_BYTES (4 * OP_STAGE * 2)

__device__ __forceinline__ float gelu_tanh(float x) {
    float x3 = x * x * x;
    return 0.5f * x * (1.f + tanhf(0.7978845608028654f * (x + 0.044715f * x3)));
}
__device__ __forceinline__ void cp_async16h(__half* dst, const __half* src) {
    u32 d = (u32)__cvta_generic_to_shared(dst);
    asm volatile("cp.async.cg.shared.global [%0], [%1], 16;\n" :: "r"(d), "l"(src));
}
__device__ __forceinline__ void cp_commit() {
    asm volatile("cp.async.commit_group;\n");
}
__device__ __forceinline__ void cp_wait0() {
    asm volatile("cp.async.wait_group 0;\n" ::: "memory");
}
__device__ __forceinline__ void ldsm4(u32& r0, u32& r1, u32& r2, u32& r3, u32 addr) {
    asm volatile("ldmatrix.sync.aligned.m8n8.x4.shared.b16 {%0,%1,%2,%3}, [%4];"
                 : "=r"(r0), "=r"(r1), "=r"(r2), "=r"(r3) : "r"(addr));
}
__device__ __forceinline__ void mma_f16(float* acc,
                                        u32 a0, u32 a1, u32 a2, u32 a3,
                                        u32 b0, u32 b1)
{
    float d0 = acc[0], d1 = acc[1], d2 = acc[2], d3 = acc[3];
    asm volatile(
        "mma.sync.aligned.m16n8k16.row.col.f32.f16.f16.f32 "
        "{%0,%1,%2,%3}, {%4,%5,%6,%7}, {%8,%9}, {%0,%1,%2,%3};"
        : "+f"(d0), "+f"(d1), "+f"(d2), "+f"(d3)
        : "r"(a0), "r"(a1), "r"(a2), "r"(a3), "r"(b0), "r"(b1));
    acc[0] = d0; acc[1] = d1; acc[2] = d2; acc[3] = d3;
}

template<int MODE>
__global__ __launch_bounds__(128, 2)
void mma_gemm(const __half* __restrict__ A, const __half* __restrict__ Bt,
              const float* __restrict__ bias, const float* __restrict__ R,
              void* __restrict__ Cv, int M, int N, int K, float scale)
{
    extern __shared__ __half smem[];
    __half* AsBase = smem;
    __half* BsBase = smem + 2 * OP_STAGE;

    const int tid  = threadIdx.x;
    const int lane = tid & 31;
    const int warp = tid >> 5;
    const int wm   = (warp >> 1) * 64;
    const int wn   = (warp & 1) * 64;
    const int bm   = blockIdx.y * 128;
    const int bn   = blockIdx.x * 128;
    const int gid  = lane >> 2;
    const int tig  = lane & 3;

    const int q = lane >> 3, ri = lane & 7;
    const u32 aoff0 = (u32)(((wm + (q & 1) * 8 + ri) * TSTRIDE + (q >> 1) * 8) * 2);
    const u32 boff0 = (u32)(((wn + (q >> 1) * 8 + ri) * TSTRIDE + (q & 1) * 8) * 2);

    float acc[4][8][4];
    #pragma unroll
    for (int mi = 0; mi < 4; mi++)
        #pragma unroll
        for (int ni = 0; ni < 8; ni++)
            #pragma unroll
            for (int r = 0; r < 4; r++) acc[mi][ni][r] = 0.f;

    const int T = K / BKH;

    {
        const __half* Ag = A + (size_t)bm * K;
        const __half* Bg = Bt + (size_t)bn * K;
        #pragma unroll
        for (int i = 0; i < 8; i++) {
            int idx = tid + i * 128;
            int r = idx >> 3, c = (idx & 7) * 8;
            cp_async16h(AsBase + r * TSTRIDE + c, Ag + (size_t)r * K + c);
            cp_async16h(BsBase + r * TSTRIDE + c, Bg + (size_t)r * K + c);
        }
        cp_commit();
    }

    int cur = 0;
    for (int t = 0; t < T; t++) {
        cp_wait0();
        __syncthreads();

        if (t + 1 < T) {
            int k0 = (t + 1) * BKH;
            __half* as = AsBase + (cur ^ 1) * OP_STAGE;
            __half* bs = BsBase + (cur ^ 1) * OP_STAGE;
            const __half* Ag = A + (size_t)bm * K + k0;
            const __half* Bg = Bt + (size_t)bn * K + k0;
            #pragma unroll
            for (int i = 0; i < 8; i++) {
                int idx = tid + i * 128;
                int r = idx >> 3, c = (idx & 7) * 8;
                cp_async16h(as + r * TSTRIDE + c, Ag + (size_t)r * K + c);
                cp_async16h(bs + r * TSTRIDE + c, Bg + (size_t)r * K + c);
            }
            cp_commit();
        }

        const u32 asAddr = (u32)__cvta_generic_to_shared(AsBase + cur * OP_STAGE);
        const u32 bsAddr = (u32)__cvta_generic_to_shared(BsBase + cur * OP_STAGE);

        #pragma unroll
        for (int kk = 0; kk < BKH; kk += 16) {
            const u32 kb = (u32)(kk * 2);
            u32 afrag[4][4];
            #pragma unroll
            for (int mi = 0; mi < 4; mi++) {
                u32 r0, r1, r2, r3;
                ldsm4(r0, r1, r2, r3, asAddr + aoff0 + (u32)(mi * 16 * TSTRIDE * 2) + kb);
                afrag[mi][0] = r0; afrag[mi][1] = r1;
                afrag[mi][2] = r2; afrag[mi][3] = r3;
            }
            u32 bfrag[8][2];
            #pragma unroll
            for (int np = 0; np < 4; np++) {
                u32 r0, r1, r2, r3;
                ldsm4(r0, r1, r2, r3, bsAddr + boff0 + (u32)(np * 16 * TSTRIDE * 2) + kb);
                bfrag[np * 2 + 0][0] = r0; bfrag[np * 2 + 0][1] = r1;
                bfrag[np * 2 + 1][0] = r2; bfrag[np * 2 + 1][1] = r3;
            }
            #pragma unroll
            for (int mi = 0; mi < 4; mi++) {
                u32 a0 = afrag[mi][0], a1 = afrag[mi][1];
                u32 a2 = afrag[mi][2], a3 = afrag[mi][3];
                #pragma unroll
                for (int ni = 0; ni < 8; ni++) {
                    u32 b0 = bfrag[ni][0], b1 = bfrag[ni][1];
                    mma_f16(&acc[mi][ni][0], a0, a1, a2, a3, b0, b1);
                }
            }
        }
        __syncthreads();
        cur ^= 1;
    }

    const int rbase = bm + wm + gid;
    const int cbase = bn + wn + tig * 2;
    #pragma unroll
    for (int mi = 0; mi < 4; mi++) {
        #pragma unroll
        for (int half_ = 0; half_ < 2; half_++) {
            int r = rbase + mi * 16 + half_ * 8;
            #pragma unroll
            for (int ni = 0; ni < 8; ni++) {
                int c = cbase + ni * 8;
                float v0 = acc[mi][ni][half_ * 2 + 0] + bias[c];
                float v1 = acc[mi][ni][half_ * 2 + 1] + bias[c + 1];
                if (MODE == 0) {
                    __half2* C = (__half2*)((__half*)Cv + (size_t)r * N + c);
                    *C = __floats2half2_rn(v0, v1);
                } else if (MODE == 1) {
                    __half2* C = (__half2*)((__half*)Cv + (size_t)r * N + c);
                    *C = __floats2half2_rn(gelu_tanh(v0), gelu_tanh(v1));
                } else {
                    float* C = (float*)Cv + (size_t)r * N + c;
                    const float2 rr = *(const float2*)(R + (size_t)r * N + c);
                    float2 o2;
                    o2.x = rr.x + v0 * scale;
                    o2.y = rr.y + v1 * scale;
                    *(float2*)C = o2;
                }
            }
        }
    }
}

// ---------------- block-local causal attention (packed qkv in, half ctx out) -----------
__global__ __launch_bounds__(256)
void attn_kernel(const __half* __restrict__ qkv, __half* __restrict__ ctx)
{
    __shared__ float qs[64][64];
    __shared__ float ks[64][64];
    __shared__ float vs[64][64];

    int tid = threadIdx.x;
    int rowbase = blockIdx.z * SS + blockIdx.x * 64;
    int colbase = blockIdx.y * 64;      // head offset within 1024

    #pragma unroll
    for (int i = 0; i < 8; i++) {
        int idx = tid + i * 256;        // 0..2047 half2 units
        int r = idx >> 5, c2 = idx & 31;
        size_t base = (size_t)(rowbase + r) * NQKV + colbase + c2 * 2;
        float2 fq = __half22float2(*(const __half2*)(qkv + base));
        float2 fk = __half22float2(*(const __half2*)(qkv + base + DD));
        float2 fv = __half22float2(*(const __half2*)(qkv + base + 2 * DD));
        qs[r][c2*2] = fq.x; qs[r][c2*2+1] = fq.y;
        ks[r][c2*2] = fk.x; ks[r][c2*2+1] = fk.y;
        vs[r][c2*2] = fv.x; vs[r][c2*2+1] = fv.y;
    }
    __syncthreads();

    int qi = tid >> 2;
    int jg = (tid & 3) * 16;

    float sc[16];
    float m = -1e30f;
    #pragma unroll
    for (int jj = 0; jj < 16; jj++) {
        int j = jg + jj;
        float s = -1e30f;
        if (j <= qi) {
            s = 0.f;
            #pragma unroll
            for (int d = 0; d < 64; d++) s += qs[qi][d] * ks[j][d];
            s *= 0.125f;
            m = fmaxf(m, s);
        }
        sc[jj] = s;
    }
    m = fmaxf(m, __shfl_xor_sync(0xffffffffu, m, 1));
    m = fmaxf(m, __shfl_xor_sync(0xffffffffu, m, 2));

    float sum = 0.f;
    #pragma unroll
    for (int jj = 0; jj < 16; jj++) {
        float e = (jg + jj <= qi) ? expf(sc[jj] - m) : 0.f;
        sc[jj] = e;
        sum += e;
    }
    sum += __shfl_xor_sync(0xffffffffu, sum, 1);
    sum += __shfl_xor_sync(0xffffffffu, sum, 2);
    float inv = 1.f / sum;

    __syncthreads();
    #pragma unroll
    for (int jj = 0; jj < 16; jj++)
        ks[qi][jg + jj] = sc[jj] * inv;
    __syncthreads();

    float out[16];
    #pragma unroll
    for (int dd = 0; dd < 16; dd++) out[dd] = 0.f;
    for (int j = 0; j <= qi; j++) {
        float p = ks[qi][j];
        #pragma unroll
        for (int dd = 0; dd < 16; dd++)
            out[dd] += p * vs[j][jg + dd];
    }

    __half* dst = ctx + (size_t)(rowbase + qi) * DD + colbase + jg;
    #pragma unroll
    for (int dd = 0; dd < 16; dd += 2)
        *(__half2*)(dst + dd) = __floats2half2_rn(out[dd], out[dd+1]);
}

// ---------------- launch ----------------
extern "C" void kernel_launch(void* const* d_in, const int* in_sizes, int n_in,
                              void* d_out, int out_size)
{
    const float* x    = (const float*)d_in[0];
    const float* Wq   = (const float*)d_in[2];
    const float* bq   = (const float*)d_in[3];
    const float* Wk   = (const float*)d_in[4];
    const float* bk   = (const float*)d_in[5];
    const float* Wv   = (const float*)d_in[6];
    const float* bv   = (const float*)d_in[7];
    const float* Wo   = (const float*)d_in[8];
    const float* bo   = (const float*)d_in[9];
    const float* ln1g = (const float*)d_in[10];
    const float* ln1b = (const float*)d_in[11];
    const float* ln2g = (const float*)d_in[12];
    const float* ln2b = (const float*)d_in[13];
    const float* W1   = (const float*)d_in[14];
    const float* b1   = (const float*)d_in[15];
    const float* W2   = (const float*)d_in[16];
    const float* b2   = (const float*)d_in[17];
    float* out = (float*)d_out;

    __half *h, *qkv, *ctx, *ff;
    float *x1, *bqkv;
    __half *wqkv, *wo, *w1, *w2;
    cudaGetSymbolAddress((void**)&h,    g_h);
    cudaGetSymbolAddress((void**)&qkv,  g_qkv);
    cudaGetSymbolAddress((void**)&ctx,  g_ctx);
    cudaGetSymbolAddress((void**)&x1,   g_x1);
    cudaGetSymbolAddress((void**)&ff,   g_ff);
    cudaGetSymbolAddress((void**)&wqkv, g_wqkv);
    cudaGetSymbolAddress((void**)&wo,   g_wo);
    cudaGetSymbolAddress((void**)&w1,   g_w1);
    cudaGetSymbolAddress((void**)&w2,   g_w2);
    cudaGetSymbolAddress((void**)&bqkv, g_bqkv);

    cudaFuncSetAttribute(mma_gemm<0>, cudaFuncAttributeMaxDynamicSharedMemorySize, SMEM_BYTES);
    cudaFuncSetAttribute(mma_gemm<1>, cudaFuncAttributeMaxDynamicSharedMemorySize, SMEM_BYTES);
    cudaFuncSetAttribute(mma_gemm<2>, cudaFuncAttributeMaxDynamicSharedMemorySize, SMEM_BYTES);

    // 0. ONE fused convert launch (weights transposed to fp16, bias concat)
    cvt_all_kernel<<<12289, dim3(32, 8)>>>(Wq, Wk, Wv, Wo, W1, W2, bq, bk, bv);

    // 1. LN1 -> h (half)
    ln_kernel<<<MROWS, 256>>>(x, ln1g, ln1b, h);

    // 2. Fused QKV projection: [4096][3072]
    dim3 gQKV(NQKV / 128, MROWS / 128);   // (24, 32)
    mma_gemm<0><<<gQKV, 128, SMEM_BYTES>>>(h, wqkv, bqkv, nullptr, qkv, MROWS, NQKV, DD, 0.f);

    // 3. attention -> ctx (half)
    dim3 gA(SS / 64, HH, BB);
    attn_kernel<<<gA, 256>>>(qkv, ctx);

    // 4. x1 = x + (ctx @ Wo + bo) * res_scale   (fp32 out)
    dim3 gD(DD / 128, MROWS / 128);       // (8, 32)
    mma_gemm<2><<<gD, 128, SMEM_BYTES>>>(ctx, wo, bo, x, x1, MROWS, DD, DD, RES_SCALE);

    // 5. LN2 -> h (half)
    ln_kernel<<<MROWS, 256>>>(x1, ln2g, ln2b, h);

    // 6. ff = (half)gelu(h @ W1 + b1)
    dim3 gF1(DFFN / 128, MROWS / 128);    // (32, 32)
    mma_gemm<1><<<gF1, 128, SMEM_BYTES>>>(h, w1, b1, nullptr, ff, MROWS, DFFN, DD, 0.f);

    // 7. out = x1 + (ff @ W2 + b2) * res_scale   (fp32 out)
    mma_gemm<2><<<gD, 128, SMEM_BYTES>>>(ff, w2, b2, x1, out, MROWS, DD, DFFN, RES_SCALE);
}

// round 10
// speedup vs baseline: 6.1673x; 1.3315x over previous
#include <cuda_runtime.h>
#include <cuda_fp16.h>
#include <math.h>

typedef unsigned int u32;

// Problem constants
#define BB 2
#define SS 2048
#define DD 1024
#define HH 16
#define DFFN 4096
#define MROWS (BB*SS)          // 4096
#define NQKV 3072
#define RES_SCALE 0.70710678118654752440f

// ---------------- device scratch ----------------
__device__ __half g_h   [MROWS * DD];
__device__ __half g_qkv [MROWS * NQKV];
__device__ __half g_ctx [MROWS * DD];
__device__ float  g_x1  [MROWS * DD];
__device__ __half g_ff  [MROWS * DFFN];
__device__ __half g_wqkv[NQKV * DD];
__device__ __half g_wo  [DD * DD];
__device__ __half g_w1  [DFFN * DD];
__device__ __half g_w2  [DD * DFFN];
__device__ float  g_bqkv[NQKV];

// ---------------- fused weight convert (one launch) ----------------
__global__ __launch_bounds__(256) void cvt_all_kernel(
    const float* __restrict__ Wq, const float* __restrict__ Wk,
    const float* __restrict__ Wv, const float* __restrict__ Wo,
    const float* __restrict__ W1, const float* __restrict__ W2,
    const float* __restrict__ bq, const float* __restrict__ bk,
    const float* __restrict__ bv)
{
    int bid = blockIdx.x;
    int tx = threadIdx.x, ty = threadIdx.y;

    if (bid == 12288) {
        int t = ty * 32 + tx;
        #pragma unroll
        for (int i = 0; i < 4; i++) {
            int j = t + i * 256;
            g_bqkv[j]          = bq[j];
            g_bqkv[DD + j]     = bk[j];
            g_bqkv[2 * DD + j] = bv[j];
        }
        return;
    }

    const float* in;
    __half* out;
    int Kdim, Ndim, n0, k0, rowOff;
    if (bid < 4096) {
        int m = bid >> 10;
        int lb = bid & 1023;
        Kdim = DD; Ndim = DD;
        n0 = (lb & 31) * 32; k0 = (lb >> 5) * 32;
        if (m == 0)      { in = Wq; out = g_wqkv; rowOff = 0; }
        else if (m == 1) { in = Wk; out = g_wqkv; rowOff = DD; }
        else if (m == 2) { in = Wv; out = g_wqkv; rowOff = 2 * DD; }
        else             { in = Wo; out = g_wo;   rowOff = 0; }
    } else if (bid < 8192) {
        int lb = bid - 4096;
        Kdim = DD; Ndim = DFFN;
        n0 = (lb & 127) * 32; k0 = (lb >> 7) * 32;
        in = W1; out = g_w1; rowOff = 0;
    } else {
        int lb = bid - 8192;
        Kdim = DFFN; Ndim = DD;
        n0 = (lb & 31) * 32; k0 = (lb >> 5) * 32;
        in = W2; out = g_w2; rowOff = 0;
    }

    __shared__ float sm[32][33];
    #pragma unroll
    for (int i = 0; i < 4; i++) {
        int r = ty + i * 8;
        sm[r][tx] = in[(size_t)(k0 + r) * Ndim + n0 + tx];
    }
    __syncthreads();
    #pragma unroll
    for (int i = 0; i < 4; i++) {
        int r = ty + i * 8;
        out[(size_t)(rowOff + n0 + r) * Kdim + k0 + tx] = __float2half_rn(sm[tx][r]);
    }
}

// ---------------- LayerNorm (fp32 in, fp16 out) ----------------
__global__ __launch_bounds__(256) void ln_kernel(const float* __restrict__ x,
                                                 const float* __restrict__ g,
                                                 const float* __restrict__ b,
                                                 __half* __restrict__ out)
{
    int row = blockIdx.x;
    int tid = threadIdx.x;
    const float4* xr = (const float4*)(x + (size_t)row * DD);
    float4 v = xr[tid];
    float s  = v.x + v.y + v.z + v.w;
    float ss = v.x*v.x + v.y*v.y + v.z*v.z + v.w*v.w;
    #pragma unroll
    for (int o = 16; o; o >>= 1) {
        s  += __shfl_xor_sync(0xffffffffu, s, o);
        ss += __shfl_xor_sync(0xffffffffu, ss, o);
    }
    __shared__ float sm1[8], sm2[8];
    int w = tid >> 5, l = tid & 31;
    if (l == 0) { sm1[w] = s; sm2[w] = ss; }
    __syncthreads();
    if (tid == 0) {
        float S = 0.f, SSu = 0.f;
        #pragma unroll
        for (int i = 0; i < 8; i++) { S += sm1[i]; SSu += sm2[i]; }
        float mu  = S  * (1.f / DD);
        float var = SSu * (1.f / DD) - mu * mu;
        sm1[0] = mu;
        sm2[0] = rsqrtf(var + 1e-5f);
    }
    __syncthreads();
    float mu  = sm1[0];
    float inv = sm2[0];
    float4 gg = ((const float4*)g)[tid];
    float4 bb = ((const float4*)b)[tid];
    __half2* orow = (__half2*)(out + (size_t)row * DD);
    orow[tid * 2 + 0] = __floats2half2_rn((v.x - mu) * inv * gg.x + bb.x,
                                          (v.y - mu) * inv * gg.y + bb.y);
    orow[tid * 2 + 1] = __floats2half2_rn((v.z - mu) * inv * gg.z + bb.z,
                                          (v.w - mu) * inv * gg.w + bb.w);
}

// ---------------- FP16 tensor-core GEMM (unchanged core) ----------------
#define BKH 64
#define TSTRIDE 72
#define OP_STAGE (128 * TSTRIDE)
#define SMEM_BYTES (4 * OP_STAGE * 2)

__device__ __forceinline__ float gelu_tanh(float x) {
    float x3 = x * x * x;
    return 0.5f * x * (1.f + tanhf(0.7978845608028654f * (x + 0.044715f * x3)));
}
__device__ __forceinline__ void cp_async16h(__half* dst, const __half* src) {
    u32 d = (u32)__cvta_generic_to_shared(dst);
    asm volatile("cp.async.cg.shared.global [%0], [%1], 16;\n" :: "r"(d), "l"(src));
}
__device__ __forceinline__ void cp_commit() {
    asm volatile("cp.async.commit_group;\n");
}
__device__ __forceinline__ void cp_wait0() {
    asm volatile("cp.async.wait_group 0;\n" ::: "memory");
}
__device__ __forceinline__ void ldsm4(u32& r0, u32& r1, u32& r2, u32& r3, u32 addr) {
    asm volatile("ldmatrix.sync.aligned.m8n8.x4.shared.b16 {%0,%1,%2,%3}, [%4];"
                 : "=r"(r0), "=r"(r1), "=r"(r2), "=r"(r3) : "r"(addr));
}
__device__ __forceinline__ void mma_f16(float* acc,
                                        u32 a0, u32 a1, u32 a2, u32 a3,
                                        u32 b0, u32 b1)
{
    float d0 = acc[0], d1 = acc[1], d2 = acc[2], d3 = acc[3];
    asm volatile(
        "mma.sync.aligned.m16n8k16.row.col.f32.f16.f16.f32 "
        "{%0,%1,%2,%3}, {%4,%5,%6,%7}, {%8,%9}, {%0,%1,%2,%3};"
        : "+f"(d0), "+f"(d1), "+f"(d2), "+f"(d3)
        : "r"(a0), "r"(a1), "r"(a2), "r"(a3), "r"(b0), "r"(b1));
    acc[0] = d0; acc[1] = d1; acc[2] = d2; acc[3] = d3;
}

template<int MODE>
__global__ __launch_bounds__(128, 2)
void mma_gemm(const __half* __restrict__ A, const __half* __restrict__ Bt,
              const float* __restrict__ bias, const float* __restrict__ R,
              void* __restrict__ Cv, int M, int N, int K, float scale)
{
    extern __shared__ __half smem[];
    __half* AsBase = smem;
    __half* BsBase = smem + 2 * OP_STAGE;

    const int tid  = threadIdx.x;
    const int lane = tid & 31;
    const int warp = tid >> 5;
    const int wm   = (warp >> 1) * 64;
    const int wn   = (warp & 1) * 64;
    const int bm   = blockIdx.y * 128;
    const int bn   = blockIdx.x * 128;
    const int gid  = lane >> 2;
    const int tig  = lane & 3;

    const int q = lane >> 3, ri = lane & 7;
    const u32 aoff0 = (u32)(((wm + (q & 1) * 8 + ri) * TSTRIDE + (q >> 1) * 8) * 2);
    const u32 boff0 = (u32)(((wn + (q >> 1) * 8 + ri) * TSTRIDE + (q & 1) * 8) * 2);

    float acc[4][8][4];
    #pragma unroll
    for (int mi = 0; mi < 4; mi++)
        #pragma unroll
        for (int ni = 0; ni < 8; ni++)
            #pragma unroll
            for (int r = 0; r < 4; r++) acc[mi][ni][r] = 0.f;

    const int T = K / BKH;

    {
        const __half* Ag = A + (size_t)bm * K;
        const __half* Bg = Bt + (size_t)bn * K;
        #pragma unroll
        for (int i = 0; i < 8; i++) {
            int idx = tid + i * 128;
            int r = idx >> 3, c = (idx & 7) * 8;
            cp_async16h(AsBase + r * TSTRIDE + c, Ag + (size_t)r * K + c);
            cp_async16h(BsBase + r * TSTRIDE + c, Bg + (size_t)r * K + c);
        }
        cp_commit();
    }

    int cur = 0;
    for (int t = 0; t < T; t++) {
        cp_wait0();
        __syncthreads();

        if (t + 1 < T) {
            int k0 = (t + 1) * BKH;
            __half* as = AsBase + (cur ^ 1) * OP_STAGE;
            __half* bs = BsBase + (cur ^ 1) * OP_STAGE;
            const __half* Ag = A + (size_t)bm * K + k0;
            const __half* Bg = Bt + (size_t)bn * K + k0;
            #pragma unroll
            for (int i = 0; i < 8; i++) {
                int idx = tid + i * 128;
                int r = idx >> 3, c = (idx & 7) * 8;
                cp_async16h(as + r * TSTRIDE + c, Ag + (size_t)r * K + c);
                cp_async16h(bs + r * TSTRIDE + c, Bg + (size_t)r * K + c);
            }
            cp_commit();
        }

        const u32 asAddr = (u32)__cvta_generic_to_shared(AsBase + cur * OP_STAGE);
        const u32 bsAddr = (u32)__cvta_generic_to_shared(BsBase + cur * OP_STAGE);

        #pragma unroll
        for (int kk = 0; kk < BKH; kk += 16) {
            const u32 kb = (u32)(kk * 2);
            u32 afrag[4][4];
            #pragma unroll
            for (int mi = 0; mi < 4; mi++) {
                u32 r0, r1, r2, r3;
                ldsm4(r0, r1, r2, r3, asAddr + aoff0 + (u32)(mi * 16 * TSTRIDE * 2) + kb);
                afrag[mi][0] = r0; afrag[mi][1] = r1;
                afrag[mi][2] = r2; afrag[mi][3] = r3;
            }
            u32 bfrag[8][2];
            #pragma unroll
            for (int np = 0; np < 4; np++) {
                u32 r0, r1, r2, r3;
                ldsm4(r0, r1, r2, r3, bsAddr + boff0 + (u32)(np * 16 * TSTRIDE * 2) + kb);
                bfrag[np * 2 + 0][0] = r0; bfrag[np * 2 + 0][1] = r1;
                bfrag[np * 2 + 1][0] = r2; bfrag[np * 2 + 1][1] = r3;
            }
            #pragma unroll
            for (int mi = 0; mi < 4; mi++) {
                u32 a0 = afrag[mi][0], a1 = afrag[mi][1];
                u32 a2 = afrag[mi][2], a3 = afrag[mi][3];
                #pragma unroll
                for (int ni = 0; ni < 8; ni++) {
                    u32 b0 = bfrag[ni][0], b1 = bfrag[ni][1];
                    mma_f16(&acc[mi][ni][0], a0, a1, a2, a3, b0, b1);
                }
            }
        }
        __syncthreads();
        cur ^= 1;
    }

    const int rbase = bm + wm + gid;
    const int cbase = bn + wn + tig * 2;
    #pragma unroll
    for (int mi = 0; mi < 4; mi++) {
        #pragma unroll
        for (int half_ = 0; half_ < 2; half_++) {
            int r = rbase + mi * 16 + half_ * 8;
            #pragma unroll
            for (int ni = 0; ni < 8; ni++) {
                int c = cbase + ni * 8;
                float v0 = acc[mi][ni][half_ * 2 + 0] + bias[c];
                float v1 = acc[mi][ni][half_ * 2 + 1] + bias[c + 1];
                if (MODE == 0) {
                    __half2* C = (__half2*)((__half*)Cv + (size_t)r * N + c);
                    *C = __floats2half2_rn(v0, v1);
                } else if (MODE == 1) {
                    __half2* C = (__half2*)((__half*)Cv + (size_t)r * N + c);
                    *C = __floats2half2_rn(gelu_tanh(v0), gelu_tanh(v1));
                } else {
                    float* C = (float*)Cv + (size_t)r * N + c;
                    const float2 rr = *(const float2*)(R + (size_t)r * N + c);
                    float2 o2;
                    o2.x = rr.x + v0 * scale;
                    o2.y = rr.y + v1 * scale;
                    *(float2*)C = o2;
                }
            }
        }
    }
}

// ---------------- tensor-core block-local causal attention ----------------
// 128 threads = 4 warps; each warp: 16 query rows x 64 keys x 64 dims.
// S = QK^T via mma (fp16), softmax in registers, P stays in registers as
// A-fragments for P@V (V stored transposed [d][key] in smem).
__global__ __launch_bounds__(128)
void attn_kernel(const __half* __restrict__ qkv, __half* __restrict__ ctx)
{
    __shared__ __half qs [64 * TSTRIDE];
    __shared__ __half ks [64 * TSTRIDE];
    __shared__ __half vsT[64 * TSTRIDE];

    const int tid  = threadIdx.x;
    const int lane = tid & 31;
    const int warp = tid >> 5;           // 0..3
    const int gid  = lane >> 2;
    const int tig  = lane & 3;
    const int rowbase = blockIdx.z * SS + blockIdx.x * 64;
    const int colbase = blockIdx.y * 64;

    // fill qs/ks [seq][d] (16B chunks) and vsT [d][seq] (transposed)
    #pragma unroll
    for (int i = 0; i < 4; i++) {
        int idx = tid + i * 128;          // 0..511
        int r = idx >> 3, c = (idx & 7) * 8;
        size_t base = (size_t)(rowbase + r) * NQKV + colbase + c;
        *(uint4*)(qs + r * TSTRIDE + c) = *(const uint4*)(qkv + base);
        *(uint4*)(ks + r * TSTRIDE + c) = *(const uint4*)(qkv + base + DD);
    }
    #pragma unroll
    for (int i = 0; i < 16; i++) {
        int idx = tid + i * 128;          // 0..2047 half2 units
        int r = idx >> 5, c2 = idx & 31;
        __half2 hv = *(const __half2*)(qkv + (size_t)(rowbase + r) * NQKV
                                       + colbase + 2 * DD + c2 * 2);
        vsT[(c2 * 2 + 0) * TSTRIDE + r] = __low2half(hv);
        vsT[(c2 * 2 + 1) * TSTRIDE + r] = __high2half(hv);
    }
    __syncthreads();

    const int q = lane >> 3, ri = lane & 7;
    const u32 qsA = (u32)__cvta_generic_to_shared(qs);
    const u32 ksA = (u32)__cvta_generic_to_shared(ks);
    const u32 vsA = (u32)__cvta_generic_to_shared(vsT);
    const u32 aoff0 = (u32)(((warp * 16 + (q & 1) * 8 + ri) * TSTRIDE + (q >> 1) * 8) * 2);
    const u32 boff0 = (u32)((((q >> 1) * 8 + ri) * TSTRIDE + (q & 1) * 8) * 2);

    // ---- stage 1: S = Q @ K^T ----
    float sacc[8][4];
    #pragma unroll
    for (int ni = 0; ni < 8; ni++)
        #pragma unroll
        for (int r = 0; r < 4; r++) sacc[ni][r] = 0.f;

    #pragma unroll
    for (int j = 0; j < 4; j++) {
        const u32 kb = (u32)(j * 32);     // 16 halves = 32 bytes
        u32 a0, a1, a2, a3;
        ldsm4(a0, a1, a2, a3, qsA + aoff0 + kb);
        u32 bfrag[8][2];
        #pragma unroll
        for (int np = 0; np < 4; np++) {
            u32 r0, r1, r2, r3;
            ldsm4(r0, r1, r2, r3, ksA + boff0 + (u32)(np * 16 * TSTRIDE * 2) + kb);
            bfrag[np * 2 + 0][0] = r0; bfrag[np * 2 + 0][1] = r1;
            bfrag[np * 2 + 1][0] = r2; bfrag[np * 2 + 1][1] = r3;
        }
        #pragma unroll
        for (int ni = 0; ni < 8; ni++)
            mma_f16(&sacc[ni][0], a0, a1, a2, a3, bfrag[ni][0], bfrag[ni][1]);
    }

    // ---- softmax in registers (rows rowA = warp*16+gid, rowB = rowA+8) ----
    const int rowA = warp * 16 + gid;
    const int rowB = rowA + 8;
    float mA = -1e30f, mB = -1e30f;
    #pragma unroll
    for (int ni = 0; ni < 8; ni++) {
        int c0 = ni * 8 + tig * 2, c1 = c0 + 1;
        float s0 = sacc[ni][0] * 0.125f;
        float s1 = sacc[ni][1] * 0.125f;
        float s2 = sacc[ni][2] * 0.125f;
        float s3 = sacc[ni][3] * 0.125f;
        sacc[ni][0] = s0; sacc[ni][1] = s1; sacc[ni][2] = s2; sacc[ni][3] = s3;
        if (c0 <= rowA) mA = fmaxf(mA, s0);
        if (c1 <= rowA) mA = fmaxf(mA, s1);
        if (c0 <= rowB) mB = fmaxf(mB, s2);
        if (c1 <= rowB) mB = fmaxf(mB, s3);
    }
    mA = fmaxf(mA, __shfl_xor_sync(0xffffffffu, mA, 1));
    mA = fmaxf(mA, __shfl_xor_sync(0xffffffffu, mA, 2));
    mB = fmaxf(mB, __shfl_xor_sync(0xffffffffu, mB, 1));
    mB = fmaxf(mB, __shfl_xor_sync(0xffffffffu, mB, 2));

    float sumA = 0.f, sumB = 0.f;
    #pragma unroll
    for (int ni = 0; ni < 8; ni++) {
        int c0 = ni * 8 + tig * 2, c1 = c0 + 1;
        float e0 = (c0 <= rowA) ? expf(sacc[ni][0] - mA) : 0.f;
        float e1 = (c1 <= rowA) ? expf(sacc[ni][1] - mA) : 0.f;
        float e2 = (c0 <= rowB) ? expf(sacc[ni][2] - mB) : 0.f;
        float e3 = (c1 <= rowB) ? expf(sacc[ni][3] - mB) : 0.f;
        sacc[ni][0] = e0; sacc[ni][1] = e1; sacc[ni][2] = e2; sacc[ni][3] = e3;
        sumA += e0 + e1;
        sumB += e2 + e3;
    }
    sumA += __shfl_xor_sync(0xffffffffu, sumA, 1);
    sumA += __shfl_xor_sync(0xffffffffu, sumA, 2);
    sumB += __shfl_xor_sync(0xffffffffu, sumB, 1);
    sumB += __shfl_xor_sync(0xffffffffu, sumB, 2);
    const float invA = 1.f / sumA, invB = 1.f / sumB;

    // pack P into fp16 A-fragment halves: ph[ni][0] = rows gid (k-cols ni*8+tig*2),
    // ph[ni][1] = rows gid+8. C-layout of S == A-frag layout for P@V.
    u32 ph[8][2];
    #pragma unroll
    for (int ni = 0; ni < 8; ni++) {
        __half2 lo = __floats2half2_rn(sacc[ni][0] * invA, sacc[ni][1] * invA);
        __half2 hi = __floats2half2_rn(sacc[ni][2] * invB, sacc[ni][3] * invB);
        ph[ni][0] = *(u32*)&lo;
        ph[ni][1] = *(u32*)&hi;
    }

    // ---- stage 2: O = P @ V  (B operand = vsT [d][key]) ----
    float oacc[8][4];
    #pragma unroll
    for (int ni = 0; ni < 8; ni++)
        #pragma unroll
        for (int r = 0; r < 4; r++) oacc[ni][r] = 0.f;

    #pragma unroll
    for (int j = 0; j < 4; j++) {
        const u32 kb = (u32)(j * 32);
        u32 a0 = ph[2 * j][0], a1 = ph[2 * j][1];
        u32 a2 = ph[2 * j + 1][0], a3 = ph[2 * j + 1][1];
        u32 bfrag[8][2];
        #pragma unroll
        for (int np = 0; np < 4; np++) {
            u32 r0, r1, r2, r3;
            ldsm4(r0, r1, r2, r3, vsA + boff0 + (u32)(np * 16 * TSTRIDE * 2) + kb);
            bfrag[np * 2 + 0][0] = r0; bfrag[np * 2 + 0][1] = r1;
            bfrag[np * 2 + 1][0] = r2; bfrag[np * 2 + 1][1] = r3;
        }
        #pragma unroll
        for (int ni = 0; ni < 8; ni++)
            mma_f16(&oacc[ni][0], a0, a1, a2, a3, bfrag[ni][0], bfrag[ni][1]);
    }

    // write ctx (fp16): rows rowbase+rowA / +rowB, cols colbase + ni*8 + tig*2
    __half* dA = ctx + (size_t)(rowbase + rowA) * DD + colbase + tig * 2;
    __half* dB = ctx + (size_t)(rowbase + rowB) * DD + colbase + tig * 2;
    #pragma unroll
    for (int ni = 0; ni < 8; ni++) {
        *(__half2*)(dA + ni * 8) = __floats2half2_rn(oacc[ni][0], oacc[ni][1]);
        *(__half2*)(dB + ni * 8) = __floats2half2_rn(oacc[ni][2], oacc[ni][3]);
    }
}

// ---------------- launch ----------------
extern "C" void kernel_launch(void* const* d_in, const int* in_sizes, int n_in,
                              void* d_out, int out_size)
{
    const float* x    = (const float*)d_in[0];
    const float* Wq   = (const float*)d_in[2];
    const float* bq   = (const float*)d_in[3];
    const float* Wk   = (const float*)d_in[4];
    const float* bk   = (const float*)d_in[5];
    const float* Wv   = (const float*)d_in[6];
    const float* bv   = (const float*)d_in[7];
    const float* Wo   = (const float*)d_in[8];
    const float* bo   = (const float*)d_in[9];
    const float* ln1g = (const float*)d_in[10];
    const float* ln1b = (const float*)d_in[11];
    const float* ln2g = (const float*)d_in[12];
    const float* ln2b = (const float*)d_in[13];
    const float* W1   = (const float*)d_in[14];
    const float* b1   = (const float*)d_in[15];
    const float* W2   = (const float*)d_in[16];
    const float* b2   = (const float*)d_in[17];
    float* out = (float*)d_out;

    __half *h, *qkv, *ctx, *ff;
    float *x1, *bqkv;
    __half *wqkv, *wo, *w1, *w2;
    cudaGetSymbolAddress((void**)&h,    g_h);
    cudaGetSymbolAddress((void**)&qkv,  g_qkv);
    cudaGetSymbolAddress((void**)&ctx,  g_ctx);
    cudaGetSymbolAddress((void**)&x1,   g_x1);
    cudaGetSymbolAddress((void**)&ff,   g_ff);
    cudaGetSymbolAddress((void**)&wqkv, g_wqkv);
    cudaGetSymbolAddress((void**)&wo,   g_wo);
    cudaGetSymbolAddress((void**)&w1,   g_w1);
    cudaGetSymbolAddress((void**)&w2,   g_w2);
    cudaGetSymbolAddress((void**)&bqkv, g_bqkv);

    cudaFuncSetAttribute(mma_gemm<0>, cudaFuncAttributeMaxDynamicSharedMemorySize, SMEM_BYTES);
    cudaFuncSetAttribute(mma_gemm<1>, cudaFuncAttributeMaxDynamicSharedMemorySize, SMEM_BYTES);
    cudaFuncSetAttribute(mma_gemm<2>, cudaFuncAttributeMaxDynamicSharedMemorySize, SMEM_BYTES);

    // 0. one fused convert launch
    cvt_all_kernel<<<12289, dim3(32, 8)>>>(Wq, Wk, Wv, Wo, W1, W2, bq, bk, bv);

    // 1. LN1 -> h (half)
    ln_kernel<<<MROWS, 256>>>(x, ln1g, ln1b, h);

    // 2. fused QKV projection
    dim3 gQKV(NQKV / 128, MROWS / 128);
    mma_gemm<0><<<gQKV, 128, SMEM_BYTES>>>(h, wqkv, bqkv, nullptr, qkv, MROWS, NQKV, DD, 0.f);

    // 3. tensor-core attention -> ctx (half)
    dim3 gA(SS / 64, HH, BB);
    attn_kernel<<<gA, 128>>>(qkv, ctx);

    // 4. x1 = x + (ctx @ Wo + bo) * res_scale
    dim3 gD(DD / 128, MROWS / 128);
    mma_gemm<2><<<gD, 128, SMEM_BYTES>>>(ctx, wo, bo, x, x1, MROWS, DD, DD, RES_SCALE);

    // 5. LN2 -> h (half)
    ln_kernel<<<MROWS, 256>>>(x1, ln2g, ln2b, h);

    // 6. ff = (half)gelu(h @ W1 + b1)
    dim3 gF1(DFFN / 128, MROWS / 128);
    mma_gemm<1><<<gF1, 128, SMEM_BYTES>>>(h, w1, b1, nullptr, ff, MROWS, DFFN, DD, 0.f);

    // 7. out = x1 + (ff @ W2 + b2) * res_scale
    mma_gemm<2><<<gD, 128, SMEM_BYTES>>>(ff, w2, b2, x1, out, MROWS, DD, DFFN, RES_SCALE);
}

// round 11
// speedup vs baseline: 6.3324x; 1.0268x over previous
#include <cuda_runtime.h>
#include <cuda_fp16.h>
#include <math.h>

typedef unsigned int u32;

// Problem constants
#define BB 2
#define SS 2048
#define DD 1024
#define HH 16
#define DFFN 4096
#define MROWS (BB*SS)          // 4096
#define NQKV 3072
#define RES_SCALE 0.70710678118654752440f

// ---------------- device scratch ----------------
__device__ __half g_h   [MROWS * DD];
__device__ __half g_qkv [MROWS * NQKV];
__device__ __half g_ctx [MROWS * DD];
__device__ float  g_x1  [MROWS * DD];
__device__ __half g_ff  [MROWS * DFFN];
__device__ __half g_wqkv[NQKV * DD];
__device__ __half g_wo  [DD * DD];
__device__ __half g_w1  [DFFN * DD];
__device__ __half g_w2  [DD * DFFN];
__device__ float  g_bqkv[NQKV];

// ---------------- fused weight convert (one launch) ----------------
__global__ __launch_bounds__(256) void cvt_all_kernel(
    const float* __restrict__ Wq, const float* __restrict__ Wk,
    const float* __restrict__ Wv, const float* __restrict__ Wo,
    const float* __restrict__ W1, const float* __restrict__ W2,
    const float* __restrict__ bq, const float* __restrict__ bk,
    const float* __restrict__ bv)
{
    int bid = blockIdx.x;
    int tx = threadIdx.x, ty = threadIdx.y;

    if (bid == 12288) {
        int t = ty * 32 + tx;
        #pragma unroll
        for (int i = 0; i < 4; i++) {
            int j = t + i * 256;
            g_bqkv[j]          = bq[j];
            g_bqkv[DD + j]     = bk[j];
            g_bqkv[2 * DD + j] = bv[j];
        }
        return;
    }

    const float* in;
    __half* out;
    int Kdim, Ndim, n0, k0, rowOff;
    if (bid < 4096) {
        int m = bid >> 10;
        int lb = bid & 1023;
        Kdim = DD; Ndim = DD;
        n0 = (lb & 31) * 32; k0 = (lb >> 5) * 32;
        if (m == 0)      { in = Wq; out = g_wqkv; rowOff = 0; }
        else if (m == 1) { in = Wk; out = g_wqkv; rowOff = DD; }
        else if (m == 2) { in = Wv; out = g_wqkv; rowOff = 2 * DD; }
        else             { in = Wo; out = g_wo;   rowOff = 0; }
    } else if (bid < 8192) {
        int lb = bid - 4096;
        Kdim = DD; Ndim = DFFN;
        n0 = (lb & 127) * 32; k0 = (lb >> 7) * 32;
        in = W1; out = g_w1; rowOff = 0;
    } else {
        int lb = bid - 8192;
        Kdim = DFFN; Ndim = DD;
        n0 = (lb & 31) * 32; k0 = (lb >> 5) * 32;
        in = W2; out = g_w2; rowOff = 0;
    }

    __shared__ float sm[32][33];
    #pragma unroll
    for (int i = 0; i < 4; i++) {
        int r = ty + i * 8;
        sm[r][tx] = in[(size_t)(k0 + r) * Ndim + n0 + tx];
    }
    __syncthreads();
    #pragma unroll
    for (int i = 0; i < 4; i++) {
        int r = ty + i * 8;
        out[(size_t)(rowOff + n0 + r) * Kdim + k0 + tx] = __float2half_rn(sm[tx][r]);
    }
}

// ---------------- LayerNorm (fp32 in, fp16 out) ----------------
__global__ __launch_bounds__(256) void ln_kernel(const float* __restrict__ x,
                                                 const float* __restrict__ g,
                                                 const float* __restrict__ b,
                                                 __half* __restrict__ out)
{
    int row = blockIdx.x;
    int tid = threadIdx.x;
    const float4* xr = (const float4*)(x + (size_t)row * DD);
    float4 v = xr[tid];
    float s  = v.x + v.y + v.z + v.w;
    float ss = v.x*v.x + v.y*v.y + v.z*v.z + v.w*v.w;
    #pragma unroll
    for (int o = 16; o; o >>= 1) {
        s  += __shfl_xor_sync(0xffffffffu, s, o);
        ss += __shfl_xor_sync(0xffffffffu, ss, o);
    }
    __shared__ float sm1[8], sm2[8];
    int w = tid >> 5, l = tid & 31;
    if (l == 0) { sm1[w] = s; sm2[w] = ss; }
    __syncthreads();
    if (tid == 0) {
        float S = 0.f, SSu = 0.f;
        #pragma unroll
        for (int i = 0; i < 8; i++) { S += sm1[i]; SSu += sm2[i]; }
        float mu  = S  * (1.f / DD);
        float var = SSu * (1.f / DD) - mu * mu;
        sm1[0] = mu;
        sm2[0] = rsqrtf(var + 1e-5f);
    }
    __syncthreads();
    float mu  = sm1[0];
    float inv = sm2[0];
    float4 gg = ((const float4*)g)[tid];
    float4 bb = ((const float4*)b)[tid];
    __half2* orow = (__half2*)(out + (size_t)row * DD);
    orow[tid * 2 + 0] = __floats2half2_rn((v.x - mu) * inv * gg.x + bb.x,
                                          (v.y - mu) * inv * gg.y + bb.y);
    orow[tid * 2 + 1] = __floats2half2_rn((v.z - mu) * inv * gg.z + bb.z,
                                          (v.w - mu) * inv * gg.w + bb.w);
}

// ---------------- FP16 tensor-core GEMM: 3-stage cp.async + reg pipelining ------------
#define BKH 64
#define TSTRIDE 72
#define OP_STAGE (128 * TSTRIDE)                 // halves per operand per stage
#define NSTAGE 3
#define STAGE_H (2 * OP_STAGE)                   // halves per stage (A+B)
#define SMEM_BYTES (NSTAGE * STAGE_H * 2)        // 110592 B

__device__ __forceinline__ float gelu_tanh(float x) {
    float x3 = x * x * x;
    return 0.5f * x * (1.f + tanhf(0.7978845608028654f * (x + 0.044715f * x3)));
}
__device__ __forceinline__ void cp_async16h(__half* dst, const __half* src) {
    u32 d = (u32)__cvta_generic_to_shared(dst);
    asm volatile("cp.async.cg.shared.global [%0], [%1], 16;\n" :: "r"(d), "l"(src));
}
__device__ __forceinline__ void cp_commit() {
    asm volatile("cp.async.commit_group;\n");
}
__device__ __forceinline__ void cp_wait1() {
    asm volatile("cp.async.wait_group 1;\n" ::: "memory");
}
__device__ __forceinline__ void ldsm4(u32& r0, u32& r1, u32& r2, u32& r3, u32 addr) {
    asm volatile("ldmatrix.sync.aligned.m8n8.x4.shared.b16 {%0,%1,%2,%3}, [%4];"
                 : "=r"(r0), "=r"(r1), "=r"(r2), "=r"(r3) : "r"(addr));
}
__device__ __forceinline__ void mma_f16(float* acc,
                                        u32 a0, u32 a1, u32 a2, u32 a3,
                                        u32 b0, u32 b1)
{
    float d0 = acc[0], d1 = acc[1], d2 = acc[2], d3 = acc[3];
    asm volatile(
        "mma.sync.aligned.m16n8k16.row.col.f32.f16.f16.f32 "
        "{%0,%1,%2,%3}, {%4,%5,%6,%7}, {%8,%9}, {%0,%1,%2,%3};"
        : "+f"(d0), "+f"(d1), "+f"(d2), "+f"(d3)
        : "r"(a0), "r"(a1), "r"(a2), "r"(a3), "r"(b0), "r"(b1));
    acc[0] = d0; acc[1] = d1; acc[2] = d2; acc[3] = d3;
}

template<int MODE>
__global__ __launch_bounds__(128, 2)
void mma_gemm(const __half* __restrict__ A, const __half* __restrict__ Bt,
              const float* __restrict__ bias, const float* __restrict__ R,
              void* __restrict__ Cv, int M, int N, int K, float scale)
{
    extern __shared__ __half smem[];

    const int tid  = threadIdx.x;
    const int lane = tid & 31;
    const int warp = tid >> 5;
    const int wm   = (warp >> 1) * 64;
    const int wn   = (warp & 1) * 64;
    const int bm   = blockIdx.y * 128;
    const int bn   = blockIdx.x * 128;
    const int gid  = lane >> 2;
    const int tig  = lane & 3;

    const int q = lane >> 3, ri = lane & 7;
    const u32 aoff0 = (u32)(((wm + (q & 1) * 8 + ri) * TSTRIDE + (q >> 1) * 8) * 2);
    const u32 boff0 = (u32)(((wn + (q >> 1) * 8 + ri) * TSTRIDE + (q & 1) * 8) * 2);

    float acc[4][8][4];
    #pragma unroll
    for (int mi = 0; mi < 4; mi++)
        #pragma unroll
        for (int ni = 0; ni < 8; ni++)
            #pragma unroll
            for (int r = 0; r < 4; r++) acc[mi][ni][r] = 0.f;

    const int T = K / BKH;

    // stage loader
    auto load_tile = [&](int s, int tp) {
        __half* as = smem + s * STAGE_H;
        __half* bs = as + OP_STAGE;
        int k0 = tp * BKH;
        const __half* Ag = A + (size_t)bm * K + k0;
        const __half* Bg = Bt + (size_t)bn * K + k0;
        #pragma unroll
        for (int i = 0; i < 8; i++) {
            int idx = tid + i * 128;
            int r = idx >> 3, c = (idx & 7) * 8;
            cp_async16h(as + r * TSTRIDE + c, Ag + (size_t)r * K + c);
            cp_async16h(bs + r * TSTRIDE + c, Bg + (size_t)r * K + c);
        }
        cp_commit();
    };

    // prologue: tiles 0 and 1
    load_tile(0, 0);
    load_tile(1, 1);

    int sc = 0;
    for (int t = 0; t < T; t++) {
        cp_wait1();                 // tile t resident; tile t+1 may be in flight
        __syncthreads();

        if (t + 2 < T) {
            int sp = sc + 2; if (sp >= NSTAGE) sp -= NSTAGE;
            load_tile(sp, t + 2);
        }

        const u32 asAddr = (u32)__cvta_generic_to_shared(smem + sc * STAGE_H);
        const u32 bsAddr = asAddr + (u32)(OP_STAGE * 2);

        // register-pipelined compute over 4 k-steps
        u32 af[2][4][4];
        u32 bf[2][8][2];

        // prefetch k-step 0
        #pragma unroll
        for (int mi = 0; mi < 4; mi++) {
            u32 r0, r1, r2, r3;
            ldsm4(r0, r1, r2, r3, asAddr + aoff0 + (u32)(mi * 16 * TSTRIDE * 2));
            af[0][mi][0] = r0; af[0][mi][1] = r1; af[0][mi][2] = r2; af[0][mi][3] = r3;
        }
        #pragma unroll
        for (int np = 0; np < 4; np++) {
            u32 r0, r1, r2, r3;
            ldsm4(r0, r1, r2, r3, bsAddr + boff0 + (u32)(np * 16 * TSTRIDE * 2));
            bf[0][np * 2 + 0][0] = r0; bf[0][np * 2 + 0][1] = r1;
            bf[0][np * 2 + 1][0] = r2; bf[0][np * 2 + 1][1] = r3;
        }

        #pragma unroll
        for (int kk = 0; kk < 4; kk++) {
            const int cb = kk & 1, nb = cb ^ 1;
            if (kk < 3) {
                const u32 kb = (u32)((kk + 1) * 32);
                #pragma unroll
                for (int mi = 0; mi < 4; mi++) {
                    u32 r0, r1, r2, r3;
                    ldsm4(r0, r1, r2, r3, asAddr + aoff0 + (u32)(mi * 16 * TSTRIDE * 2) + kb);
                    af[nb][mi][0] = r0; af[nb][mi][1] = r1;
                    af[nb][mi][2] = r2; af[nb][mi][3] = r3;
                }
                #pragma unroll
                for (int np = 0; np < 4; np++) {
                    u32 r0, r1, r2, r3;
                    ldsm4(r0, r1, r2, r3, bsAddr + boff0 + (u32)(np * 16 * TSTRIDE * 2) + kb);
                    bf[nb][np * 2 + 0][0] = r0; bf[nb][np * 2 + 0][1] = r1;
                    bf[nb][np * 2 + 1][0] = r2; bf[nb][np * 2 + 1][1] = r3;
                }
            }
            #pragma unroll
            for (int mi = 0; mi < 4; mi++) {
                u32 a0 = af[cb][mi][0], a1 = af[cb][mi][1];
                u32 a2 = af[cb][mi][2], a3 = af[cb][mi][3];
                #pragma unroll
                for (int ni = 0; ni < 8; ni++) {
                    u32 b0 = bf[cb][ni][0], b1 = bf[cb][ni][1];
                    mma_f16(&acc[mi][ni][0], a0, a1, a2, a3, b0, b1);
                }
            }
        }

        __syncthreads();
        if (++sc >= NSTAGE) sc = 0;
    }

    // epilogue
    const int rbase = bm + wm + gid;
    const int cbase = bn + wn + tig * 2;
    #pragma unroll
    for (int mi = 0; mi < 4; mi++) {
        #pragma unroll
        for (int half_ = 0; half_ < 2; half_++) {
            int r = rbase + mi * 16 + half_ * 8;
            #pragma unroll
            for (int ni = 0; ni < 8; ni++) {
                int c = cbase + ni * 8;
                float v0 = acc[mi][ni][half_ * 2 + 0] + bias[c];
                float v1 = acc[mi][ni][half_ * 2 + 1] + bias[c + 1];
                if (MODE == 0) {
                    __half2* C = (__half2*)((__half*)Cv + (size_t)r * N + c);
                    *C = __floats2half2_rn(v0, v1);
                } else if (MODE == 1) {
                    __half2* C = (__half2*)((__half*)Cv + (size_t)r * N + c);
                    *C = __floats2half2_rn(gelu_tanh(v0), gelu_tanh(v1));
                } else {
                    float* C = (float*)Cv + (size_t)r * N + c;
                    const float2 rr = *(const float2*)(R + (size_t)r * N + c);
                    float2 o2;
                    o2.x = rr.x + v0 * scale;
                    o2.y = rr.y + v1 * scale;
                    *(float2*)C = o2;
                }
            }
        }
    }
}

// ---------------- tensor-core block-local causal attention (unchanged) ----------------
__global__ __launch_bounds__(128)
void attn_kernel(const __half* __restrict__ qkv, __half* __restrict__ ctx)
{
    __shared__ __half qs [64 * TSTRIDE];
    __shared__ __half ks [64 * TSTRIDE];
    __shared__ __half vsT[64 * TSTRIDE];

    const int tid  = threadIdx.x;
    const int lane = tid & 31;
    const int warp = tid >> 5;
    const int gid  = lane >> 2;
    const int tig  = lane & 3;
    const int rowbase = blockIdx.z * SS + blockIdx.x * 64;
    const int colbase = blockIdx.y * 64;

    #pragma unroll
    for (int i = 0; i < 4; i++) {
        int idx = tid + i * 128;
        int r = idx >> 3, c = (idx & 7) * 8;
        size_t base = (size_t)(rowbase + r) * NQKV + colbase + c;
        *(uint4*)(qs + r * TSTRIDE + c) = *(const uint4*)(qkv + base);
        *(uint4*)(ks + r * TSTRIDE + c) = *(const uint4*)(qkv + base + DD);
    }
    #pragma unroll
    for (int i = 0; i < 16; i++) {
        int idx = tid + i * 128;
        int r = idx >> 5, c2 = idx & 31;
        __half2 hv = *(const __half2*)(qkv + (size_t)(rowbase + r) * NQKV
                                       + colbase + 2 * DD + c2 * 2);
        vsT[(c2 * 2 + 0) * TSTRIDE + r] = __low2half(hv);
        vsT[(c2 * 2 + 1) * TSTRIDE + r] = __high2half(hv);
    }
    __syncthreads();

    const int q = lane >> 3, ri = lane & 7;
    const u32 qsA = (u32)__cvta_generic_to_shared(qs);
    const u32 ksA = (u32)__cvta_generic_to_shared(ks);
    const u32 vsA = (u32)__cvta_generic_to_shared(vsT);
    const u32 aoff0 = (u32)(((warp * 16 + (q & 1) * 8 + ri) * TSTRIDE + (q >> 1) * 8) * 2);
    const u32 boff0 = (u32)((((q >> 1) * 8 + ri) * TSTRIDE + (q & 1) * 8) * 2);

    float sacc[8][4];
    #pragma unroll
    for (int ni = 0; ni < 8; ni++)
        #pragma unroll
        for (int r = 0; r < 4; r++) sacc[ni][r] = 0.f;

    #pragma unroll
    for (int j = 0; j < 4; j++) {
        const u32 kb = (u32)(j * 32);
        u32 a0, a1, a2, a3;
        ldsm4(a0, a1, a2, a3, qsA + aoff0 + kb);
        u32 bfrag[8][2];
        #pragma unroll
        for (int np = 0; np < 4; np++) {
            u32 r0, r1, r2, r3;
            ldsm4(r0, r1, r2, r3, ksA + boff0 + (u32)(np * 16 * TSTRIDE * 2) + kb);
            bfrag[np * 2 + 0][0] = r0; bfrag[np * 2 + 0][1] = r1;
            bfrag[np * 2 + 1][0] = r2; bfrag[np * 2 + 1][1] = r3;
        }
        #pragma unroll
        for (int ni = 0; ni < 8; ni++)
            mma_f16(&sacc[ni][0], a0, a1, a2, a3, bfrag[ni][0], bfrag[ni][1]);
    }

    const int rowA = warp * 16 + gid;
    const int rowB = rowA + 8;
    float mA = -1e30f, mB = -1e30f;
    #pragma unroll
    for (int ni = 0; ni < 8; ni++) {
        int c0 = ni * 8 + tig * 2, c1 = c0 + 1;
        float s0 = sacc[ni][0] * 0.125f;
        float s1 = sacc[ni][1] * 0.125f;
        float s2 = sacc[ni][2] * 0.125f;
        float s3 = sacc[ni][3] * 0.125f;
        sacc[ni][0] = s0; sacc[ni][1] = s1; sacc[ni][2] = s2; sacc[ni][3] = s3;
        if (c0 <= rowA) mA = fmaxf(mA, s0);
        if (c1 <= rowA) mA = fmaxf(mA, s1);
        if (c0 <= rowB) mB = fmaxf(mB, s2);
        if (c1 <= rowB) mB = fmaxf(mB, s3);
    }
    mA = fmaxf(mA, __shfl_xor_sync(0xffffffffu, mA, 1));
    mA = fmaxf(mA, __shfl_xor_sync(0xffffffffu, mA, 2));
    mB = fmaxf(mB, __shfl_xor_sync(0xffffffffu, mB, 1));
    mB = fmaxf(mB, __shfl_xor_sync(0xffffffffu, mB, 2));

    float sumA = 0.f, sumB = 0.f;
    #pragma unroll
    for (int ni = 0; ni < 8; ni++) {
        int c0 = ni * 8 + tig * 2, c1 = c0 + 1;
        float e0 = (c0 <= rowA) ? expf(sacc[ni][0] - mA) : 0.f;
        float e1 = (c1 <= rowA) ? expf(sacc[ni][1] - mA) : 0.f;
        float e2 = (c0 <= rowB) ? expf(sacc[ni][2] - mB) : 0.f;
        float e3 = (c1 <= rowB) ? expf(sacc[ni][3] - mB) : 0.f;
        sacc[ni][0] = e0; sacc[ni][1] = e1; sacc[ni][2] = e2; sacc[ni][3] = e3;
        sumA += e0 + e1;
        sumB += e2 + e3;
    }
    sumA += __shfl_xor_sync(0xffffffffu, sumA, 1);
    sumA += __shfl_xor_sync(0xffffffffu, sumA, 2);
    sumB += __shfl_xor_sync(0xffffffffu, sumB, 1);
    sumB += __shfl_xor_sync(0xffffffffu, sumB, 2);
    const float invA = 1.f / sumA, invB = 1.f / sumB;

    u32 ph[8][2];
    #pragma unroll
    for (int ni = 0; ni < 8; ni++) {
        __half2 lo = __floats2half2_rn(sacc[ni][0] * invA, sacc[ni][1] * invA);
        __half2 hi = __floats2half2_rn(sacc[ni][2] * invB, sacc[ni][3] * invB);
        ph[ni][0] = *(u32*)&lo;
        ph[ni][1] = *(u32*)&hi;
    }

    float oacc[8][4];
    #pragma unroll
    for (int ni = 0; ni < 8; ni++)
        #pragma unroll
        for (int r = 0; r < 4; r++) oacc[ni][r] = 0.f;

    #pragma unroll
    for (int j = 0; j < 4; j++) {
        const u32 kb = (u32)(j * 32);
        u32 a0 = ph[2 * j][0], a1 = ph[2 * j][1];
        u32 a2 = ph[2 * j + 1][0], a3 = ph[2 * j + 1][1];
        u32 bfrag[8][2];
        #pragma unroll
        for (int np = 0; np < 4; np++) {
            u32 r0, r1, r2, r3;
            ldsm4(r0, r1, r2, r3, vsA + boff0 + (u32)(np * 16 * TSTRIDE * 2) + kb);
            bfrag[np * 2 + 0][0] = r0; bfrag[np * 2 + 0][1] = r1;
            bfrag[np * 2 + 1][0] = r2; bfrag[np * 2 + 1][1] = r3;
        }
        #pragma unroll
        for (int ni = 0; ni < 8; ni++)
            mma_f16(&oacc[ni][0], a0, a1, a2, a3, bfrag[ni][0], bfrag[ni][1]);
    }

    __half* dA = ctx + (size_t)(rowbase + rowA) * DD + colbase + tig * 2;
    __half* dB = ctx + (size_t)(rowbase + rowB) * DD + colbase + tig * 2;
    #pragma unroll
    for (int ni = 0; ni < 8; ni++) {
        *(__half2*)(dA + ni * 8) = __floats2half2_rn(oacc[ni][0], oacc[ni][1]);
        *(__half2*)(dB + ni * 8) = __floats2half2_rn(oacc[ni][2], oacc[ni][3]);
    }
}

// ---------------- launch ----------------
extern "C" void kernel_launch(void* const* d_in, const int* in_sizes, int n_in,
                              void* d_out, int out_size)
{
    const float* x    = (const float*)d_in[0];
    const float* Wq   = (const float*)d_in[2];
    const float* bq   = (const float*)d_in[3];
    const float* Wk   = (const float*)d_in[4];
    const float* bk   = (const float*)d_in[5];
    const float* Wv   = (const float*)d_in[6];
    const float* bv   = (const float*)d_in[7];
    const float* Wo   = (const float*)d_in[8];
    const float* bo   = (const float*)d_in[9];
    const float* ln1g = (const float*)d_in[10];
    const float* ln1b = (const float*)d_in[11];
    const float* ln2g = (const float*)d_in[12];
    const float* ln2b = (const float*)d_in[13];
    const float* W1   = (const float*)d_in[14];
    const float* b1   = (const float*)d_in[15];
    const float* W2   = (const float*)d_in[16];
    const float* b2   = (const float*)d_in[17];
    float* out = (float*)d_out;

    __half *h, *qkv, *ctx, *ff;
    float *x1, *bqkv;
    __half *wqkv, *wo, *w1, *w2;
    cudaGetSymbolAddress((void**)&h,    g_h);
    cudaGetSymbolAddress((void**)&qkv,  g_qkv);
    cudaGetSymbolAddress((void**)&ctx,  g_ctx);
    cudaGetSymbolAddress((void**)&x1,   g_x1);
    cudaGetSymbolAddress((void**)&ff,   g_ff);
    cudaGetSymbolAddress((void**)&wqkv, g_wqkv);
    cudaGetSymbolAddress((void**)&wo,   g_wo);
    cudaGetSymbolAddress((void**)&w1,   g_w1);
    cudaGetSymbolAddress((void**)&w2,   g_w2);
    cudaGetSymbolAddress((void**)&bqkv, g_bqkv);

    cudaFuncSetAttribute(mma_gemm<0>, cudaFuncAttributeMaxDynamicSharedMemorySize, SMEM_BYTES);
    cudaFuncSetAttribute(mma_gemm<1>, cudaFuncAttributeMaxDynamicSharedMemorySize, SMEM_BYTES);
    cudaFuncSetAttribute(mma_gemm<2>, cudaFuncAttributeMaxDynamicSharedMemorySize, SMEM_BYTES);

    // 0. one fused convert launch
    cvt_all_kernel<<<12289, dim3(32, 8)>>>(Wq, Wk, Wv, Wo, W1, W2, bq, bk, bv);

    // 1. LN1 -> h (half)
    ln_kernel<<<MROWS, 256>>>(x, ln1g, ln1b, h);

    // 2. fused QKV projection
    dim3 gQKV(NQKV / 128, MROWS / 128);
    mma_gemm<0><<<gQKV, 128, SMEM_BYTES>>>(h, wqkv, bqkv, nullptr, qkv, MROWS, NQKV, DD, 0.f);

    // 3. tensor-core attention -> ctx (half)
    dim3 gA(SS / 64, HH, BB);
    attn_kernel<<<gA, 128>>>(qkv, ctx);

    // 4. x1 = x + (ctx @ Wo + bo) * res_scale
    dim3 gD(DD / 128, MROWS / 128);
    mma_gemm<2><<<gD, 128, SMEM_BYTES>>>(ctx, wo, bo, x, x1, MROWS, DD, DD, RES_SCALE);

    // 5. LN2 -> h (half)
    ln_kernel<<<MROWS, 256>>>(x1, ln2g, ln2b, h);

    // 6. ff = (half)gelu(h @ W1 + b1)
    dim3 gF1(DFFN / 128, MROWS / 128);
    mma_gemm<1><<<gF1, 128, SMEM_BYTES>>>(h, w1, b1, nullptr, ff, MROWS, DFFN, DD, 0.f);

    // 7. out = x1 + (ff @ W2 + b2) * res_scale
    mma_gemm<2><<<gD, 128, SMEM_BYTES>>>(ff, w2, b2, x1, out, MROWS, DD, DFFN, RES_SCALE);
}

// round 12
// speedup vs baseline: 6.3920x; 1.0094x over previous
#include <cuda_runtime.h>
#include <cuda_fp16.h>
#include <math.h>

typedef unsigned int u32;

// Problem constants
#define BB 2
#define SS 2048
#define DD 1024
#define HH 16
#define DFFN 4096
#define MROWS (BB*SS)          // 4096
#define NQKV 3072
#define RES_SCALE 0.70710678118654752440f

// ---------------- device scratch ----------------
__device__ __half g_h   [MROWS * DD];
__device__ __half g_qkv [MROWS * NQKV];
__device__ __half g_ctx [MROWS * DD];
__device__ float  g_x1  [MROWS * DD];
__device__ __half g_ff  [MROWS * DFFN];
__device__ __half g_wqkv[NQKV * DD];
__device__ __half g_wo  [DD * DD];
__device__ __half g_w1  [DFFN * DD];
__device__ __half g_w2  [DD * DFFN];
__device__ float  g_bqkv[NQKV];

// ---------------- fused weight convert (one launch) ----------------
__global__ __launch_bounds__(256) void cvt_all_kernel(
    const float* __restrict__ Wq, const float* __restrict__ Wk,
    const float* __restrict__ Wv, const float* __restrict__ Wo,
    const float* __restrict__ W1, const float* __restrict__ W2,
    const float* __restrict__ bq, const float* __restrict__ bk,
    const float* __restrict__ bv)
{
    int bid = blockIdx.x;
    int tx = threadIdx.x, ty = threadIdx.y;

    if (bid == 12288) {
        int t = ty * 32 + tx;
        #pragma unroll
        for (int i = 0; i < 4; i++) {
            int j = t + i * 256;
            g_bqkv[j]          = bq[j];
            g_bqkv[DD + j]     = bk[j];
            g_bqkv[2 * DD + j] = bv[j];
        }
        return;
    }

    const float* in;
    __half* out;
    int Kdim, Ndim, n0, k0, rowOff;
    if (bid < 4096) {
        int m = bid >> 10;
        int lb = bid & 1023;
        Kdim = DD; Ndim = DD;
        n0 = (lb & 31) * 32; k0 = (lb >> 5) * 32;
        if (m == 0)      { in = Wq; out = g_wqkv; rowOff = 0; }
        else if (m == 1) { in = Wk; out = g_wqkv; rowOff = DD; }
        else if (m == 2) { in = Wv; out = g_wqkv; rowOff = 2 * DD; }
        else             { in = Wo; out = g_wo;   rowOff = 0; }
    } else if (bid < 8192) {
        int lb = bid - 4096;
        Kdim = DD; Ndim = DFFN;
        n0 = (lb & 127) * 32; k0 = (lb >> 7) * 32;
        in = W1; out = g_w1; rowOff = 0;
    } else {
        int lb = bid - 8192;
        Kdim = DFFN; Ndim = DD;
        n0 = (lb & 31) * 32; k0 = (lb >> 5) * 32;
        in = W2; out = g_w2; rowOff = 0;
    }

    __shared__ float sm[32][33];
    #pragma unroll
    for (int i = 0; i < 4; i++) {
        int r = ty + i * 8;
        sm[r][tx] = in[(size_t)(k0 + r) * Ndim + n0 + tx];
    }
    __syncthreads();
    #pragma unroll
    for (int i = 0; i < 4; i++) {
        int r = ty + i * 8;
        out[(size_t)(rowOff + n0 + r) * Kdim + k0 + tx] = __float2half_rn(sm[tx][r]);
    }
}

// ---------------- LayerNorm (fp32 in, fp16 out) ----------------
__global__ __launch_bounds__(256) void ln_kernel(const float* __restrict__ x,
                                                 const float* __restrict__ g,
                                                 const float* __restrict__ b,
                                                 __half* __restrict__ out)
{
    int row = blockIdx.x;
    int tid = threadIdx.x;
    const float4* xr = (const float4*)(x + (size_t)row * DD);
    float4 v = xr[tid];
    float s  = v.x + v.y + v.z + v.w;
    float ss = v.x*v.x + v.y*v.y + v.z*v.z + v.w*v.w;
    #pragma unroll
    for (int o = 16; o; o >>= 1) {
        s  += __shfl_xor_sync(0xffffffffu, s, o);
        ss += __shfl_xor_sync(0xffffffffu, ss, o);
    }
    __shared__ float sm1[8], sm2[8];
    int w = tid >> 5, l = tid & 31;
    if (l == 0) { sm1[w] = s; sm2[w] = ss; }
    __syncthreads();
    if (tid == 0) {
        float S = 0.f, SSu = 0.f;
        #pragma unroll
        for (int i = 0; i < 8; i++) { S += sm1[i]; SSu += sm2[i]; }
        float mu  = S  * (1.f / DD);
        float var = SSu * (1.f / DD) - mu * mu;
        sm1[0] = mu;
        sm2[0] = rsqrtf(var + 1e-5f);
    }
    __syncthreads();
    float mu  = sm1[0];
    float inv = sm2[0];
    float4 gg = ((const float4*)g)[tid];
    float4 bb = ((const float4*)b)[tid];
    __half2* orow = (__half2*)(out + (size_t)row * DD);
    orow[tid * 2 + 0] = __floats2half2_rn((v.x - mu) * inv * gg.x + bb.x,
                                          (v.y - mu) * inv * gg.y + bb.y);
    orow[tid * 2 + 1] = __floats2half2_rn((v.z - mu) * inv * gg.z + bb.z,
                                          (v.w - mu) * inv * gg.w + bb.w);
}

// ---------------- FP16 tensor-core GEMM: 3-stage, 1 barrier/tile, compile-time K ------
#define BKH 64
#define TSTRIDE 72
#define OP_STAGE (128 * TSTRIDE)
#define NSTAGE 3
#define STAGE_H (2 * OP_STAGE)
#define SMEM_BYTES (NSTAGE * STAGE_H * 2)        // 110592 B

__device__ __forceinline__ float gelu_tanh(float x) {
    float x3 = x * x * x;
    return 0.5f * x * (1.f + tanhf(0.7978845608028654f * (x + 0.044715f * x3)));
}
__device__ __forceinline__ void cp_async16h(__half* dst, const __half* src) {
    u32 d = (u32)__cvta_generic_to_shared(dst);
    asm volatile("cp.async.cg.shared.global [%0], [%1], 16;\n" :: "r"(d), "l"(src));
}
__device__ __forceinline__ void cp_commit() {
    asm volatile("cp.async.commit_group;\n");
}
__device__ __forceinline__ void cp_wait1() {
    asm volatile("cp.async.wait_group 1;\n" ::: "memory");
}
__device__ __forceinline__ void ldsm4(u32& r0, u32& r1, u32& r2, u32& r3, u32 addr) {
    asm volatile("ldmatrix.sync.aligned.m8n8.x4.shared.b16 {%0,%1,%2,%3}, [%4];"
                 : "=r"(r0), "=r"(r1), "=r"(r2), "=r"(r3) : "r"(addr));
}
__device__ __forceinline__ void mma_f16(float* acc,
                                        u32 a0, u32 a1, u32 a2, u32 a3,
                                        u32 b0, u32 b1)
{
    float d0 = acc[0], d1 = acc[1], d2 = acc[2], d3 = acc[3];
    asm volatile(
        "mma.sync.aligned.m16n8k16.row.col.f32.f16.f16.f32 "
        "{%0,%1,%2,%3}, {%4,%5,%6,%7}, {%8,%9}, {%0,%1,%2,%3};"
        : "+f"(d0), "+f"(d1), "+f"(d2), "+f"(d3)
        : "r"(a0), "r"(a1), "r"(a2), "r"(a3), "r"(b0), "r"(b1));
    acc[0] = d0; acc[1] = d1; acc[2] = d2; acc[3] = d3;
}

template<int MODE, int KDIM>
__global__ __launch_bounds__(128, 2)
void mma_gemm(const __half* __restrict__ A, const __half* __restrict__ Bt,
              const float* __restrict__ bias, const float* __restrict__ R,
              void* __restrict__ Cv, int N, float scale)
{
    extern __shared__ __half smem[];
    constexpr int K = KDIM;
    constexpr int T = K / BKH;

    const int tid  = threadIdx.x;
    const int lane = tid & 31;
    const int warp = tid >> 5;
    const int wm   = (warp >> 1) * 64;
    const int wn   = (warp & 1) * 64;
    const int bm   = blockIdx.y * 128;
    const int bn   = blockIdx.x * 128;
    const int gid  = lane >> 2;
    const int tig  = lane & 3;

    const int q = lane >> 3, ri = lane & 7;
    const u32 aoff0 = (u32)(((wm + (q & 1) * 8 + ri) * TSTRIDE + (q >> 1) * 8) * 2);
    const u32 boff0 = (u32)(((wn + (q >> 1) * 8 + ri) * TSTRIDE + (q & 1) * 8) * 2);

    float acc[4][8][4];
    #pragma unroll
    for (int mi = 0; mi < 4; mi++)
        #pragma unroll
        for (int ni = 0; ni < 8; ni++)
            #pragma unroll
            for (int r = 0; r < 4; r++) acc[mi][ni][r] = 0.f;

    // stage loader
    auto load_tile = [&](int s, int tp) {
        __half* as = smem + s * STAGE_H;
        __half* bs = as + OP_STAGE;
        int k0 = tp * BKH;
        const __half* Ag = A + (size_t)bm * K + k0;
        const __half* Bg = Bt + (size_t)bn * K + k0;
        #pragma unroll
        for (int i = 0; i < 8; i++) {
            int idx = tid + i * 128;
            int r = idx >> 3, c = (idx & 7) * 8;
            cp_async16h(as + r * TSTRIDE + c, Ag + (size_t)r * K + c);
            cp_async16h(bs + r * TSTRIDE + c, Bg + (size_t)r * K + c);
        }
        cp_commit();
    };

    // prologue: tiles 0 and 1
    load_tile(0, 0);
    load_tile(1, 1);

    int sc = 0;
    #pragma unroll 2
    for (int t = 0; t < T; t++) {
        cp_wait1();                 // tile t resident; tile t+1 may be in flight
        __syncthreads();            // also orders: all warps done computing t-1
                                    // (=> stage (t+2)%3 is free to overwrite)

        if (t + 2 < T) {
            int sp = sc + 2; if (sp >= NSTAGE) sp -= NSTAGE;
            load_tile(sp, t + 2);
        }

        const u32 asAddr = (u32)__cvta_generic_to_shared(smem + sc * STAGE_H);
        const u32 bsAddr = asAddr + (u32)(OP_STAGE * 2);

        // register-pipelined compute over 4 k-steps
        u32 af[2][4][4];
        u32 bf[2][8][2];

        #pragma unroll
        for (int mi = 0; mi < 4; mi++) {
            u32 r0, r1, r2, r3;
            ldsm4(r0, r1, r2, r3, asAddr + aoff0 + (u32)(mi * 16 * TSTRIDE * 2));
            af[0][mi][0] = r0; af[0][mi][1] = r1; af[0][mi][2] = r2; af[0][mi][3] = r3;
        }
        #pragma unroll
        for (int np = 0; np < 4; np++) {
            u32 r0, r1, r2, r3;
            ldsm4(r0, r1, r2, r3, bsAddr + boff0 + (u32)(np * 16 * TSTRIDE * 2));
            bf[0][np * 2 + 0][0] = r0; bf[0][np * 2 + 0][1] = r1;
            bf[0][np * 2 + 1][0] = r2; bf[0][np * 2 + 1][1] = r3;
        }

        #pragma unroll
        for (int kk = 0; kk < 4; kk++) {
            const int cb = kk & 1, nb = cb ^ 1;
            if (kk < 3) {
                const u32 kb = (u32)((kk + 1) * 32);
                #pragma unroll
                for (int mi = 0; mi < 4; mi++) {
                    u32 r0, r1, r2, r3;
                    ldsm4(r0, r1, r2, r3, asAddr + aoff0 + (u32)(mi * 16 * TSTRIDE * 2) + kb);
                    af[nb][mi][0] = r0; af[nb][mi][1] = r1;
                    af[nb][mi][2] = r2; af[nb][mi][3] = r3;
                }
                #pragma unroll
                for (int np = 0; np < 4; np++) {
                    u32 r0, r1, r2, r3;
                    ldsm4(r0, r1, r2, r3, bsAddr + boff0 + (u32)(np * 16 * TSTRIDE * 2) + kb);
                    bf[nb][np * 2 + 0][0] = r0; bf[nb][np * 2 + 0][1] = r1;
                    bf[nb][np * 2 + 1][0] = r2; bf[nb][np * 2 + 1][1] = r3;
                }
            }
            #pragma unroll
            for (int mi = 0; mi < 4; mi++) {
                u32 a0 = af[cb][mi][0], a1 = af[cb][mi][1];
                u32 a2 = af[cb][mi][2], a3 = af[cb][mi][3];
                #pragma unroll
                for (int ni = 0; ni < 8; ni++) {
                    u32 b0 = bf[cb][ni][0], b1 = bf[cb][ni][1];
                    mma_f16(&acc[mi][ni][0], a0, a1, a2, a3, b0, b1);
                }
            }
        }

        // NOTE: no trailing __syncthreads — top-of-loop barrier at t+1 provides
        // the ordering before stage (t+3)%3 == (t)%3 is overwritten.
        if (++sc >= NSTAGE) sc = 0;
    }

    // epilogue
    const int rbase = bm + wm + gid;
    const int cbase = bn + wn + tig * 2;
    #pragma unroll
    for (int mi = 0; mi < 4; mi++) {
        #pragma unroll
        for (int half_ = 0; half_ < 2; half_++) {
            int r = rbase + mi * 16 + half_ * 8;
            #pragma unroll
            for (int ni = 0; ni < 8; ni++) {
                int c = cbase + ni * 8;
                float v0 = acc[mi][ni][half_ * 2 + 0] + bias[c];
                float v1 = acc[mi][ni][half_ * 2 + 1] + bias[c + 1];
                if (MODE == 0) {
                    __half2* C = (__half2*)((__half*)Cv + (size_t)r * N + c);
                    *C = __floats2half2_rn(v0, v1);
                } else if (MODE == 1) {
                    __half2* C = (__half2*)((__half*)Cv + (size_t)r * N + c);
                    *C = __floats2half2_rn(gelu_tanh(v0), gelu_tanh(v1));
                } else {
                    float* C = (float*)Cv + (size_t)r * N + c;
                    const float2 rr = *(const float2*)(R + (size_t)r * N + c);
                    float2 o2;
                    o2.x = rr.x + v0 * scale;
                    o2.y = rr.y + v1 * scale;
                    *(float2*)C = o2;
                }
            }
        }
    }
}

// ---------------- tensor-core block-local causal attention ----------------
__global__ __launch_bounds__(128)
void attn_kernel(const __half* __restrict__ qkv, __half* __restrict__ ctx)
{
    __shared__ __half qs [64 * TSTRIDE];
    __shared__ __half ks [64 * TSTRIDE];
    __shared__ __half vsT[64 * TSTRIDE];

    const int tid  = threadIdx.x;
    const int lane = tid & 31;
    const int warp = tid >> 5;
    const int gid  = lane >> 2;
    const int tig  = lane & 3;
    const int rowbase = blockIdx.z * SS + blockIdx.x * 64;
    const int colbase = blockIdx.y * 64;

    #pragma unroll
    for (int i = 0; i < 4; i++) {
        int idx = tid + i * 128;
        int r = idx >> 3, c = (idx & 7) * 8;
        size_t base = (size_t)(rowbase + r) * NQKV + colbase + c;
        *(uint4*)(qs + r * TSTRIDE + c) = *(const uint4*)(qkv + base);
        *(uint4*)(ks + r * TSTRIDE + c) = *(const uint4*)(qkv + base + DD);
    }
    #pragma unroll
    for (int i = 0; i < 16; i++) {
        int idx = tid + i * 128;
        int r = idx >> 5, c2 = idx & 31;
        __half2 hv = *(const __half2*)(qkv + (size_t)(rowbase + r) * NQKV
                                       + colbase + 2 * DD + c2 * 2);
        vsT[(c2 * 2 + 0) * TSTRIDE + r] = __low2half(hv);
        vsT[(c2 * 2 + 1) * TSTRIDE + r] = __high2half(hv);
    }
    __syncthreads();

    const int q = lane >> 3, ri = lane & 7;
    const u32 qsA = (u32)__cvta_generic_to_shared(qs);
    const u32 ksA = (u32)__cvta_generic_to_shared(ks);
    const u32 vsA = (u32)__cvta_generic_to_shared(vsT);
    const u32 aoff0 = (u32)(((warp * 16 + (q & 1) * 8 + ri) * TSTRIDE + (q >> 1) * 8) * 2);
    const u32 boff0 = (u32)((((q >> 1) * 8 + ri) * TSTRIDE + (q & 1) * 8) * 2);

    float sacc[8][4];
    #pragma unroll
    for (int ni = 0; ni < 8; ni++)
        #pragma unroll
        for (int r = 0; r < 4; r++) sacc[ni][r] = 0.f;

    #pragma unroll
    for (int j = 0; j < 4; j++) {
        const u32 kb = (u32)(j * 32);
        u32 a0, a1, a2, a3;
        ldsm4(a0, a1, a2, a3, qsA + aoff0 + kb);
        u32 bfrag[8][2];
        #pragma unroll
        for (int np = 0; np < 4; np++) {
            u32 r0, r1, r2, r3;
            ldsm4(r0, r1, r2, r3, ksA + boff0 + (u32)(np * 16 * TSTRIDE * 2) + kb);
            bfrag[np * 2 + 0][0] = r0; bfrag[np * 2 + 0][1] = r1;
            bfrag[np * 2 + 1][0] = r2; bfrag[np * 2 + 1][1] = r3;
        }
        #pragma unroll
        for (int ni = 0; ni < 8; ni++)
            mma_f16(&sacc[ni][0], a0, a1, a2, a3, bfrag[ni][0], bfrag[ni][1]);
    }

    const int rowA = warp * 16 + gid;
    const int rowB = rowA + 8;
    float mA = -1e30f, mB = -1e30f;
    #pragma unroll
    for (int ni = 0; ni < 8; ni++) {
        int c0 = ni * 8 + tig * 2, c1 = c0 + 1;
        float s0 = sacc[ni][0] * 0.125f;
        float s1 = sacc[ni][1] * 0.125f;
        float s2 = sacc[ni][2] * 0.125f;
        float s3 = sacc[ni][3] * 0.125f;
        sacc[ni][0] = s0; sacc[ni][1] = s1; sacc[ni][2] = s2; sacc[ni][3] = s3;
        if (c0 <= rowA) mA = fmaxf(mA, s0);
        if (c1 <= rowA) mA = fmaxf(mA, s1);
        if (c0 <= rowB) mB = fmaxf(mB, s2);
        if (c1 <= rowB) mB = fmaxf(mB, s3);
    }
    mA = fmaxf(mA, __shfl_xor_sync(0xffffffffu, mA, 1));
    mA = fmaxf(mA, __shfl_xor_sync(0xffffffffu, mA, 2));
    mB = fmaxf(mB, __shfl_xor_sync(0xffffffffu, mB, 1));
    mB = fmaxf(mB, __shfl_xor_sync(0xffffffffu, mB, 2));

    float sumA = 0.f, sumB = 0.f;
    #pragma unroll
    for (int ni = 0; ni < 8; ni++) {
        int c0 = ni * 8 + tig * 2, c1 = c0 + 1;
        float e0 = (c0 <= rowA) ? expf(sacc[ni][0] - mA) : 0.f;
        float e1 = (c1 <= rowA) ? expf(sacc[ni][1] - mA) : 0.f;
        float e2 = (c0 <= rowB) ? expf(sacc[ni][2] - mB) : 0.f;
        float e3 = (c1 <= rowB) ? expf(sacc[ni][3] - mB) : 0.f;
        sacc[ni][0] = e0; sacc[ni][1] = e1; sacc[ni][2] = e2; sacc[ni][3] = e3;
        sumA += e0 + e1;
        sumB += e2 + e3;
    }
    sumA += __shfl_xor_sync(0xffffffffu, sumA, 1);
    sumA += __shfl_xor_sync(0xffffffffu, sumA, 2);
    sumB += __shfl_xor_sync(0xffffffffu, sumB, 1);
    sumB += __shfl_xor_sync(0xffffffffu, sumB, 2);
    const float invA = 1.f / sumA, invB = 1.f / sumB;

    u32 ph[8][2];
    #pragma unroll
    for (int ni = 0; ni < 8; ni++) {
        __half2 lo = __floats2half2_rn(sacc[ni][0] * invA, sacc[ni][1] * invA);
        __half2 hi = __floats2half2_rn(sacc[ni][2] * invB, sacc[ni][3] * invB);
        ph[ni][0] = *(u32*)&lo;
        ph[ni][1] = *(u32*)&hi;
    }

    float oacc[8][4];
    #pragma unroll
    for (int ni = 0; ni < 8; ni++)
        #pragma unroll
        for (int r = 0; r < 4; r++) oacc[ni][r] = 0.f;

    #pragma unroll
    for (int j = 0; j < 4; j++) {
        const u32 kb = (u32)(j * 32);
        u32 a0 = ph[2 * j][0], a1 = ph[2 * j][1];
        u32 a2 = ph[2 * j + 1][0], a3 = ph[2 * j + 1][1];
        u32 bfrag[8][2];
        #pragma unroll
        for (int np = 0; np < 4; np++) {
            u32 r0, r1, r2, r3;
            ldsm4(r0, r1, r2, r3, vsA + boff0 + (u32)(np * 16 * TSTRIDE * 2) + kb);
            bfrag[np * 2 + 0][0] = r0; bfrag[np * 2 + 0][1] = r1;
            bfrag[np * 2 + 1][0] = r2; bfrag[np * 2 + 1][1] = r3;
        }
        #pragma unroll
        for (int ni = 0; ni < 8; ni++)
            mma_f16(&oacc[ni][0], a0, a1, a2, a3, bfrag[ni][0], bfrag[ni][1]);
    }

    __half* dA = ctx + (size_t)(rowbase + rowA) * DD + colbase + tig * 2;
    __half* dB = ctx + (size_t)(rowbase + rowB) * DD + colbase + tig * 2;
    #pragma unroll
    for (int ni = 0; ni < 8; ni++) {
        *(__half2*)(dA + ni * 8) = __floats2half2_rn(oacc[ni][0], oacc[ni][1]);
        *(__half2*)(dB + ni * 8) = __floats2half2_rn(oacc[ni][2], oacc[ni][3]);
    }
}

// ---------------- launch ----------------
extern "C" void kernel_launch(void* const* d_in, const int* in_sizes, int n_in,
                              void* d_out, int out_size)
{
    const float* x    = (const float*)d_in[0];
    const float* Wq   = (const float*)d_in[2];
    const float* bq   = (const float*)d_in[3];
    const float* Wk   = (const float*)d_in[4];
    const float* bk   = (const float*)d_in[5];
    const float* Wv   = (const float*)d_in[6];
    const float* bv   = (const float*)d_in[7];
    const float* Wo   = (const float*)d_in[8];
    const float* bo   = (const float*)d_in[9];
    const float* ln1g = (const float*)d_in[10];
    const float* ln1b = (const float*)d_in[11];
    const float* ln2g = (const float*)d_in[12];
    const float* ln2b = (const float*)d_in[13];
    const float* W1   = (const float*)d_in[14];
    const float* b1   = (const float*)d_in[15];
    const float* W2   = (const float*)d_in[16];
    const float* b2   = (const float*)d_in[17];
    float* out = (float*)d_out;

    __half *h, *qkv, *ctx, *ff;
    float *x1, *bqkv;
    __half *wqkv, *wo, *w1, *w2;
    cudaGetSymbolAddress((void**)&h,    g_h);
    cudaGetSymbolAddress((void**)&qkv,  g_qkv);
    cudaGetSymbolAddress((void**)&ctx,  g_ctx);
    cudaGetSymbolAddress((void**)&x1,   g_x1);
    cudaGetSymbolAddress((void**)&ff,   g_ff);
    cudaGetSymbolAddress((void**)&wqkv, g_wqkv);
    cudaGetSymbolAddress((void**)&wo,   g_wo);
    cudaGetSymbolAddress((void**)&w1,   g_w1);
    cudaGetSymbolAddress((void**)&w2,   g_w2);
    cudaGetSymbolAddress((void**)&bqkv, g_bqkv);

    cudaFuncSetAttribute((const void*)mma_gemm<0, DD>,
                         cudaFuncAttributeMaxDynamicSharedMemorySize, SMEM_BYTES);
    cudaFuncSetAttribute((const void*)mma_gemm<2, DD>,
                         cudaFuncAttributeMaxDynamicSharedMemorySize, SMEM_BYTES);
    cudaFuncSetAttribute((const void*)mma_gemm<1, DD>,
                         cudaFuncAttributeMaxDynamicSharedMemorySize, SMEM_BYTES);
    cudaFuncSetAttribute((const void*)mma_gemm<2, DFFN>,
                         cudaFuncAttributeMaxDynamicSharedMemorySize, SMEM_BYTES);

    // 0. one fused convert launch
    cvt_all_kernel<<<12289, dim3(32, 8)>>>(Wq, Wk, Wv, Wo, W1, W2, bq, bk, bv);

    // 1. LN1 -> h (half)
    ln_kernel<<<MROWS, 256>>>(x, ln1g, ln1b, h);

    // 2. fused QKV projection (K=1024)
    dim3 gQKV(NQKV / 128, MROWS / 128);
    mma_gemm<0, DD><<<gQKV, 128, SMEM_BYTES>>>(h, wqkv, bqkv, nullptr, qkv, NQKV, 0.f);

    // 3. tensor-core attention -> ctx (half)
    dim3 gA(SS / 64, HH, BB);
    attn_kernel<<<gA, 128>>>(qkv, ctx);

    // 4. x1 = x + (ctx @ Wo + bo) * res_scale   (K=1024)
    dim3 gD(DD / 128, MROWS / 128);
    mma_gemm<2, DD><<<gD, 128, SMEM_BYTES>>>(ctx, wo, bo, x, x1, DD, RES_SCALE);

    // 5. LN2 -> h (half)
    ln_kernel<<<MROWS, 256>>>(x1, ln2g, ln2b, h);

    // 6. ff = (half)gelu(h @ W1 + b1)   (K=1024)
    dim3 gF1(DFFN / 128, MROWS / 128);
    mma_gemm<1, DD><<<gF1, 128, SMEM_BYTES>>>(h, w1, b1, nullptr, ff, DFFN, 0.f);

    // 7. out = x1 + (ff @ W2 + b2) * res_scale   (K=4096)
    mma_gemm<2, DFFN><<<gD, 128, SMEM_BYTES>>>(ff, w2, b2, x1, out, DD, RES_SCALE);
}

// round 13
// speedup vs baseline: 6.4721x; 1.0125x over previous
#include <cuda_runtime.h>
#include <cuda_fp16.h>
#include <math.h>

typedef unsigned int u32;

// Problem constants
#define BB 2
#define SS 2048
#define DD 1024
#define HH 16
#define DFFN 4096
#define MROWS (BB*SS)          // 4096
#define NQKV 3072
#define RES_SCALE 0.70710678118654752440f

// ---------------- device scratch ----------------
__device__ __half g_h   [MROWS * DD];
__device__ __half g_qkv [MROWS * NQKV];
__device__ __half g_ctx [MROWS * DD];
__device__ float  g_x1  [MROWS * DD];
__device__ __half g_ff  [MROWS * DFFN];
__device__ __half g_wqkv[NQKV * DD];
__device__ __half g_wo  [DD * DD];
__device__ __half g_w1  [DFFN * DD];
__device__ __half g_w2  [DD * DFFN];
__device__ float  g_bqkv[NQKV];

// ---------------- fused convert + LN1 (one launch) ----------------
// blocks [0,12288): weight transpose-convert; 12288: bias concat;
// blocks [12289, 12289+4096): LN1 rows (x -> g_h fp16)
__global__ __launch_bounds__(256) void cvt_all_kernel(
    const float* __restrict__ Wq, const float* __restrict__ Wk,
    const float* __restrict__ Wv, const float* __restrict__ Wo,
    const float* __restrict__ W1, const float* __restrict__ W2,
    const float* __restrict__ bq, const float* __restrict__ bk,
    const float* __restrict__ bv,
    const float* __restrict__ x,
    const float* __restrict__ ln1g, const float* __restrict__ ln1b)
{
    int bid = blockIdx.x;
    int tx = threadIdx.x, ty = threadIdx.y;
    int tid = ty * 32 + tx;

    if (bid >= 12289) {
        // ---- LN1 row ----
        int row = bid - 12289;
        const float4* xr = (const float4*)(x + (size_t)row * DD);
        float4 v = xr[tid];
        float s  = v.x + v.y + v.z + v.w;
        float ss = v.x*v.x + v.y*v.y + v.z*v.z + v.w*v.w;
        #pragma unroll
        for (int o = 16; o; o >>= 1) {
            s  += __shfl_xor_sync(0xffffffffu, s, o);
            ss += __shfl_xor_sync(0xffffffffu, ss, o);
        }
        __shared__ float sm1[8], sm2[8];
        int w = tid >> 5, l = tid & 31;
        if (l == 0) { sm1[w] = s; sm2[w] = ss; }
        __syncthreads();
        if (tid == 0) {
            float S = 0.f, SSu = 0.f;
            #pragma unroll
            for (int i = 0; i < 8; i++) { S += sm1[i]; SSu += sm2[i]; }
            float mu  = S  * (1.f / DD);
            float var = SSu * (1.f / DD) - mu * mu;
            sm1[0] = mu;
            sm2[0] = rsqrtf(var + 1e-5f);
        }
        __syncthreads();
        float mu  = sm1[0];
        float inv = sm2[0];
        float4 gg = ((const float4*)ln1g)[tid];
        float4 bb = ((const float4*)ln1b)[tid];
        __half2* orow = (__half2*)(g_h + (size_t)row * DD);
        orow[tid * 2 + 0] = __floats2half2_rn((v.x - mu) * inv * gg.x + bb.x,
                                              (v.y - mu) * inv * gg.y + bb.y);
        orow[tid * 2 + 1] = __floats2half2_rn((v.z - mu) * inv * gg.z + bb.z,
                                              (v.w - mu) * inv * gg.w + bb.w);
        return;
    }

    if (bid == 12288) {
        #pragma unroll
        for (int i = 0; i < 4; i++) {
            int j = tid + i * 256;
            g_bqkv[j]          = bq[j];
            g_bqkv[DD + j]     = bk[j];
            g_bqkv[2 * DD + j] = bv[j];
        }
        return;
    }

    const float* in;
    __half* out;
    int Kdim, Ndim, n0, k0, rowOff;
    if (bid < 4096) {
        int m = bid >> 10;
        int lb = bid & 1023;
        Kdim = DD; Ndim = DD;
        n0 = (lb & 31) * 32; k0 = (lb >> 5) * 32;
        if (m == 0)      { in = Wq; out = g_wqkv; rowOff = 0; }
        else if (m == 1) { in = Wk; out = g_wqkv; rowOff = DD; }
        else if (m == 2) { in = Wv; out = g_wqkv; rowOff = 2 * DD; }
        else             { in = Wo; out = g_wo;   rowOff = 0; }
    } else if (bid < 8192) {
        int lb = bid - 4096;
        Kdim = DD; Ndim = DFFN;
        n0 = (lb & 127) * 32; k0 = (lb >> 7) * 32;
        in = W1; out = g_w1; rowOff = 0;
    } else {
        int lb = bid - 8192;
        Kdim = DFFN; Ndim = DD;
        n0 = (lb & 31) * 32; k0 = (lb >> 5) * 32;
        in = W2; out = g_w2; rowOff = 0;
    }

    __shared__ float sm[32][33];
    #pragma unroll
    for (int i = 0; i < 4; i++) {
        int r = ty + i * 8;
        sm[r][tx] = in[(size_t)(k0 + r) * Ndim + n0 + tx];
    }
    __syncthreads();
    #pragma unroll
    for (int i = 0; i < 4; i++) {
        int r = ty + i * 8;
        out[(size_t)(rowOff + n0 + r) * Kdim + k0 + tx] = __float2half_rn(sm[tx][r]);
    }
}

// ---------------- LayerNorm (fp32 in, fp16 out) — used for LN2 ----------------
__global__ __launch_bounds__(256) void ln_kernel(const float* __restrict__ x,
                                                 const float* __restrict__ g,
                                                 const float* __restrict__ b,
                                                 __half* __restrict__ out)
{
    int row = blockIdx.x;
    int tid = threadIdx.x;
    const float4* xr = (const float4*)(x + (size_t)row * DD);
    float4 v = xr[tid];
    float s  = v.x + v.y + v.z + v.w;
    float ss = v.x*v.x + v.y*v.y + v.z*v.z + v.w*v.w;
    #pragma unroll
    for (int o = 16; o; o >>= 1) {
        s  += __shfl_xor_sync(0xffffffffu, s, o);
        ss += __shfl_xor_sync(0xffffffffu, ss, o);
    }
    __shared__ float sm1[8], sm2[8];
    int w = tid >> 5, l = tid & 31;
    if (l == 0) { sm1[w] = s; sm2[w] = ss; }
    __syncthreads();
    if (tid == 0) {
        float S = 0.f, SSu = 0.f;
        #pragma unroll
        for (int i = 0; i < 8; i++) { S += sm1[i]; SSu += sm2[i]; }
        float mu  = S  * (1.f / DD);
        float var = SSu * (1.f / DD) - mu * mu;
        sm1[0] = mu;
        sm2[0] = rsqrtf(var + 1e-5f);
    }
    __syncthreads();
    float mu  = sm1[0];
    float inv = sm2[0];
    float4 gg = ((const float4*)g)[tid];
    float4 bb = ((const float4*)b)[tid];
    __half2* orow = (__half2*)(out + (size_t)row * DD);
    orow[tid * 2 + 0] = __floats2half2_rn((v.x - mu) * inv * gg.x + bb.x,
                                          (v.y - mu) * inv * gg.y + bb.y);
    orow[tid * 2 + 1] = __floats2half2_rn((v.z - mu) * inv * gg.z + bb.z,
                                          (v.w - mu) * inv * gg.w + bb.w);
}

// ---------------- FP16 tensor-core GEMM (saturated; unchanged) ----------------
#define BKH 64
#define TSTRIDE 72
#define OP_STAGE (128 * TSTRIDE)
#define NSTAGE 3
#define STAGE_H (2 * OP_STAGE)
#define SMEM_BYTES (NSTAGE * STAGE_H * 2)        // 110592 B

__device__ __forceinline__ float gelu_tanh(float x) {
    float x3 = x * x * x;
    return 0.5f * x * (1.f + tanhf(0.7978845608028654f * (x + 0.044715f * x3)));
}
__device__ __forceinline__ void cp_async16h(__half* dst, const __half* src) {
    u32 d = (u32)__cvta_generic_to_shared(dst);
    asm volatile("cp.async.cg.shared.global [%0], [%1], 16;\n" :: "r"(d), "l"(src));
}
__device__ __forceinline__ void cp_commit() {
    asm volatile("cp.async.commit_group;\n");
}
__device__ __forceinline__ void cp_wait1() {
    asm volatile("cp.async.wait_group 1;\n" ::: "memory");
}
__device__ __forceinline__ void ldsm4(u32& r0, u32& r1, u32& r2, u32& r3, u32 addr) {
    asm volatile("ldmatrix.sync.aligned.m8n8.x4.shared.b16 {%0,%1,%2,%3}, [%4];"
                 : "=r"(r0), "=r"(r1), "=r"(r2), "=r"(r3) : "r"(addr));
}
__device__ __forceinline__ void ldsm4t(u32& r0, u32& r1, u32& r2, u32& r3, u32 addr) {
    asm volatile("ldmatrix.sync.aligned.m8n8.x4.trans.shared.b16 {%0,%1,%2,%3}, [%4];"
                 : "=r"(r0), "=r"(r1), "=r"(r2), "=r"(r3) : "r"(addr));
}
__device__ __forceinline__ void mma_f16(float* acc,
                                        u32 a0, u32 a1, u32 a2, u32 a3,
                                        u32 b0, u32 b1)
{
    float d0 = acc[0], d1 = acc[1], d2 = acc[2], d3 = acc[3];
    asm volatile(
        "mma.sync.aligned.m16n8k16.row.col.f32.f16.f16.f32 "
        "{%0,%1,%2,%3}, {%4,%5,%6,%7}, {%8,%9}, {%0,%1,%2,%3};"
        : "+f"(d0), "+f"(d1), "+f"(d2), "+f"(d3)
        : "r"(a0), "r"(a1), "r"(a2), "r"(a3), "r"(b0), "r"(b1));
    acc[0] = d0; acc[1] = d1; acc[2] = d2; acc[3] = d3;
}

template<int MODE, int KDIM>
__global__ __launch_bounds__(128, 2)
void mma_gemm(const __half* __restrict__ A, const __half* __restrict__ Bt,
              const float* __restrict__ bias, const float* __restrict__ R,
              void* __restrict__ Cv, int N, float scale)
{
    extern __shared__ __half smem[];
    constexpr int K = KDIM;
    constexpr int T = K / BKH;

    const int tid  = threadIdx.x;
    const int lane = tid & 31;
    const int warp = tid >> 5;
    const int wm   = (warp >> 1) * 64;
    const int wn   = (warp & 1) * 64;
    const int bm   = blockIdx.y * 128;
    const int bn   = blockIdx.x * 128;
    const int gid  = lane >> 2;
    const int tig  = lane & 3;

    const int q = lane >> 3, ri = lane & 7;
    const u32 aoff0 = (u32)(((wm + (q & 1) * 8 + ri) * TSTRIDE + (q >> 1) * 8) * 2);
    const u32 boff0 = (u32)(((wn + (q >> 1) * 8 + ri) * TSTRIDE + (q & 1) * 8) * 2);

    float acc[4][8][4];
    #pragma unroll
    for (int mi = 0; mi < 4; mi++)
        #pragma unroll
        for (int ni = 0; ni < 8; ni++)
            #pragma unroll
            for (int r = 0; r < 4; r++) acc[mi][ni][r] = 0.f;

    auto load_tile = [&](int s, int tp) {
        __half* as = smem + s * STAGE_H;
        __half* bs = as + OP_STAGE;
        int k0 = tp * BKH;
        const __half* Ag = A + (size_t)bm * K + k0;
        const __half* Bg = Bt + (size_t)bn * K + k0;
        #pragma unroll
        for (int i = 0; i < 8; i++) {
            int idx = tid + i * 128;
            int r = idx >> 3, c = (idx & 7) * 8;
            cp_async16h(as + r * TSTRIDE + c, Ag + (size_t)r * K + c);
            cp_async16h(bs + r * TSTRIDE + c, Bg + (size_t)r * K + c);
        }
        cp_commit();
    };

    load_tile(0, 0);
    load_tile(1, 1);

    int sc = 0;
    #pragma unroll 2
    for (int t = 0; t < T; t++) {
        cp_wait1();
        __syncthreads();

        if (t + 2 < T) {
            int sp = sc + 2; if (sp >= NSTAGE) sp -= NSTAGE;
            load_tile(sp, t + 2);
        }

        const u32 asAddr = (u32)__cvta_generic_to_shared(smem + sc * STAGE_H);
        const u32 bsAddr = asAddr + (u32)(OP_STAGE * 2);

        u32 af[2][4][4];
        u32 bf[2][8][2];

        #pragma unroll
        for (int mi = 0; mi < 4; mi++) {
            u32 r0, r1, r2, r3;
            ldsm4(r0, r1, r2, r3, asAddr + aoff0 + (u32)(mi * 16 * TSTRIDE * 2));
            af[0][mi][0] = r0; af[0][mi][1] = r1; af[0][mi][2] = r2; af[0][mi][3] = r3;
        }
        #pragma unroll
        for (int np = 0; np < 4; np++) {
            u32 r0, r1, r2, r3;
            ldsm4(r0, r1, r2, r3, bsAddr + boff0 + (u32)(np * 16 * TSTRIDE * 2));
            bf[0][np * 2 + 0][0] = r0; bf[0][np * 2 + 0][1] = r1;
            bf[0][np * 2 + 1][0] = r2; bf[0][np * 2 + 1][1] = r3;
        }

        #pragma unroll
        for (int kk = 0; kk < 4; kk++) {
            const int cb = kk & 1, nb = cb ^ 1;
            if (kk < 3) {
                const u32 kb = (u32)((kk + 1) * 32);
                #pragma unroll
                for (int mi = 0; mi < 4; mi++) {
                    u32 r0, r1, r2, r3;
                    ldsm4(r0, r1, r2, r3, asAddr + aoff0 + (u32)(mi * 16 * TSTRIDE * 2) + kb);
                    af[nb][mi][0] = r0; af[nb][mi][1] = r1;
                    af[nb][mi][2] = r2; af[nb][mi][3] = r3;
                }
                #pragma unroll
                for (int np = 0; np < 4; np++) {
                    u32 r0, r1, r2, r3;
                    ldsm4(r0, r1, r2, r3, bsAddr + boff0 + (u32)(np * 16 * TSTRIDE * 2) + kb);
                    bf[nb][np * 2 + 0][0] = r0; bf[nb][np * 2 + 0][1] = r1;
                    bf[nb][np * 2 + 1][0] = r2; bf[nb][np * 2 + 1][1] = r3;
                }
            }
            #pragma unroll
            for (int mi = 0; mi < 4; mi++) {
                u32 a0 = af[cb][mi][0], a1 = af[cb][mi][1];
                u32 a2 = af[cb][mi][2], a3 = af[cb][mi][3];
                #pragma unroll
                for (int ni = 0; ni < 8; ni++) {
                    u32 b0 = bf[cb][ni][0], b1 = bf[cb][ni][1];
                    mma_f16(&acc[mi][ni][0], a0, a1, a2, a3, b0, b1);
                }
            }
        }

        if (++sc >= NSTAGE) sc = 0;
    }

    const int rbase = bm + wm + gid;
    const int cbase = bn + wn + tig * 2;
    #pragma unroll
    for (int mi = 0; mi < 4; mi++) {
        #pragma unroll
        for (int half_ = 0; half_ < 2; half_++) {
            int r = rbase + mi * 16 + half_ * 8;
            #pragma unroll
            for (int ni = 0; ni < 8; ni++) {
                int c = cbase + ni * 8;
                float v0 = acc[mi][ni][half_ * 2 + 0] + bias[c];
                float v1 = acc[mi][ni][half_ * 2 + 1] + bias[c + 1];
                if (MODE == 0) {
                    __half2* C = (__half2*)((__half*)Cv + (size_t)r * N + c);
                    *C = __floats2half2_rn(v0, v1);
                } else if (MODE == 1) {
                    __half2* C = (__half2*)((__half*)Cv + (size_t)r * N + c);
                    *C = __floats2half2_rn(gelu_tanh(v0), gelu_tanh(v1));
                } else {
                    float* C = (float*)Cv + (size_t)r * N + c;
                    const float2 rr = *(const float2*)(R + (size_t)r * N + c);
                    float2 o2;
                    o2.x = rr.x + v0 * scale;
                    o2.y = rr.y + v1 * scale;
                    *(float2*)C = o2;
                }
            }
        }
    }
}

// ---------------- tensor-core block-local causal attention ----------------
// V kept in [key][d] layout (same fill as K); PV B-fragments via ldmatrix.trans.
__global__ __launch_bounds__(128)
void attn_kernel(const __half* __restrict__ qkv, __half* __restrict__ ctx)
{
    __shared__ __half qs[64 * TSTRIDE];
    __shared__ __half ks[64 * TSTRIDE];
    __shared__ __half vs[64 * TSTRIDE];

    const int tid  = threadIdx.x;
    const int lane = tid & 31;
    const int warp = tid >> 5;
    const int gid  = lane >> 2;
    const int tig  = lane & 3;
    const int rowbase = blockIdx.z * SS + blockIdx.x * 64;
    const int colbase = blockIdx.y * 64;

    #pragma unroll
    for (int i = 0; i < 4; i++) {
        int idx = tid + i * 128;
        int r = idx >> 3, c = (idx & 7) * 8;
        size_t base = (size_t)(rowbase + r) * NQKV + colbase + c;
        *(uint4*)(qs + r * TSTRIDE + c) = *(const uint4*)(qkv + base);
        *(uint4*)(ks + r * TSTRIDE + c) = *(const uint4*)(qkv + base + DD);
        *(uint4*)(vs + r * TSTRIDE + c) = *(const uint4*)(qkv + base + 2 * DD);
    }
    __syncthreads();

    const int q = lane >> 3, ri = lane & 7;
    const u32 qsA = (u32)__cvta_generic_to_shared(qs);
    const u32 ksA = (u32)__cvta_generic_to_shared(ks);
    const u32 vsA = (u32)__cvta_generic_to_shared(vs);
    const u32 aoff0 = (u32)(((warp * 16 + (q & 1) * 8 + ri) * TSTRIDE + (q >> 1) * 8) * 2);
    const u32 boff0 = (u32)((((q >> 1) * 8 + ri) * TSTRIDE + (q & 1) * 8) * 2);
    // trans-load offset for V [k=key][n=d]: tile row = kbase+(q&1)*8+ri, col = (q>>1)*8
    const u32 voff0 = (u32)((((q & 1) * 8 + ri) * TSTRIDE + (q >> 1) * 8) * 2);

    // ---- stage 1: S = Q @ K^T ----
    float sacc[8][4];
    #pragma unroll
    for (int ni = 0; ni < 8; ni++)
        #pragma unroll
        for (int r = 0; r < 4; r++) sacc[ni][r] = 0.f;

    #pragma unroll
    for (int j = 0; j < 4; j++) {
        const u32 kb = (u32)(j * 32);
        u32 a0, a1, a2, a3;
        ldsm4(a0, a1, a2, a3, qsA + aoff0 + kb);
        u32 bfrag[8][2];
        #pragma unroll
        for (int np = 0; np < 4; np++) {
            u32 r0, r1, r2, r3;
            ldsm4(r0, r1, r2, r3, ksA + boff0 + (u32)(np * 16 * TSTRIDE * 2) + kb);
            bfrag[np * 2 + 0][0] = r0; bfrag[np * 2 + 0][1] = r1;
            bfrag[np * 2 + 1][0] = r2; bfrag[np * 2 + 1][1] = r3;
        }
        #pragma unroll
        for (int ni = 0; ni < 8; ni++)
            mma_f16(&sacc[ni][0], a0, a1, a2, a3, bfrag[ni][0], bfrag[ni][1]);
    }

    // ---- softmax in registers ----
    const int rowA = warp * 16 + gid;
    const int rowB = rowA + 8;
    float mA = -1e30f, mB = -1e30f;
    #pragma unroll
    for (int ni = 0; ni < 8; ni++) {
        int c0 = ni * 8 + tig * 2, c1 = c0 + 1;
        float s0 = sacc[ni][0] * 0.125f;
        float s1 = sacc[ni][1] * 0.125f;
        float s2 = sacc[ni][2] * 0.125f;
        float s3 = sacc[ni][3] * 0.125f;
        sacc[ni][0] = s0; sacc[ni][1] = s1; sacc[ni][2] = s2; sacc[ni][3] = s3;
        if (c0 <= rowA) mA = fmaxf(mA, s0);
        if (c1 <= rowA) mA = fmaxf(mA, s1);
        if (c0 <= rowB) mB = fmaxf(mB, s2);
        if (c1 <= rowB) mB = fmaxf(mB, s3);
    }
    mA = fmaxf(mA, __shfl_xor_sync(0xffffffffu, mA, 1));
    mA = fmaxf(mA, __shfl_xor_sync(0xffffffffu, mA, 2));
    mB = fmaxf(mB, __shfl_xor_sync(0xffffffffu, mB, 1));
    mB = fmaxf(mB, __shfl_xor_sync(0xffffffffu, mB, 2));

    float sumA = 0.f, sumB = 0.f;
    #pragma unroll
    for (int ni = 0; ni < 8; ni++) {
        int c0 = ni * 8 + tig * 2, c1 = c0 + 1;
        float e0 = (c0 <= rowA) ? expf(sacc[ni][0] - mA) : 0.f;
        float e1 = (c1 <= rowA) ? expf(sacc[ni][1] - mA) : 0.f;
        float e2 = (c0 <= rowB) ? expf(sacc[ni][2] - mB) : 0.f;
        float e3 = (c1 <= rowB) ? expf(sacc[ni][3] - mB) : 0.f;
        sacc[ni][0] = e0; sacc[ni][1] = e1; sacc[ni][2] = e2; sacc[ni][3] = e3;
        sumA += e0 + e1;
        sumB += e2 + e3;
    }
    sumA += __shfl_xor_sync(0xffffffffu, sumA, 1);
    sumA += __shfl_xor_sync(0xffffffffu, sumA, 2);
    sumB += __shfl_xor_sync(0xffffffffu, sumB, 1);
    sumB += __shfl_xor_sync(0xffffffffu, sumB, 2);
    const float invA = 1.f / sumA, invB = 1.f / sumB;

    u32 ph[8][2];
    #pragma unroll
    for (int ni = 0; ni < 8; ni++) {
        __half2 lo = __floats2half2_rn(sacc[ni][0] * invA, sacc[ni][1] * invA);
        __half2 hi = __floats2half2_rn(sacc[ni][2] * invB, sacc[ni][3] * invB);
        ph[ni][0] = *(u32*)&lo;
        ph[ni][1] = *(u32*)&hi;
    }

    // ---- stage 2: O = P @ V  (B fragments via trans-ldmatrix from vs [key][d]) ----
    float oacc[8][4];
    #pragma unroll
    for (int ni = 0; ni < 8; ni++)
        #pragma unroll
        for (int r = 0; r < 4; r++) oacc[ni][r] = 0.f;

    #pragma unroll
    for (int j = 0; j < 4; j++) {
        u32 a0 = ph[2 * j][0], a1 = ph[2 * j][1];
        u32 a2 = ph[2 * j + 1][0], a3 = ph[2 * j + 1][1];
        u32 bfrag[8][2];
        #pragma unroll
        for (int np = 0; np < 4; np++) {
            u32 r0, r1, r2, r3;
            // tile base: rows (key) j*16.., cols (d) np*16..
            ldsm4t(r0, r1, r2, r3,
                   vsA + voff0 + (u32)((j * 16 * TSTRIDE + np * 16) * 2));
            bfrag[np * 2 + 0][0] = r0; bfrag[np * 2 + 0][1] = r1;
            bfrag[np * 2 + 1][0] = r2; bfrag[np * 2 + 1][1] = r3;
        }
        #pragma unroll
        for (int ni = 0; ni < 8; ni++)
            mma_f16(&oacc[ni][0], a0, a1, a2, a3, bfrag[ni][0], bfrag[ni][1]);
    }

    __half* dA = ctx + (size_t)(rowbase + rowA) * DD + colbase + tig * 2;
    __half* dB = ctx + (size_t)(rowbase + rowB) * DD + colbase + tig * 2;
    #pragma unroll
    for (int ni = 0; ni < 8; ni++) {
        *(__half2*)(dA + ni * 8) = __floats2half2_rn(oacc[ni][0], oacc[ni][1]);
        *(__half2*)(dB + ni * 8) = __floats2half2_rn(oacc[ni][2], oacc[ni][3]);
    }
}

// ---------------- launch ----------------
extern "C" void kernel_launch(void* const* d_in, const int* in_sizes, int n_in,
                              void* d_out, int out_size)
{
    const float* x    = (const float*)d_in[0];
    const float* Wq   = (const float*)d_in[2];
    const float* bq   = (const float*)d_in[3];
    const float* Wk   = (const float*)d_in[4];
    const float* bk   = (const float*)d_in[5];
    const float* Wv   = (const float*)d_in[6];
    const float* bv   = (const float*)d_in[7];
    const float* Wo   = (const float*)d_in[8];
    const float* bo   = (const float*)d_in[9];
    const float* ln1g = (const float*)d_in[10];
    const float* ln1b = (const float*)d_in[11];
    const float* ln2g = (const float*)d_in[12];
    const float* ln2b = (const float*)d_in[13];
    const float* W1   = (const float*)d_in[14];
    const float* b1   = (const float*)d_in[15];
    const float* W2   = (const float*)d_in[16];
    const float* b2   = (const float*)d_in[17];
    float* out = (float*)d_out;

    __half *h, *qkv, *ctx, *ff;
    float *x1, *bqkv;
    __half *wqkv, *wo, *w1, *w2;
    cudaGetSymbolAddress((void**)&h,    g_h);
    cudaGetSymbolAddress((void**)&qkv,  g_qkv);
    cudaGetSymbolAddress((void**)&ctx,  g_ctx);
    cudaGetSymbolAddress((void**)&x1,   g_x1);
    cudaGetSymbolAddress((void**)&ff,   g_ff);
    cudaGetSymbolAddress((void**)&wqkv, g_wqkv);
    cudaGetSymbolAddress((void**)&wo,   g_wo);
    cudaGetSymbolAddress((void**)&w1,   g_w1);
    cudaGetSymbolAddress((void**)&w2,   g_w2);
    cudaGetSymbolAddress((void**)&bqkv, g_bqkv);

    cudaFuncSetAttribute((const void*)mma_gemm<0, DD>,
                         cudaFuncAttributeMaxDynamicSharedMemorySize, SMEM_BYTES);
    cudaFuncSetAttribute((const void*)mma_gemm<2, DD>,
                         cudaFuncAttributeMaxDynamicSharedMemorySize, SMEM_BYTES);
    cudaFuncSetAttribute((const void*)mma_gemm<1, DD>,
                         cudaFuncAttributeMaxDynamicSharedMemorySize, SMEM_BYTES);
    cudaFuncSetAttribute((const void*)mma_gemm<2, DFFN>,
                         cudaFuncAttributeMaxDynamicSharedMemorySize, SMEM_BYTES);

    // 0+1. fused convert + LN1 (one launch)
    cvt_all_kernel<<<12289 + MROWS, dim3(32, 8)>>>(Wq, Wk, Wv, Wo, W1, W2,
                                                   bq, bk, bv, x, ln1g, ln1b);

    // 2. fused QKV projection (K=1024)
    dim3 gQKV(NQKV / 128, MROWS / 128);
    mma_gemm<0, DD><<<gQKV, 128, SMEM_BYTES>>>(h, wqkv, bqkv, nullptr, qkv, NQKV, 0.f);

    // 3. tensor-core attention -> ctx (half)
    dim3 gA(SS / 64, HH, BB);
    attn_kernel<<<gA, 128>>>(qkv, ctx);

    // 4. x1 = x + (ctx @ Wo + bo) * res_scale   (K=1024)
    dim3 gD(DD / 128, MROWS / 128);
    mma_gemm<2, DD><<<gD, 128, SMEM_BYTES>>>(ctx, wo, bo, x, x1, DD, RES_SCALE);

    // 5. LN2 -> h (half)
    ln_kernel<<<MROWS, 256>>>(x1, ln2g, ln2b, h);

    // 6. ff = (half)gelu(h @ W1 + b1)   (K=1024)
    dim3 gF1(DFFN / 128, MROWS / 128);
    mma_gemm<1, DD><<<gF1, 128, SMEM_BYTES>>>(h, w1, b1, nullptr, ff, DFFN, 0.f);

    // 7. out = x1 + (ff @ W2 + b2) * res_scale   (K=4096)
    mma_gemm<2, DFFN><<<gD, 128, SMEM_BYTES>>>(ff, w2, b2, x1, out, DD, RES_SCALE);
}